// round 1
// baseline (speedup 1.0000x reference)
#include <cuda_runtime.h>
#include <math.h>

#define B_  2
#define S_  2048
#define D_  1024
#define H_  16
#define DH_ 64
#define E_  16
#define F_  256
#define T_  (B_*S_)

// ---------------- scratch (device globals: allocation-guard safe) ----------------
__device__ float g_h1[(size_t)T_*D_];
__device__ float g_q [(size_t)T_*D_];
__device__ float g_k [(size_t)T_*D_];
__device__ float g_v [(size_t)T_*D_];
__device__ float g_ctx[(size_t)T_*D_];
__device__ float g_x2[(size_t)T_*D_];
__device__ float g_h2[(size_t)T_*D_];
__device__ float g_up[(size_t)E_*T_*F_];
__device__ int   g_cnt[E_];
__device__ int   g_elist[E_*T_];
__device__ float g_egate[E_*T_];

// ---------------- zero expert counters (must run each call: graph replay) --------
__global__ void zero_cnt_kernel() {
    if (threadIdx.x < E_) g_cnt[threadIdx.x] = 0;
}

// ---------------- LayerNorm: one block per row, D=1024, 256 threads --------------
__global__ __launch_bounds__(256) void ln_kernel(const float* __restrict__ x,
                                                 const float* __restrict__ sc,
                                                 const float* __restrict__ bi,
                                                 float* __restrict__ o) {
    int t = blockIdx.x;
    const float* xr = x + (size_t)t * D_;
    float* orow = o + (size_t)t * D_;
    float v[4];
    float s = 0.f, s2 = 0.f;
#pragma unroll
    for (int i = 0; i < 4; i++) {
        v[i] = xr[threadIdx.x + i * 256];
        s  += v[i];
        s2 += v[i] * v[i];
    }
#pragma unroll
    for (int off = 16; off; off >>= 1) {
        s  += __shfl_xor_sync(0xffffffffu, s,  off);
        s2 += __shfl_xor_sync(0xffffffffu, s2, off);
    }
    __shared__ float ws[8], ws2[8];
    int w = threadIdx.x >> 5, ln = threadIdx.x & 31;
    if (ln == 0) { ws[w] = s; ws2[w] = s2; }
    __syncthreads();
    float S = 0.f, S2 = 0.f;
#pragma unroll
    for (int i = 0; i < 8; i++) { S += ws[i]; S2 += ws2[i]; }
    float mu  = S * (1.0f / D_);
    float var = S2 * (1.0f / D_) - mu * mu;
    float inv = rsqrtf(var + 1e-5f);
#pragma unroll
    for (int i = 0; i < 4; i++) {
        int d = threadIdx.x + i * 256;
        orow[d] = (v[i] - mu) * inv * sc[d] + bi[d];
    }
}

// ---------------- SGEMM 128x128x8, 256 threads, 8x8 microtile --------------------
// C = A(MxK) @ B(KxN) [+ Res]; optional duplicate output C2.
// Requires M%128==0, N%128==0, K%8==0 (true for all projection GEMMs here).
__global__ __launch_bounds__(256) void sgemm128(const float* __restrict__ A,
                                                const float* __restrict__ Bm,
                                                const float* __restrict__ Res,
                                                float* __restrict__ C,
                                                float* __restrict__ C2,
                                                int M, int N, int Kd) {
    __shared__ float As[8][128];
    __shared__ float Bs[8][128];
    int bx = blockIdx.x * 128, by = blockIdx.y * 128;
    int tid = threadIdx.x;
    int tx = tid & 15, ty = tid >> 4;

    float acc[8][8];
#pragma unroll
    for (int i = 0; i < 8; i++)
#pragma unroll
        for (int j = 0; j < 8; j++) acc[i][j] = 0.f;

    int arow = tid >> 1, acol = (tid & 1) * 4;
    int brow = tid >> 5, bcol = (tid & 31) * 4;
    const float* Aptr = A + (size_t)(by + arow) * Kd + acol;
    const float* Bptr = Bm + (size_t)brow * N + bx + bcol;

    for (int k0 = 0; k0 < Kd; k0 += 8) {
        float4 a4 = *(const float4*)(Aptr + k0);
        float4 b4 = *(const float4*)(Bptr + (size_t)k0 * N);
        As[acol + 0][arow] = a4.x;
        As[acol + 1][arow] = a4.y;
        As[acol + 2][arow] = a4.z;
        As[acol + 3][arow] = a4.w;
        *(float4*)&Bs[brow][bcol] = b4;
        __syncthreads();
#pragma unroll
        for (int k = 0; k < 8; k++) {
            float4 a0 = *(const float4*)&As[k][ty * 8];
            float4 a1 = *(const float4*)&As[k][ty * 8 + 4];
            float4 b0 = *(const float4*)&Bs[k][tx * 8];
            float4 b1 = *(const float4*)&Bs[k][tx * 8 + 4];
            float ar[8] = {a0.x, a0.y, a0.z, a0.w, a1.x, a1.y, a1.z, a1.w};
            float br[8] = {b0.x, b0.y, b0.z, b0.w, b1.x, b1.y, b1.z, b1.w};
#pragma unroll
            for (int i = 0; i < 8; i++)
#pragma unroll
                for (int j = 0; j < 8; j++) acc[i][j] = fmaf(ar[i], br[j], acc[i][j]);
        }
        __syncthreads();
    }

#pragma unroll
    for (int i = 0; i < 8; i++) {
        size_t row = (size_t)(by + ty * 8 + i);
        size_t off = row * N + bx + tx * 8;
#pragma unroll
        for (int jj = 0; jj < 2; jj++) {
            float4 c;
            c.x = acc[i][jj * 4 + 0];
            c.y = acc[i][jj * 4 + 1];
            c.z = acc[i][jj * 4 + 2];
            c.w = acc[i][jj * 4 + 3];
            if (Res) {
                float4 r = *(const float4*)(Res + off + jj * 4);
                c.x += r.x; c.y += r.y; c.z += r.z; c.w += r.w;
            }
            *(float4*)(C + off + jj * 4) = c;
            if (C2) *(float4*)(C2 + off + jj * 4) = c;
        }
    }
}

// ---------------- Flash attention (fp32): 64q x 64k tiles, online softmax --------
// grid (S/64, B*H), 256 threads (8 warps, warp handles 8 query rows).
__global__ __launch_bounds__(256) void attn_kernel(const float* __restrict__ Q,
                                                   const float* __restrict__ Kt,
                                                   const float* __restrict__ V,
                                                   float* __restrict__ O) {
    int bh = blockIdx.y;
    int b = bh / H_, h = bh % H_;
    int q0 = blockIdx.x * 64;

    __shared__ float q_s[64][65];
    __shared__ float k_s[64][65];
    __shared__ float v_s[64][65];

    int tid = threadIdx.x, warp = tid >> 5, lane = tid & 31;

    // load Q tile
    {
        int r = tid >> 2, c0 = (tid & 3) * 16;
        const float* src = Q + ((size_t)(b * S_ + q0 + r)) * D_ + h * DH_ + c0;
#pragma unroll
        for (int i = 0; i < 16; i += 4) {
            float4 f = *(const float4*)(src + i);
            q_s[r][c0 + i + 0] = f.x;
            q_s[r][c0 + i + 1] = f.y;
            q_s[r][c0 + i + 2] = f.z;
            q_s[r][c0 + i + 3] = f.w;
        }
    }

    float m[8], l[8], a0[8], a1[8];
#pragma unroll
    for (int i = 0; i < 8; i++) { m[i] = -1e30f; l[i] = 0.f; a0[i] = 0.f; a1[i] = 0.f; }

    for (int kt = 0; kt < S_; kt += 64) {
        __syncthreads();
        {
            int r = tid >> 2, c0 = (tid & 3) * 16;
            const float* ks = Kt + ((size_t)(b * S_ + kt + r)) * D_ + h * DH_ + c0;
            const float* vs = V  + ((size_t)(b * S_ + kt + r)) * D_ + h * DH_ + c0;
#pragma unroll
            for (int i = 0; i < 16; i += 4) {
                float4 fk = *(const float4*)(ks + i);
                float4 fv = *(const float4*)(vs + i);
                k_s[r][c0 + i + 0] = fk.x; k_s[r][c0 + i + 1] = fk.y;
                k_s[r][c0 + i + 2] = fk.z; k_s[r][c0 + i + 3] = fk.w;
                v_s[r][c0 + i + 0] = fv.x; v_s[r][c0 + i + 1] = fv.y;
                v_s[r][c0 + i + 2] = fv.z; v_s[r][c0 + i + 3] = fv.w;
            }
        }
        __syncthreads();

#pragma unroll
        for (int ri = 0; ri < 8; ri++) {
            int i = warp * 8 + ri;
            float s0 = 0.f, s1 = 0.f;
#pragma unroll
            for (int d = 0; d < 64; d++) {
                float qd = q_s[i][d];
                s0 = fmaf(qd, k_s[lane][d], s0);
                s1 = fmaf(qd, k_s[lane + 32][d], s1);
            }
            s0 *= 0.125f;
            s1 *= 0.125f;
            float tm = fmaxf(s0, s1);
#pragma unroll
            for (int o = 16; o; o >>= 1) tm = fmaxf(tm, __shfl_xor_sync(0xffffffffu, tm, o));
            float mn = fmaxf(m[ri], tm);
            float al = __expf(m[ri] - mn);
            float p0 = __expf(s0 - mn);
            float p1 = __expf(s1 - mn);
            float rs = p0 + p1;
#pragma unroll
            for (int o = 16; o; o >>= 1) rs += __shfl_xor_sync(0xffffffffu, rs, o);
            l[ri] = l[ri] * al + rs;
            m[ri] = mn;
            a0[ri] *= al;
            a1[ri] *= al;
#pragma unroll
            for (int j = 0; j < 32; j++) {
                float pj = __shfl_sync(0xffffffffu, p0, j);
                a0[ri] = fmaf(pj, v_s[j][lane], a0[ri]);
                a1[ri] = fmaf(pj, v_s[j][lane + 32], a1[ri]);
            }
#pragma unroll
            for (int j = 0; j < 32; j++) {
                float pj = __shfl_sync(0xffffffffu, p1, j);
                a0[ri] = fmaf(pj, v_s[j + 32][lane], a0[ri]);
                a1[ri] = fmaf(pj, v_s[j + 32][lane + 32], a1[ri]);
            }
        }
    }

#pragma unroll
    for (int ri = 0; ri < 8; ri++) {
        int i = warp * 8 + ri;
        float inv = 1.0f / l[ri];
        size_t base = ((size_t)(b * S_ + q0 + i)) * D_ + h * DH_;
        O[base + lane]      = a0[ri] * inv;
        O[base + lane + 32] = a1[ri] * inv;
    }
}

// ---------------- Selector: sigmoid(h @ W_sel), top-2, expert bucketing ----------
// 1 warp per token, 4 warps per block.
__global__ __launch_bounds__(128) void selector_kernel(const float* __restrict__ h,
                                                       const float* __restrict__ Wsel) {
    int t = blockIdx.x * 4 + (threadIdx.x >> 5);
    int lane = threadIdx.x & 31;
    float acc[16];
#pragma unroll
    for (int e = 0; e < 16; e++) acc[e] = 0.f;
    const float* hr = h + (size_t)t * D_;
    for (int d = lane; d < D_; d += 32) {
        float hv = hr[d];
        const float4* w = (const float4*)(Wsel + (size_t)d * E_);
        float4 w0 = w[0], w1 = w[1], w2 = w[2], w3 = w[3];
        acc[0]  = fmaf(hv, w0.x, acc[0]);  acc[1]  = fmaf(hv, w0.y, acc[1]);
        acc[2]  = fmaf(hv, w0.z, acc[2]);  acc[3]  = fmaf(hv, w0.w, acc[3]);
        acc[4]  = fmaf(hv, w1.x, acc[4]);  acc[5]  = fmaf(hv, w1.y, acc[5]);
        acc[6]  = fmaf(hv, w1.z, acc[6]);  acc[7]  = fmaf(hv, w1.w, acc[7]);
        acc[8]  = fmaf(hv, w2.x, acc[8]);  acc[9]  = fmaf(hv, w2.y, acc[9]);
        acc[10] = fmaf(hv, w2.z, acc[10]); acc[11] = fmaf(hv, w2.w, acc[11]);
        acc[12] = fmaf(hv, w3.x, acc[12]); acc[13] = fmaf(hv, w3.y, acc[13]);
        acc[14] = fmaf(hv, w3.z, acc[14]); acc[15] = fmaf(hv, w3.w, acc[15]);
    }
#pragma unroll
    for (int e = 0; e < 16; e++)
#pragma unroll
        for (int o = 16; o; o >>= 1) acc[e] += __shfl_xor_sync(0xffffffffu, acc[e], o);
    if (lane == 0) {
        float v1 = -1.f, v2 = -1.f;
        int i1 = 0, i2 = 0;
#pragma unroll
        for (int e = 0; e < 16; e++) {
            float sg = 1.0f / (1.0f + __expf(-acc[e]));
            if (sg > v1) { v2 = v1; i2 = i1; v1 = sg; i1 = e; }
            else if (sg > v2) { v2 = sg; i2 = e; }
        }
        int p1 = atomicAdd(&g_cnt[i1], 1);
        g_elist[i1 * T_ + p1] = t;
        g_egate[i1 * T_ + p1] = v1;
        int p2 = atomicAdd(&g_cnt[i2], 1);
        g_elist[i2 * T_ + p2] = t;
        g_egate[i2 * T_ + p2] = v2;
    }
}

// ---------------- MoE up: up = gate * relu(gather(h2) @ W1[e]) -------------------
// grid (F/64, T/64, E); 64x64x16 tile, 256 threads, 4x4 microtile, row-gather.
__global__ __launch_bounds__(256) void moe_up_kernel(const float* __restrict__ h,
                                                     const float* __restrict__ W1) {
    int e = blockIdx.z;
    int n = g_cnt[e];
    int rb = blockIdx.y * 64;
    if (rb >= n) return;
    int bn = blockIdx.x * 64;

    __shared__ float As[16][64];
    __shared__ float Bs[16][64];
    __shared__ int rows[64];

    int tid = threadIdx.x, tx = tid & 15, ty = tid >> 4;
    if (tid < 64) {
        int rg = rb + tid;
        rows[tid] = (rg < n) ? g_elist[e * T_ + rg] : 0;
    }
    __syncthreads();

    float acc[4][4];
#pragma unroll
    for (int i = 0; i < 4; i++)
#pragma unroll
        for (int j = 0; j < 4; j++) acc[i][j] = 0.f;

    int lr = tid >> 2, lk = (tid & 3) * 4;
    int brow = tid >> 4, bcol = (tid & 15) * 4;
    const float* Wb = W1 + (size_t)e * D_ * F_ + bn;
    const float* Arow = h + (size_t)rows[lr] * D_ + lk;

    for (int k0 = 0; k0 < D_; k0 += 16) {
        float4 a4 = *(const float4*)(Arow + k0);
        float4 b4 = *(const float4*)(Wb + (size_t)(k0 + brow) * F_ + bcol);
        As[lk + 0][lr] = a4.x; As[lk + 1][lr] = a4.y;
        As[lk + 2][lr] = a4.z; As[lk + 3][lr] = a4.w;
        *(float4*)&Bs[brow][bcol] = b4;
        __syncthreads();
#pragma unroll
        for (int k = 0; k < 16; k++) {
            float4 a = *(const float4*)&As[k][ty * 4];
            float4 b = *(const float4*)&Bs[k][tx * 4];
            float ar[4] = {a.x, a.y, a.z, a.w};
            float br[4] = {b.x, b.y, b.z, b.w};
#pragma unroll
            for (int i = 0; i < 4; i++)
#pragma unroll
                for (int j = 0; j < 4; j++) acc[i][j] = fmaf(ar[i], br[j], acc[i][j]);
        }
        __syncthreads();
    }

#pragma unroll
    for (int i = 0; i < 4; i++) {
        int rg = rb + ty * 4 + i;
        if (rg < n) {
            float gte = g_egate[e * T_ + rg];
            float* op = g_up + ((size_t)e * T_ + rg) * F_ + bn + tx * 4;
#pragma unroll
            for (int j = 0; j < 4; j++) op[j] = fmaxf(acc[i][j], 0.f) * gte;
        }
    }
}

// ---------------- MoE down: out[t] += up @ W2[e] (atomic scatter) ----------------
// grid (D/64, T/64, E)
__global__ __launch_bounds__(256) void moe_down_kernel(const float* __restrict__ W2,
                                                       float* __restrict__ out) {
    int e = blockIdx.z;
    int n = g_cnt[e];
    int rb = blockIdx.y * 64;
    if (rb >= n) return;
    int bn = blockIdx.x * 64;

    __shared__ float As[16][64];
    __shared__ float Bs[16][64];

    int tid = threadIdx.x, tx = tid & 15, ty = tid >> 4;

    float acc[4][4];
#pragma unroll
    for (int i = 0; i < 4; i++)
#pragma unroll
        for (int j = 0; j < 4; j++) acc[i][j] = 0.f;

    int lr = tid >> 2, lk = (tid & 3) * 4;
    int brow = tid >> 4, bcol = (tid & 15) * 4;
    const float* Wb = W2 + (size_t)e * F_ * D_ + bn;
    const float* Arow = g_up + ((size_t)e * T_ + rb + lr) * F_ + lk;

    for (int k0 = 0; k0 < F_; k0 += 16) {
        float4 a4 = *(const float4*)(Arow + k0);
        float4 b4 = *(const float4*)(Wb + (size_t)(k0 + brow) * D_ + bcol);
        As[lk + 0][lr] = a4.x; As[lk + 1][lr] = a4.y;
        As[lk + 2][lr] = a4.z; As[lk + 3][lr] = a4.w;
        *(float4*)&Bs[brow][bcol] = b4;
        __syncthreads();
#pragma unroll
        for (int k = 0; k < 16; k++) {
            float4 a = *(const float4*)&As[k][ty * 4];
            float4 b = *(const float4*)&Bs[k][tx * 4];
            float ar[4] = {a.x, a.y, a.z, a.w};
            float br[4] = {b.x, b.y, b.z, b.w};
#pragma unroll
            for (int i = 0; i < 4; i++)
#pragma unroll
                for (int j = 0; j < 4; j++) acc[i][j] = fmaf(ar[i], br[j], acc[i][j]);
        }
        __syncthreads();
    }

#pragma unroll
    for (int i = 0; i < 4; i++) {
        int rg = rb + ty * 4 + i;
        if (rg < n) {
            int t = g_elist[e * T_ + rg];
            float* op = out + (size_t)t * D_ + bn + tx * 4;
#pragma unroll
            for (int j = 0; j < 4; j++) atomicAdd(&op[j], acc[i][j]);
        }
    }
}

// ---------------- launch --------------------------------------------------------
extern "C" void kernel_launch(void* const* d_in, const int* in_sizes, int n_in,
                              void* d_out, int out_size) {
    (void)in_sizes; (void)n_in; (void)out_size;
    const float* x    = (const float*)d_in[0];
    const float* Wq   = (const float*)d_in[1];
    const float* Wk   = (const float*)d_in[2];
    const float* Wv   = (const float*)d_in[3];
    const float* Wo   = (const float*)d_in[4];
    const float* ln1s = (const float*)d_in[5];
    const float* ln1b = (const float*)d_in[6];
    const float* ln2s = (const float*)d_in[7];
    const float* ln2b = (const float*)d_in[8];
    const float* Wsel = (const float*)d_in[9];
    const float* W1   = (const float*)d_in[10];
    const float* W2   = (const float*)d_in[11];
    float* out = (float*)d_out;

    float *h1p, *qp, *kp, *vp, *ctxp, *x2p, *h2p;
    cudaGetSymbolAddress((void**)&h1p, g_h1);
    cudaGetSymbolAddress((void**)&qp,  g_q);
    cudaGetSymbolAddress((void**)&kp,  g_k);
    cudaGetSymbolAddress((void**)&vp,  g_v);
    cudaGetSymbolAddress((void**)&ctxp, g_ctx);
    cudaGetSymbolAddress((void**)&x2p, g_x2);
    cudaGetSymbolAddress((void**)&h2p, g_h2);

    zero_cnt_kernel<<<1, 32>>>();
    ln_kernel<<<T_, 256>>>(x, ln1s, ln1b, h1p);

    dim3 gg(D_ / 128, T_ / 128);
    sgemm128<<<gg, 256>>>(h1p, Wq, nullptr, qp, nullptr, T_, D_, D_);
    sgemm128<<<gg, 256>>>(h1p, Wk, nullptr, kp, nullptr, T_, D_, D_);
    sgemm128<<<gg, 256>>>(h1p, Wv, nullptr, vp, nullptr, T_, D_, D_);

    attn_kernel<<<dim3(S_ / 64, B_ * H_), 256>>>(qp, kp, vp, ctxp);

    // x2 = x + ctx @ Wo ; also initialize d_out with x2 (moe scatters on top)
    sgemm128<<<gg, 256>>>(ctxp, Wo, x, x2p, out, T_, D_, D_);

    ln_kernel<<<T_, 256>>>(x2p, ln2s, ln2b, h2p);
    selector_kernel<<<T_ / 4, 128>>>(h2p, Wsel);

    moe_up_kernel<<<dim3(F_ / 64, T_ / 64, E_), 256>>>(h2p, W1);
    moe_down_kernel<<<dim3(D_ / 64, T_ / 64, E_), 256>>>(W2, out);
}

// round 3
// speedup vs baseline: 1.8210x; 1.8210x over previous
#include <cuda_runtime.h>
#include <math.h>

#define B_  2
#define S_  2048
#define D_  1024
#define H_  16
#define DH_ 64
#define E_  16
#define F_  256
#define T_  (B_*S_)

// ---------------- scratch ----------------
__device__ float g_h1[(size_t)T_*D_];
__device__ float g_q [(size_t)T_*D_];
__device__ float g_k [(size_t)T_*D_];
__device__ float g_v [(size_t)T_*D_];
__device__ float g_ctx[(size_t)T_*D_];
__device__ float g_x2[(size_t)T_*D_];
__device__ float g_h2[(size_t)T_*D_];
__device__ float g_up[(size_t)E_*T_*F_];
__device__ int   g_cnt[E_];
__device__ int   g_elist[E_*T_];
__device__ float g_egate[E_*T_];

__global__ void zero_cnt_kernel() {
    if (threadIdx.x < E_) g_cnt[threadIdx.x] = 0;
}

// ---------------- tf32 helpers ----------------
__device__ __forceinline__ unsigned f2tf(float f) {
    unsigned u;
    asm("cvt.rna.tf32.f32 %0, %1;" : "=r"(u) : "f"(f));
    return u;
}

__device__ __forceinline__ void mma8(float* d, const unsigned* a, unsigned b0, unsigned b1) {
    asm volatile(
        "mma.sync.aligned.m16n8k8.row.col.f32.tf32.tf32.f32 "
        "{%0,%1,%2,%3},{%4,%5,%6,%7},{%8,%9},{%0,%1,%2,%3};"
        : "+f"(d[0]), "+f"(d[1]), "+f"(d[2]), "+f"(d[3])
        : "r"(a[0]), "r"(a[1]), "r"(a[2]), "r"(a[3]), "r"(b0), "r"(b1));
}

// ---------------- LayerNorm ----------------
__global__ __launch_bounds__(256) void ln_kernel(const float* __restrict__ x,
                                                 const float* __restrict__ sc,
                                                 const float* __restrict__ bi,
                                                 float* __restrict__ o) {
    int t = blockIdx.x;
    const float* xr = x + (size_t)t * D_;
    float* orow = o + (size_t)t * D_;
    float v[4];
    float s = 0.f, s2 = 0.f;
#pragma unroll
    for (int i = 0; i < 4; i++) {
        v[i] = xr[threadIdx.x + i * 256];
        s  += v[i];
        s2 += v[i] * v[i];
    }
#pragma unroll
    for (int off = 16; off; off >>= 1) {
        s  += __shfl_xor_sync(0xffffffffu, s,  off);
        s2 += __shfl_xor_sync(0xffffffffu, s2, off);
    }
    __shared__ float ws[8], ws2[8];
    int w = threadIdx.x >> 5, ln = threadIdx.x & 31;
    if (ln == 0) { ws[w] = s; ws2[w] = s2; }
    __syncthreads();
    float S = 0.f, S2 = 0.f;
#pragma unroll
    for (int i = 0; i < 8; i++) { S += ws[i]; S2 += ws2[i]; }
    float mu  = S * (1.0f / D_);
    float var = S2 * (1.0f / D_) - mu * mu;
    float inv = rsqrtf(var + 1e-5f);
#pragma unroll
    for (int i = 0; i < 4; i++) {
        int d = threadIdx.x + i * 256;
        orow[d] = (v[i] - mu) * inv * sc[d] + bi[d];
    }
}

// ---------------- tf32 tensor-core GEMM: 128x128 block, BK=16 -------------------
// C = A(MxK) @ B(KxN) [+Res]; optional dup to C2. M%128==0, N%128==0, K%16==0.
__global__ __launch_bounds__(256) void gemm_tf32(const float* __restrict__ A,
                                                 const float* __restrict__ Bm,
                                                 const float* __restrict__ Res,
                                                 float* __restrict__ C,
                                                 float* __restrict__ C2,
                                                 int M, int N, int K) {
    __shared__ unsigned As[128][20];   // row-major [m][k], pad to 20
    __shared__ unsigned Bs[16][136];   // row-major [k][n], pad to 136 (stride%32==8)

    int tid = threadIdx.x, warp = tid >> 5, lane = tid & 31;
    int g = lane >> 2, t4 = lane & 3;
    int wm = warp >> 1, wn = warp & 1;     // 4 x 2 warps; warp tile 32x64
    int bx = blockIdx.x * 128, by = blockIdx.y * 128;

    float acc[2][8][4];
#pragma unroll
    for (int i = 0; i < 2; i++)
#pragma unroll
        for (int j = 0; j < 8; j++)
#pragma unroll
            for (int q = 0; q < 4; q++) acc[i][j][q] = 0.f;

    int ar = tid >> 2, ac = (tid & 3) * 4;        // A: rows 0..127, cols {0,4,8,12}
    int ar2 = (tid + 256) >> 2;                    // second A float4 (rows 64..127)
    int br = tid >> 5, bc = (tid & 31) * 4;       // B: rows 0..7 / 8..15, cols 0..124

    for (int k0 = 0; k0 < K; k0 += 16) {
        float4 a0 = *(const float4*)(A + (size_t)(by + ar)  * K + k0 + ac);
        float4 a1 = *(const float4*)(A + (size_t)(by + ar2) * K + k0 + ac);
        float4 b0 = *(const float4*)(Bm + (size_t)(k0 + br)     * N + bx + bc);
        float4 b1 = *(const float4*)(Bm + (size_t)(k0 + br + 8) * N + bx + bc);
        __syncthreads();
        {
            uint4 u;
            u.x = f2tf(a0.x); u.y = f2tf(a0.y); u.z = f2tf(a0.z); u.w = f2tf(a0.w);
            *(uint4*)&As[ar][ac] = u;
            u.x = f2tf(a1.x); u.y = f2tf(a1.y); u.z = f2tf(a1.z); u.w = f2tf(a1.w);
            *(uint4*)&As[ar2][ac] = u;
            u.x = f2tf(b0.x); u.y = f2tf(b0.y); u.z = f2tf(b0.z); u.w = f2tf(b0.w);
            *(uint4*)&Bs[br][bc] = u;
            u.x = f2tf(b1.x); u.y = f2tf(b1.y); u.z = f2tf(b1.z); u.w = f2tf(b1.w);
            *(uint4*)&Bs[br + 8][bc] = u;
        }
        __syncthreads();

#pragma unroll
        for (int kk = 0; kk < 16; kk += 8) {
            unsigned afr[2][4];
#pragma unroll
            for (int mt = 0; mt < 2; mt++) {
                int r0 = wm * 32 + mt * 16;
                afr[mt][0] = As[r0 + g][kk + t4];
                afr[mt][1] = As[r0 + g + 8][kk + t4];
                afr[mt][2] = As[r0 + g][kk + t4 + 4];
                afr[mt][3] = As[r0 + g + 8][kk + t4 + 4];
            }
#pragma unroll
            for (int nt = 0; nt < 8; nt++) {
                int c0 = wn * 64 + nt * 8 + g;
                unsigned bb0 = Bs[kk + t4][c0];
                unsigned bb1 = Bs[kk + t4 + 4][c0];
                mma8(acc[0][nt], afr[0], bb0, bb1);
                mma8(acc[1][nt], afr[1], bb0, bb1);
            }
        }
    }

#pragma unroll
    for (int mt = 0; mt < 2; mt++) {
#pragma unroll
        for (int nt = 0; nt < 8; nt++) {
            int col = bx + wn * 64 + nt * 8 + 2 * t4;
            size_t r0 = (size_t)(by + wm * 32 + mt * 16 + g);
            size_t r1 = r0 + 8;
            float2 v01 = {acc[mt][nt][0], acc[mt][nt][1]};
            float2 v23 = {acc[mt][nt][2], acc[mt][nt][3]};
            if (Res) {
                float2 q0 = *(const float2*)(Res + r0 * N + col);
                float2 q1 = *(const float2*)(Res + r1 * N + col);
                v01.x += q0.x; v01.y += q0.y;
                v23.x += q1.x; v23.y += q1.y;
            }
            *(float2*)(C + r0 * N + col) = v01;
            *(float2*)(C + r1 * N + col) = v23;
            if (C2) {
                *(float2*)(C2 + r0 * N + col) = v01;
                *(float2*)(C2 + r1 * N + col) = v23;
            }
        }
    }
}

// ---------------- Flash attention with tf32 mma: 64q x 64k tiles ----------------
// grid (S/64, B*H), 256 threads. Dynamic smem.
#define QS_  0
#define KS_  4352            /* 64*68 */
#define VS_  8704            /* 64*68 */
#define SP_  13312           /* v stride 72 -> 64*72=4608 */
#define MS_  17664
#define LS_  17728
#define ALS_ 17792
#define ATTN_SMEM_FLOATS 17856

__global__ __launch_bounds__(256) void attn_tf32_kernel(const float* __restrict__ Q,
                                                        const float* __restrict__ Kt,
                                                        const float* __restrict__ V,
                                                        float* __restrict__ O) {
    extern __shared__ float smem[];
    unsigned* q_s = (unsigned*)(smem + QS_);   // [64][68] tf32, row=q, col=d
    unsigned* k_s = (unsigned*)(smem + KS_);   // [64][68] tf32, row=key, col=d
    unsigned* v_s = (unsigned*)(smem + VS_);   // [64][72] tf32, row=key, col=d
    float*    s_p = smem + SP_;                // [64][68] scores -> tf32 P (aliased)
    float*    m_s = smem + MS_;
    float*    l_s = smem + LS_;
    float*    al_s = smem + ALS_;

    int bh = blockIdx.y;
    int b = bh >> 4, h = bh & 15;
    int q0 = blockIdx.x * 64;

    int tid = threadIdx.x, warp = tid >> 5, lane = tid & 31;
    int g = lane >> 2, t4 = lane & 3;
    int wm = warp >> 1, wn = warp & 1;     // 4 x 2 warps; warp tile 16x32

    // load Q tile (scaled by 1/sqrt(DH)=0.125, converted to tf32)
#pragma unroll
    for (int i = 0; i < 4; i++) {
        int flat = tid + i * 256;
        int r = flat >> 4, c = (flat & 15) * 4;
        float4 f = *(const float4*)(Q + (size_t)(b * S_ + q0 + r) * D_ + h * DH_ + c);
        uint4 u;
        u.x = f2tf(f.x * 0.125f); u.y = f2tf(f.y * 0.125f);
        u.z = f2tf(f.z * 0.125f); u.w = f2tf(f.w * 0.125f);
        *(uint4*)&q_s[r * 68 + c] = u;
    }
    if (tid < 64) { m_s[tid] = -1e30f; l_s[tid] = 0.f; }

    float acc[4][4];
#pragma unroll
    for (int i = 0; i < 4; i++)
#pragma unroll
        for (int j = 0; j < 4; j++) acc[i][j] = 0.f;

    for (int kt = 0; kt < S_; kt += 64) {
        __syncthreads();   // prior PV reads of v_s / s_p complete
#pragma unroll
        for (int i = 0; i < 4; i++) {
            int flat = tid + i * 256;
            int r = flat >> 4, c = (flat & 15) * 4;
            size_t base = (size_t)(b * S_ + kt + r) * D_ + h * DH_ + c;
            float4 fk = *(const float4*)(Kt + base);
            float4 fv = *(const float4*)(V + base);
            uint4 uk, uv;
            uk.x = f2tf(fk.x); uk.y = f2tf(fk.y); uk.z = f2tf(fk.z); uk.w = f2tf(fk.w);
            uv.x = f2tf(fv.x); uv.y = f2tf(fv.y); uv.z = f2tf(fv.z); uv.w = f2tf(fv.w);
            *(uint4*)&k_s[r * 68 + c] = uk;
            *(uint4*)&v_s[r * 72 + c] = uv;
        }
        __syncthreads();

        // ---- S = (Q*scale) @ K^T ----
        float sacc[4][4];
#pragma unroll
        for (int i = 0; i < 4; i++)
#pragma unroll
            for (int j = 0; j < 4; j++) sacc[i][j] = 0.f;

#pragma unroll
        for (int kk = 0; kk < 64; kk += 8) {
            unsigned afr[4];
            int r0 = wm * 16;
            afr[0] = q_s[(r0 + g) * 68 + kk + t4];
            afr[1] = q_s[(r0 + g + 8) * 68 + kk + t4];
            afr[2] = q_s[(r0 + g) * 68 + kk + t4 + 4];
            afr[3] = q_s[(r0 + g + 8) * 68 + kk + t4 + 4];
#pragma unroll
            for (int nt = 0; nt < 4; nt++) {
                int cn = wn * 32 + nt * 8 + g;
                unsigned bb0 = k_s[cn * 68 + kk + t4];
                unsigned bb1 = k_s[cn * 68 + kk + t4 + 4];
                mma8(sacc[nt], afr, bb0, bb1);
            }
        }
        // write scores tile
#pragma unroll
        for (int nt = 0; nt < 4; nt++) {
            int col = wn * 32 + nt * 8 + 2 * t4;
            int row = wm * 16 + g;
            *(float2*)&s_p[row * 68 + col]       = make_float2(sacc[nt][0], sacc[nt][1]);
            *(float2*)&s_p[(row + 8) * 68 + col] = make_float2(sacc[nt][2], sacc[nt][3]);
        }
        __syncthreads();

        // ---- online softmax: warp w owns rows w*8 .. w*8+7 ----
#pragma unroll
        for (int rr = 0; rr < 8; rr++) {
            int r = warp * 8 + rr;
            float x0 = s_p[r * 68 + lane];
            float x1 = s_p[r * 68 + lane + 32];
            float mx = fmaxf(x0, x1);
#pragma unroll
            for (int o = 16; o; o >>= 1) mx = fmaxf(mx, __shfl_xor_sync(0xffffffffu, mx, o));
            float mold = m_s[r];
            float mnew = fmaxf(mold, mx);
            float p0 = __expf(x0 - mnew);
            float p1 = __expf(x1 - mnew);
            float rs = p0 + p1;
#pragma unroll
            for (int o = 16; o; o >>= 1) rs += __shfl_xor_sync(0xffffffffu, rs, o);
            ((unsigned*)s_p)[r * 68 + lane]      = f2tf(p0);
            ((unsigned*)s_p)[r * 68 + lane + 32] = f2tf(p1);
            if (lane == 0) {
                float al = __expf(mold - mnew);
                al_s[r] = al;
                m_s[r] = mnew;
                l_s[r] = l_s[r] * al + rs;
            }
        }
        __syncthreads();

        // ---- rescale O, then O += P @ V ----
        float al0 = al_s[wm * 16 + g];
        float al1 = al_s[wm * 16 + 8 + g];
#pragma unroll
        for (int nt = 0; nt < 4; nt++) {
            acc[nt][0] *= al0; acc[nt][1] *= al0;
            acc[nt][2] *= al1; acc[nt][3] *= al1;
        }
#pragma unroll
        for (int kk = 0; kk < 64; kk += 8) {
            unsigned afr[4];
            int r0 = wm * 16;
            const unsigned* pp = (const unsigned*)s_p;
            afr[0] = pp[(r0 + g) * 68 + kk + t4];
            afr[1] = pp[(r0 + g + 8) * 68 + kk + t4];
            afr[2] = pp[(r0 + g) * 68 + kk + t4 + 4];
            afr[3] = pp[(r0 + g + 8) * 68 + kk + t4 + 4];
#pragma unroll
            for (int nt = 0; nt < 4; nt++) {
                int cn = wn * 32 + nt * 8 + g;
                unsigned bb0 = v_s[(kk + t4) * 72 + cn];
                unsigned bb1 = v_s[(kk + t4 + 4) * 72 + cn];
                mma8(acc[nt], afr, bb0, bb1);
            }
        }
    }

    // epilogue: divide by l, store
    float il0 = 1.0f / l_s[wm * 16 + g];
    float il1 = 1.0f / l_s[wm * 16 + 8 + g];
#pragma unroll
    for (int nt = 0; nt < 4; nt++) {
        int col = wn * 32 + nt * 8 + 2 * t4;
        int row = wm * 16 + g;
        size_t b0 = (size_t)(b * S_ + q0 + row) * D_ + h * DH_ + col;
        size_t b1 = (size_t)(b * S_ + q0 + row + 8) * D_ + h * DH_ + col;
        *(float2*)(O + b0) = make_float2(acc[nt][0] * il0, acc[nt][1] * il0);
        *(float2*)(O + b1) = make_float2(acc[nt][2] * il1, acc[nt][3] * il1);
    }
}

// ---------------- Selector ----------------
__global__ __launch_bounds__(128) void selector_kernel(const float* __restrict__ h,
                                                       const float* __restrict__ Wsel) {
    int t = blockIdx.x * 4 + (threadIdx.x >> 5);
    int lane = threadIdx.x & 31;
    float acc[16];
#pragma unroll
    for (int e = 0; e < 16; e++) acc[e] = 0.f;
    const float* hr = h + (size_t)t * D_;
    for (int d = lane; d < D_; d += 32) {
        float hv = hr[d];
        const float4* w = (const float4*)(Wsel + (size_t)d * E_);
        float4 w0 = w[0], w1 = w[1], w2 = w[2], w3 = w[3];
        acc[0]  = fmaf(hv, w0.x, acc[0]);  acc[1]  = fmaf(hv, w0.y, acc[1]);
        acc[2]  = fmaf(hv, w0.z, acc[2]);  acc[3]  = fmaf(hv, w0.w, acc[3]);
        acc[4]  = fmaf(hv, w1.x, acc[4]);  acc[5]  = fmaf(hv, w1.y, acc[5]);
        acc[6]  = fmaf(hv, w1.z, acc[6]);  acc[7]  = fmaf(hv, w1.w, acc[7]);
        acc[8]  = fmaf(hv, w2.x, acc[8]);  acc[9]  = fmaf(hv, w2.y, acc[9]);
        acc[10] = fmaf(hv, w2.z, acc[10]); acc[11] = fmaf(hv, w2.w, acc[11]);
        acc[12] = fmaf(hv, w3.x, acc[12]); acc[13] = fmaf(hv, w3.y, acc[13]);
        acc[14] = fmaf(hv, w3.z, acc[14]); acc[15] = fmaf(hv, w3.w, acc[15]);
    }
#pragma unroll
    for (int e = 0; e < 16; e++)
#pragma unroll
        for (int o = 16; o; o >>= 1) acc[e] += __shfl_xor_sync(0xffffffffu, acc[e], o);
    if (lane == 0) {
        float v1 = -1.f, v2 = -1.f;
        int i1 = 0, i2 = 0;
#pragma unroll
        for (int e = 0; e < 16; e++) {
            float sg = 1.0f / (1.0f + __expf(-acc[e]));
            if (sg > v1) { v2 = v1; i2 = i1; v1 = sg; i1 = e; }
            else if (sg > v2) { v2 = sg; i2 = e; }
        }
        int p1 = atomicAdd(&g_cnt[i1], 1);
        g_elist[i1 * T_ + p1] = t;
        g_egate[i1 * T_ + p1] = v1;
        int p2 = atomicAdd(&g_cnt[i2], 1);
        g_elist[i2 * T_ + p2] = t;
        g_egate[i2 * T_ + p2] = v2;
    }
}

// ---------------- MoE up ----------------
__global__ __launch_bounds__(256) void moe_up_kernel(const float* __restrict__ h,
                                                     const float* __restrict__ W1) {
    int e = blockIdx.z;
    int n = g_cnt[e];
    int rb = blockIdx.y * 64;
    if (rb >= n) return;
    int bn = blockIdx.x * 64;

    __shared__ float As[16][64];
    __shared__ float Bs[16][64];
    __shared__ int rows[64];

    int tid = threadIdx.x, tx = tid & 15, ty = tid >> 4;
    if (tid < 64) {
        int rg = rb + tid;
        rows[tid] = (rg < n) ? g_elist[e * T_ + rg] : 0;
    }
    __syncthreads();

    float acc[4][4];
#pragma unroll
    for (int i = 0; i < 4; i++)
#pragma unroll
        for (int j = 0; j < 4; j++) acc[i][j] = 0.f;

    int lr = tid >> 2, lk = (tid & 3) * 4;
    int brow = tid >> 4, bcol = (tid & 15) * 4;
    const float* Wb = W1 + (size_t)e * D_ * F_ + bn;
    const float* Arow = h + (size_t)rows[lr] * D_ + lk;

    for (int k0 = 0; k0 < D_; k0 += 16) {
        float4 a4 = *(const float4*)(Arow + k0);
        float4 b4 = *(const float4*)(Wb + (size_t)(k0 + brow) * F_ + bcol);
        As[lk + 0][lr] = a4.x; As[lk + 1][lr] = a4.y;
        As[lk + 2][lr] = a4.z; As[lk + 3][lr] = a4.w;
        *(float4*)&Bs[brow][bcol] = b4;
        __syncthreads();
#pragma unroll
        for (int k = 0; k < 16; k++) {
            float4 a = *(const float4*)&As[k][ty * 4];
            float4 b = *(const float4*)&Bs[k][tx * 4];
            float ar[4] = {a.x, a.y, a.z, a.w};
            float br[4] = {b.x, b.y, b.z, b.w};
#pragma unroll
            for (int i = 0; i < 4; i++)
#pragma unroll
                for (int j = 0; j < 4; j++) acc[i][j] = fmaf(ar[i], br[j], acc[i][j]);
        }
        __syncthreads();
    }

#pragma unroll
    for (int i = 0; i < 4; i++) {
        int rg = rb + ty * 4 + i;
        if (rg < n) {
            float gte = g_egate[e * T_ + rg];
            float* op = g_up + ((size_t)e * T_ + rg) * F_ + bn + tx * 4;
#pragma unroll
            for (int j = 0; j < 4; j++) op[j] = fmaxf(acc[i][j], 0.f) * gte;
        }
    }
}

// ---------------- MoE down ----------------
__global__ __launch_bounds__(256) void moe_down_kernel(const float* __restrict__ W2,
                                                       float* __restrict__ out) {
    int e = blockIdx.z;
    int n = g_cnt[e];
    int rb = blockIdx.y * 64;
    if (rb >= n) return;
    int bn = blockIdx.x * 64;

    __shared__ float As[16][64];
    __shared__ float Bs[16][64];

    int tid = threadIdx.x, tx = tid & 15, ty = tid >> 4;

    float acc[4][4];
#pragma unroll
    for (int i = 0; i < 4; i++)
#pragma unroll
        for (int j = 0; j < 4; j++) acc[i][j] = 0.f;

    int lr = tid >> 2, lk = (tid & 3) * 4;
    int brow = tid >> 4, bcol = (tid & 15) * 4;
    const float* Wb = W2 + (size_t)e * F_ * D_ + bn;
    const float* Arow = g_up + ((size_t)e * T_ + rb + lr) * F_ + lk;

    for (int k0 = 0; k0 < F_; k0 += 16) {
        float4 a4 = *(const float4*)(Arow + k0);
        float4 b4 = *(const float4*)(Wb + (size_t)(k0 + brow) * D_ + bcol);
        As[lk + 0][lr] = a4.x; As[lk + 1][lr] = a4.y;
        As[lk + 2][lr] = a4.z; As[lk + 3][lr] = a4.w;
        *(float4*)&Bs[brow][bcol] = b4;
        __syncthreads();
#pragma unroll
        for (int k = 0; k < 16; k++) {
            float4 a = *(const float4*)&As[k][ty * 4];
            float4 b = *(const float4*)&Bs[k][tx * 4];
            float ar[4] = {a.x, a.y, a.z, a.w};
            float br[4] = {b.x, b.y, b.z, b.w};
#pragma unroll
            for (int i = 0; i < 4; i++)
#pragma unroll
                for (int j = 0; j < 4; j++) acc[i][j] = fmaf(ar[i], br[j], acc[i][j]);
        }
        __syncthreads();
    }

#pragma unroll
    for (int i = 0; i < 4; i++) {
        int rg = rb + ty * 4 + i;
        if (rg < n) {
            int t = g_elist[e * T_ + rg];
            float* op = out + (size_t)t * D_ + bn + tx * 4;
#pragma unroll
            for (int j = 0; j < 4; j++) atomicAdd(&op[j], acc[i][j]);
        }
    }
}

// ---------------- launch ----------------
extern "C" void kernel_launch(void* const* d_in, const int* in_sizes, int n_in,
                              void* d_out, int out_size) {
    (void)in_sizes; (void)n_in; (void)out_size;
    const float* x    = (const float*)d_in[0];
    const float* Wq   = (const float*)d_in[1];
    const float* Wk   = (const float*)d_in[2];
    const float* Wv   = (const float*)d_in[3];
    const float* Wo   = (const float*)d_in[4];
    const float* ln1s = (const float*)d_in[5];
    const float* ln1b = (const float*)d_in[6];
    const float* ln2s = (const float*)d_in[7];
    const float* ln2b = (const float*)d_in[8];
    const float* Wsel = (const float*)d_in[9];
    const float* W1   = (const float*)d_in[10];
    const float* W2   = (const float*)d_in[11];
    float* out = (float*)d_out;

    float *h1p, *qp, *kp, *vp, *ctxp, *x2p, *h2p;
    cudaGetSymbolAddress((void**)&h1p, g_h1);
    cudaGetSymbolAddress((void**)&qp,  g_q);
    cudaGetSymbolAddress((void**)&kp,  g_k);
    cudaGetSymbolAddress((void**)&vp,  g_v);
    cudaGetSymbolAddress((void**)&ctxp, g_ctx);
    cudaGetSymbolAddress((void**)&x2p, g_x2);
    cudaGetSymbolAddress((void**)&h2p, g_h2);

    static int attn_smem_set = 0;
    if (!attn_smem_set) {
        cudaFuncSetAttribute(attn_tf32_kernel,
                             cudaFuncAttributeMaxDynamicSharedMemorySize,
                             ATTN_SMEM_FLOATS * sizeof(float));
        attn_smem_set = 1;
    }

    zero_cnt_kernel<<<1, 32>>>();
    ln_kernel<<<T_, 256>>>(x, ln1s, ln1b, h1p);

    dim3 gg(D_ / 128, T_ / 128);
    gemm_tf32<<<gg, 256>>>(h1p, Wq, nullptr, qp, nullptr, T_, D_, D_);
    gemm_tf32<<<gg, 256>>>(h1p, Wk, nullptr, kp, nullptr, T_, D_, D_);
    gemm_tf32<<<gg, 256>>>(h1p, Wv, nullptr, vp, nullptr, T_, D_, D_);

    attn_tf32_kernel<<<dim3(S_ / 64, B_ * H_), 256,
                       ATTN_SMEM_FLOATS * sizeof(float)>>>(qp, kp, vp, ctxp);

    // x2 = x + ctx @ Wo ; dup into d_out (moe scatters on top)
    gemm_tf32<<<gg, 256>>>(ctxp, Wo, x, x2p, out, T_, D_, D_);

    ln_kernel<<<T_, 256>>>(x2p, ln2s, ln2b, h2p);
    selector_kernel<<<T_ / 4, 128>>>(h2p, Wsel);

    moe_up_kernel<<<dim3(F_ / 64, T_ / 64, E_), 256>>>(h2p, W1);
    moe_down_kernel<<<dim3(D_ / 64, T_ / 64, E_), 256>>>(W2, out);
}

// round 5
// speedup vs baseline: 4.7523x; 2.6097x over previous
#include <cuda_runtime.h>
#include <cuda_fp16.h>
#include <math.h>

#define B_  2
#define S_  2048
#define D_  1024
#define H_  16
#define DH_ 64
#define E_  16
#define F_  256
#define T_  (B_*S_)

// ---------------- scratch ----------------
__device__ __half g_wqkvh[(size_t)3*D_*D_];
__device__ __half g_woh[(size_t)D_*D_];
__device__ __half g_h1h[(size_t)T_*D_];
__device__ __half g_qkvh[(size_t)3*T_*D_];
__device__ __half g_ctxh[(size_t)T_*D_];
__device__ float g_x2[(size_t)T_*D_];
__device__ float g_h2[(size_t)T_*D_];
__device__ float g_up[(size_t)E_*T_*F_];
__device__ int   g_cnt[E_];
__device__ int   g_elist[E_*T_];
__device__ float g_egate[E_*T_];

__global__ void zero_cnt_kernel() {
    if (threadIdx.x < E_) g_cnt[threadIdx.x] = 0;
}

// ---------------- helpers ----------------
__device__ __forceinline__ unsigned packh(float lo, float hi) {
    unsigned u;
    asm("cvt.rn.f16x2.f32 %0, %1, %2;" : "=r"(u) : "f"(hi), "f"(lo));
    return u;
}

__device__ __forceinline__ void mma16(float* d, const unsigned* a, unsigned b0, unsigned b1) {
    asm volatile(
        "mma.sync.aligned.m16n8k16.row.col.f32.f16.f16.f32 "
        "{%0,%1,%2,%3},{%4,%5,%6,%7},{%8,%9},{%0,%1,%2,%3};"
        : "+f"(d[0]), "+f"(d[1]), "+f"(d[2]), "+f"(d[3])
        : "r"(a[0]), "r"(a[1]), "r"(a[2]), "r"(a[3]), "r"(b0), "r"(b1));
}

// ---------------- fp32 -> fp16 convert (weights, once per call) -----------------
__global__ __launch_bounds__(256) void conv_f2h(const float4* __restrict__ s,
                                                uint2* __restrict__ d, int n4) {
    int i = blockIdx.x * blockDim.x + threadIdx.x;
    int stride = gridDim.x * blockDim.x;
    for (; i < n4; i += stride) {
        float4 v = s[i];
        uint2 o;
        o.x = packh(v.x, v.y);
        o.y = packh(v.z, v.w);
        d[i] = o;
    }
}

// ---------------- LayerNorm (fp32 out) ----------------
__global__ __launch_bounds__(256) void ln_kernel(const float* __restrict__ x,
                                                 const float* __restrict__ sc,
                                                 const float* __restrict__ bi,
                                                 float* __restrict__ o) {
    int t = blockIdx.x;
    const float* xr = x + (size_t)t * D_;
    float* orow = o + (size_t)t * D_;
    float v[4];
    float s = 0.f, s2 = 0.f;
#pragma unroll
    for (int i = 0; i < 4; i++) {
        v[i] = xr[threadIdx.x + i * 256];
        s  += v[i];
        s2 += v[i] * v[i];
    }
#pragma unroll
    for (int off = 16; off; off >>= 1) {
        s  += __shfl_xor_sync(0xffffffffu, s,  off);
        s2 += __shfl_xor_sync(0xffffffffu, s2, off);
    }
    __shared__ float ws[8], ws2[8];
    int w = threadIdx.x >> 5, ln = threadIdx.x & 31;
    if (ln == 0) { ws[w] = s; ws2[w] = s2; }
    __syncthreads();
    float S = 0.f, S2 = 0.f;
#pragma unroll
    for (int i = 0; i < 8; i++) { S += ws[i]; S2 += ws2[i]; }
    float mu  = S * (1.0f / D_);
    float var = S2 * (1.0f / D_) - mu * mu;
    float inv = rsqrtf(var + 1e-5f);
#pragma unroll
    for (int i = 0; i < 4; i++) {
        int d = threadIdx.x + i * 256;
        orow[d] = (v[i] - mu) * inv * sc[d] + bi[d];
    }
}

// ---------------- LayerNorm (fp16 out) ----------------
__global__ __launch_bounds__(256) void ln_h_kernel(const float* __restrict__ x,
                                                   const float* __restrict__ sc,
                                                   const float* __restrict__ bi,
                                                   __half* __restrict__ o) {
    int t = blockIdx.x;
    const float* xr = x + (size_t)t * D_;
    __half* orow = o + (size_t)t * D_;
    float v[4];
    float s = 0.f, s2 = 0.f;
#pragma unroll
    for (int i = 0; i < 4; i++) {
        v[i] = xr[threadIdx.x + i * 256];
        s  += v[i];
        s2 += v[i] * v[i];
    }
#pragma unroll
    for (int off = 16; off; off >>= 1) {
        s  += __shfl_xor_sync(0xffffffffu, s,  off);
        s2 += __shfl_xor_sync(0xffffffffu, s2, off);
    }
    __shared__ float ws[8], ws2[8];
    int w = threadIdx.x >> 5, ln = threadIdx.x & 31;
    if (ln == 0) { ws[w] = s; ws2[w] = s2; }
    __syncthreads();
    float S = 0.f, S2 = 0.f;
#pragma unroll
    for (int i = 0; i < 8; i++) { S += ws[i]; S2 += ws2[i]; }
    float mu  = S * (1.0f / D_);
    float var = S2 * (1.0f / D_) - mu * mu;
    float inv = rsqrtf(var + 1e-5f);
#pragma unroll
    for (int i = 0; i < 4; i++) {
        int d = threadIdx.x + i * 256;
        orow[d] = __float2half((v[i] - mu) * inv * sc[d] + bi[d]);
    }
}

// ---------------- fp16 tensor-core GEMM: 128x128 block, BK=32 -------------------
// A fp16 [M][K] row-major, Bw fp16 [K][N] row-major (z-indexed).
// MODE 0: store fp16 C (z-indexed base Cb).  MODE 1: fp32 C = A@B + Res, dup C2.
template <int MODE>
__global__ __launch_bounds__(256) void gemm_h(const __half* __restrict__ A,
                                              const __half* __restrict__ Bw,
                                              const float* __restrict__ Res,
                                              float* __restrict__ Cf,
                                              float* __restrict__ C2f,
                                              __half* __restrict__ Cb,
                                              int M, int N, int K) {
    __shared__ unsigned As32[128 * 20];   // [m][k2], stride 20
    __shared__ unsigned Bs32[16 * 132];   // [k2][n], stride 132

    const __half* Bz = Bw + (size_t)blockIdx.z * K * N;
    int tid = threadIdx.x, warp = tid >> 5, lane = tid & 31;
    int g = lane >> 2, t4 = lane & 3;
    int wm = warp >> 1, wn = warp & 1;     // 4x2 warps; warp tile 32x64
    int bx = blockIdx.x * 128, by = blockIdx.y * 128;

    float acc[2][8][4];
#pragma unroll
    for (int i = 0; i < 2; i++)
#pragma unroll
        for (int j = 0; j < 8; j++)
#pragma unroll
            for (int q = 0; q < 4; q++) acc[i][j][q] = 0.f;

    int ar = tid >> 1, ah = tid & 1;           // A: row, k-half
    int bk2 = tid >> 4, bc8 = (tid & 15) * 8;  // B: k-pair row, col chunk

    for (int k0 = 0; k0 < K; k0 += 32) {
        const uint4* ap = (const uint4*)(A + (size_t)(by + ar) * K + k0 + ah * 16);
        uint4 a0 = ap[0], a1 = ap[1];
        const uint4* bp0 = (const uint4*)(Bz + (size_t)(k0 + 2 * bk2) * N + bx + bc8);
        const uint4* bp1 = (const uint4*)(Bz + (size_t)(k0 + 2 * bk2 + 1) * N + bx + bc8);
        uint4 w0 = bp0[0], w1 = bp1[0];
        __syncthreads();
        *(uint4*)&As32[ar * 20 + ah * 8]     = a0;
        *(uint4*)&As32[ar * 20 + ah * 8 + 4] = a1;
        {
            uint4 o03, o47;
            o03.x = __byte_perm(w0.x, w1.x, 0x5410);
            o03.y = __byte_perm(w0.x, w1.x, 0x7632);
            o03.z = __byte_perm(w0.y, w1.y, 0x5410);
            o03.w = __byte_perm(w0.y, w1.y, 0x7632);
            o47.x = __byte_perm(w0.z, w1.z, 0x5410);
            o47.y = __byte_perm(w0.z, w1.z, 0x7632);
            o47.z = __byte_perm(w0.w, w1.w, 0x5410);
            o47.w = __byte_perm(w0.w, w1.w, 0x7632);
            *(uint4*)&Bs32[bk2 * 132 + bc8]     = o03;
            *(uint4*)&Bs32[bk2 * 132 + bc8 + 4] = o47;
        }
        __syncthreads();

#pragma unroll
        for (int kc = 0; kc < 2; kc++) {
            unsigned afr[2][4];
#pragma unroll
            for (int mt = 0; mt < 2; mt++) {
                int r0 = wm * 32 + mt * 16;
                afr[mt][0] = As32[(r0 + g) * 20 + kc * 8 + t4];
                afr[mt][1] = As32[(r0 + g + 8) * 20 + kc * 8 + t4];
                afr[mt][2] = As32[(r0 + g) * 20 + kc * 8 + t4 + 4];
                afr[mt][3] = As32[(r0 + g + 8) * 20 + kc * 8 + t4 + 4];
            }
#pragma unroll
            for (int nt = 0; nt < 8; nt++) {
                int c0 = wn * 64 + nt * 8 + g;
                unsigned bb0 = Bs32[(kc * 8 + t4) * 132 + c0];
                unsigned bb1 = Bs32[(kc * 8 + t4 + 4) * 132 + c0];
                mma16(acc[0][nt], afr[0], bb0, bb1);
                mma16(acc[1][nt], afr[1], bb0, bb1);
            }
        }
    }

    if (MODE == 0) {
        __half* Cz = Cb + (size_t)blockIdx.z * M * N;
#pragma unroll
        for (int mt = 0; mt < 2; mt++) {
#pragma unroll
            for (int nt = 0; nt < 8; nt++) {
                int col = bx + wn * 64 + nt * 8 + 2 * t4;
                size_t r0 = (size_t)(by + wm * 32 + mt * 16 + g);
                *(unsigned*)(Cz + r0 * N + col)       = packh(acc[mt][nt][0], acc[mt][nt][1]);
                *(unsigned*)(Cz + (r0 + 8) * N + col) = packh(acc[mt][nt][2], acc[mt][nt][3]);
            }
        }
    } else {
#pragma unroll
        for (int mt = 0; mt < 2; mt++) {
#pragma unroll
            for (int nt = 0; nt < 8; nt++) {
                int col = bx + wn * 64 + nt * 8 + 2 * t4;
                size_t r0 = (size_t)(by + wm * 32 + mt * 16 + g);
                size_t r1 = r0 + 8;
                float2 v01 = {acc[mt][nt][0], acc[mt][nt][1]};
                float2 v23 = {acc[mt][nt][2], acc[mt][nt][3]};
                float2 q0 = *(const float2*)(Res + r0 * N + col);
                float2 q1 = *(const float2*)(Res + r1 * N + col);
                v01.x += q0.x; v01.y += q0.y;
                v23.x += q1.x; v23.y += q1.y;
                *(float2*)(Cf + r0 * N + col) = v01;
                *(float2*)(Cf + r1 * N + col) = v23;
                *(float2*)(C2f + r0 * N + col) = v01;
                *(float2*)(C2f + r1 * N + col) = v23;
            }
        }
    }
}

// ---------------- fp16 flash attention, register-resident P ---------------------
// grid (S/64, B*H), 128 threads (4 warps). Warp owns 16 query rows.
__global__ __launch_bounds__(128) void attn_h_kernel(const __half* __restrict__ Q,
                                                     const __half* __restrict__ Kb,
                                                     const __half* __restrict__ Vb,
                                                     __half* __restrict__ O) {
    __shared__ unsigned Ks32[64 * 36];   // [key][d2], stride 36 (also Q staging)
    __shared__ unsigned Vs32[32 * 68];   // [tokenpair][d], stride 68

    int bh = blockIdx.y;
    int b = bh >> 4, h = bh & 15;
    int q0 = blockIdx.x * 64;
    int tid = threadIdx.x, warp = tid >> 5, lane = tid & 31;
    int g = lane >> 2, t4 = lane & 3;

    // ---- stage Q tile, read fragments into registers ----
#pragma unroll
    for (int i = 0; i < 4; i++) {
        int idx = tid + i * 128;
        int row = idx >> 3, uq = idx & 7;
        *(uint4*)&Ks32[row * 36 + uq * 4] =
            *(const uint4*)(Q + (size_t)(b * S_ + q0 + row) * D_ + h * 64 + uq * 8);
    }
    __syncthreads();
    unsigned qf[4][4];
    {
        int r0 = warp * 16;
#pragma unroll
        for (int kc = 0; kc < 4; kc++) {
            qf[kc][0] = Ks32[(r0 + g) * 36 + kc * 8 + t4];
            qf[kc][1] = Ks32[(r0 + g + 8) * 36 + kc * 8 + t4];
            qf[kc][2] = Ks32[(r0 + g) * 36 + kc * 8 + t4 + 4];
            qf[kc][3] = Ks32[(r0 + g + 8) * 36 + kc * 8 + t4 + 4];
        }
    }

    float oacc[8][4];
#pragma unroll
    for (int i = 0; i < 8; i++)
#pragma unroll
        for (int j = 0; j < 4; j++) oacc[i][j] = 0.f;
    float m0 = -1e30f, m1 = -1e30f, l0 = 0.f, l1 = 0.f;

    for (int kt = 0; kt < S_; kt += 64) {
        __syncthreads();
        // load K tile (direct copy) + V tile (token-pair interleave)
#pragma unroll
        for (int i = 0; i < 4; i++) {
            int idx = tid + i * 128;
            int row = idx >> 3, uq = idx & 7;
            *(uint4*)&Ks32[row * 36 + uq * 4] =
                *(const uint4*)(Kb + (size_t)(b * S_ + kt + row) * D_ + h * 64 + uq * 8);
        }
#pragma unroll
        for (int i = 0; i < 2; i++) {
            int task = tid + i * 128;
            int tp = task >> 3, uq = task & 7;
            size_t base = (size_t)(b * S_ + kt + 2 * tp) * D_ + h * 64 + uq * 8;
            uint4 w0 = *(const uint4*)(Vb + base);
            uint4 w1 = *(const uint4*)(Vb + base + D_);
            uint4 o03, o47;
            o03.x = __byte_perm(w0.x, w1.x, 0x5410);
            o03.y = __byte_perm(w0.x, w1.x, 0x7632);
            o03.z = __byte_perm(w0.y, w1.y, 0x5410);
            o03.w = __byte_perm(w0.y, w1.y, 0x7632);
            o47.x = __byte_perm(w0.z, w1.z, 0x5410);
            o47.y = __byte_perm(w0.z, w1.z, 0x7632);
            o47.z = __byte_perm(w0.w, w1.w, 0x5410);
            o47.w = __byte_perm(w0.w, w1.w, 0x7632);
            *(uint4*)&Vs32[tp * 68 + uq * 8]     = o03;
            *(uint4*)&Vs32[tp * 68 + uq * 8 + 4] = o47;
        }
        __syncthreads();

        // ---- S = Q @ K^T ----
        float sacc[8][4];
#pragma unroll
        for (int i = 0; i < 8; i++)
#pragma unroll
            for (int j = 0; j < 4; j++) sacc[i][j] = 0.f;
#pragma unroll
        for (int nt = 0; nt < 8; nt++) {
            int kr = (nt * 8 + g) * 36;
#pragma unroll
            for (int kc = 0; kc < 4; kc++) {
                unsigned bb0 = Ks32[kr + kc * 8 + t4];
                unsigned bb1 = Ks32[kr + kc * 8 + t4 + 4];
                mma16(sacc[nt], qf[kc], bb0, bb1);
            }
        }
#pragma unroll
        for (int nt = 0; nt < 8; nt++)
#pragma unroll
            for (int j = 0; j < 4; j++) sacc[nt][j] *= 0.125f;

        // ---- online softmax (register layout) ----
        float mx0 = -1e30f, mx1 = -1e30f;
#pragma unroll
        for (int nt = 0; nt < 8; nt++) {
            mx0 = fmaxf(mx0, fmaxf(sacc[nt][0], sacc[nt][1]));
            mx1 = fmaxf(mx1, fmaxf(sacc[nt][2], sacc[nt][3]));
        }
        mx0 = fmaxf(mx0, __shfl_xor_sync(0xffffffffu, mx0, 1));
        mx0 = fmaxf(mx0, __shfl_xor_sync(0xffffffffu, mx0, 2));
        mx1 = fmaxf(mx1, __shfl_xor_sync(0xffffffffu, mx1, 1));
        mx1 = fmaxf(mx1, __shfl_xor_sync(0xffffffffu, mx1, 2));
        float mn0 = fmaxf(m0, mx0), mn1 = fmaxf(m1, mx1);
        float al0 = __expf(m0 - mn0), al1 = __expf(m1 - mn1);
        float rs0 = 0.f, rs1 = 0.f;
#pragma unroll
        for (int nt = 0; nt < 8; nt++) {
            sacc[nt][0] = __expf(sacc[nt][0] - mn0);
            sacc[nt][1] = __expf(sacc[nt][1] - mn0);
            sacc[nt][2] = __expf(sacc[nt][2] - mn1);
            sacc[nt][3] = __expf(sacc[nt][3] - mn1);
            rs0 += sacc[nt][0] + sacc[nt][1];
            rs1 += sacc[nt][2] + sacc[nt][3];
        }
        rs0 += __shfl_xor_sync(0xffffffffu, rs0, 1);
        rs0 += __shfl_xor_sync(0xffffffffu, rs0, 2);
        rs1 += __shfl_xor_sync(0xffffffffu, rs1, 1);
        rs1 += __shfl_xor_sync(0xffffffffu, rs1, 2);
        l0 = l0 * al0 + rs0;
        l1 = l1 * al1 + rs1;
        m0 = mn0; m1 = mn1;
#pragma unroll
        for (int dt = 0; dt < 8; dt++) {
            oacc[dt][0] *= al0; oacc[dt][1] *= al0;
            oacc[dt][2] *= al1; oacc[dt][3] *= al1;
        }

        // ---- O += P @ V (P packed from sacc, stays in regs) ----
#pragma unroll
        for (int kc = 0; kc < 4; kc++) {
            unsigned pf[4];
            pf[0] = packh(sacc[2 * kc][0],     sacc[2 * kc][1]);
            pf[1] = packh(sacc[2 * kc][2],     sacc[2 * kc][3]);
            pf[2] = packh(sacc[2 * kc + 1][0], sacc[2 * kc + 1][1]);
            pf[3] = packh(sacc[2 * kc + 1][2], sacc[2 * kc + 1][3]);
#pragma unroll
            for (int dt = 0; dt < 8; dt++) {
                unsigned bb0 = Vs32[(kc * 8 + t4) * 68 + dt * 8 + g];
                unsigned bb1 = Vs32[(kc * 8 + t4 + 4) * 68 + dt * 8 + g];
                mma16(oacc[dt], pf, bb0, bb1);
            }
        }
    }

    // ---- epilogue ----
    float il0 = 1.0f / l0, il1 = 1.0f / l1;
    int row = q0 + warp * 16 + g;
#pragma unroll
    for (int dt = 0; dt < 8; dt++) {
        int col = h * 64 + dt * 8 + 2 * t4;
        *(unsigned*)(O + (size_t)(b * S_ + row) * D_ + col) =
            packh(oacc[dt][0] * il0, oacc[dt][1] * il0);
        *(unsigned*)(O + (size_t)(b * S_ + row + 8) * D_ + col) =
            packh(oacc[dt][2] * il1, oacc[dt][3] * il1);
    }
}

// ---------------- Selector ----------------
__global__ __launch_bounds__(128) void selector_kernel(const float* __restrict__ h,
                                                       const float* __restrict__ Wsel) {
    int t = blockIdx.x * 4 + (threadIdx.x >> 5);
    int lane = threadIdx.x & 31;
    float acc[16];
#pragma unroll
    for (int e = 0; e < 16; e++) acc[e] = 0.f;
    const float* hr = h + (size_t)t * D_;
    for (int d = lane; d < D_; d += 32) {
        float hv = hr[d];
        const float4* w = (const float4*)(Wsel + (size_t)d * E_);
        float4 w0 = w[0], w1 = w[1], w2 = w[2], w3 = w[3];
        acc[0]  = fmaf(hv, w0.x, acc[0]);  acc[1]  = fmaf(hv, w0.y, acc[1]);
        acc[2]  = fmaf(hv, w0.z, acc[2]);  acc[3]  = fmaf(hv, w0.w, acc[3]);
        acc[4]  = fmaf(hv, w1.x, acc[4]);  acc[5]  = fmaf(hv, w1.y, acc[5]);
        acc[6]  = fmaf(hv, w1.z, acc[6]);  acc[7]  = fmaf(hv, w1.w, acc[7]);
        acc[8]  = fmaf(hv, w2.x, acc[8]);  acc[9]  = fmaf(hv, w2.y, acc[9]);
        acc[10] = fmaf(hv, w2.z, acc[10]); acc[11] = fmaf(hv, w2.w, acc[11]);
        acc[12] = fmaf(hv, w3.x, acc[12]); acc[13] = fmaf(hv, w3.y, acc[13]);
        acc[14] = fmaf(hv, w3.z, acc[14]); acc[15] = fmaf(hv, w3.w, acc[15]);
    }
#pragma unroll
    for (int e = 0; e < 16; e++)
#pragma unroll
        for (int o = 16; o; o >>= 1) acc[e] += __shfl_xor_sync(0xffffffffu, acc[e], o);
    if (lane == 0) {
        float v1 = -1.f, v2 = -1.f;
        int i1 = 0, i2 = 0;
#pragma unroll
        for (int e = 0; e < 16; e++) {
            float sg = 1.0f / (1.0f + __expf(-acc[e]));
            if (sg > v1) { v2 = v1; i2 = i1; v1 = sg; i1 = e; }
            else if (sg > v2) { v2 = sg; i2 = e; }
        }
        int p1 = atomicAdd(&g_cnt[i1], 1);
        g_elist[i1 * T_ + p1] = t;
        g_egate[i1 * T_ + p1] = v1;
        int p2 = atomicAdd(&g_cnt[i2], 1);
        g_elist[i2 * T_ + p2] = t;
        g_egate[i2 * T_ + p2] = v2;
    }
}

// ---------------- MoE up ----------------
__global__ __launch_bounds__(256) void moe_up_kernel(const float* __restrict__ h,
                                                     const float* __restrict__ W1) {
    int e = blockIdx.z;
    int n = g_cnt[e];
    int rb = blockIdx.y * 64;
    if (rb >= n) return;
    int bn = blockIdx.x * 64;

    __shared__ float As[16][64];
    __shared__ float Bs[16][64];
    __shared__ int rows[64];

    int tid = threadIdx.x, tx = tid & 15, ty = tid >> 4;
    if (tid < 64) {
        int rg = rb + tid;
        rows[tid] = (rg < n) ? g_elist[e * T_ + rg] : 0;
    }
    __syncthreads();

    float acc[4][4];
#pragma unroll
    for (int i = 0; i < 4; i++)
#pragma unroll
        for (int j = 0; j < 4; j++) acc[i][j] = 0.f;

    int lr = tid >> 2, lk = (tid & 3) * 4;
    int brow = tid >> 4, bcol = (tid & 15) * 4;
    const float* Wb = W1 + (size_t)e * D_ * F_ + bn;
    const float* Arow = h + (size_t)rows[lr] * D_ + lk;

    for (int k0 = 0; k0 < D_; k0 += 16) {
        float4 a4 = *(const float4*)(Arow + k0);
        float4 b4 = *(const float4*)(Wb + (size_t)(k0 + brow) * F_ + bcol);
        As[lk + 0][lr] = a4.x; As[lk + 1][lr] = a4.y;
        As[lk + 2][lr] = a4.z; As[lk + 3][lr] = a4.w;
        *(float4*)&Bs[brow][bcol] = b4;
        __syncthreads();
#pragma unroll
        for (int k = 0; k < 16; k++) {
            float4 a = *(const float4*)&As[k][ty * 4];
            float4 b = *(const float4*)&Bs[k][tx * 4];
            float ar[4] = {a.x, a.y, a.z, a.w};
            float br[4] = {b.x, b.y, b.z, b.w};
#pragma unroll
            for (int i = 0; i < 4; i++)
#pragma unroll
                for (int j = 0; j < 4; j++) acc[i][j] = fmaf(ar[i], br[j], acc[i][j]);
        }
        __syncthreads();
    }

#pragma unroll
    for (int i = 0; i < 4; i++) {
        int rg = rb + ty * 4 + i;
        if (rg < n) {
            float gte = g_egate[e * T_ + rg];
            float* op = g_up + ((size_t)e * T_ + rg) * F_ + bn + tx * 4;
#pragma unroll
            for (int j = 0; j < 4; j++) op[j] = fmaxf(acc[i][j], 0.f) * gte;
        }
    }
}

// ---------------- MoE down ----------------
__global__ __launch_bounds__(256) void moe_down_kernel(const float* __restrict__ W2,
                                                       float* __restrict__ out) {
    int e = blockIdx.z;
    int n = g_cnt[e];
    int rb = blockIdx.y * 64;
    if (rb >= n) return;
    int bn = blockIdx.x * 64;

    __shared__ float As[16][64];
    __shared__ float Bs[16][64];

    int tid = threadIdx.x, tx = tid & 15, ty = tid >> 4;

    float acc[4][4];
#pragma unroll
    for (int i = 0; i < 4; i++)
#pragma unroll
        for (int j = 0; j < 4; j++) acc[i][j] = 0.f;

    int lr = tid >> 2, lk = (tid & 3) * 4;
    int brow = tid >> 4, bcol = (tid & 15) * 4;
    const float* Wb = W2 + (size_t)e * F_ * D_ + bn;
    const float* Arow = g_up + ((size_t)e * T_ + rb + lr) * F_ + lk;

    for (int k0 = 0; k0 < F_; k0 += 16) {
        float4 a4 = *(const float4*)(Arow + k0);
        float4 b4 = *(const float4*)(Wb + (size_t)(k0 + brow) * D_ + bcol);
        As[lk + 0][lr] = a4.x; As[lk + 1][lr] = a4.y;
        As[lk + 2][lr] = a4.z; As[lk + 3][lr] = a4.w;
        *(float4*)&Bs[brow][bcol] = b4;
        __syncthreads();
#pragma unroll
        for (int k = 0; k < 16; k++) {
            float4 a = *(const float4*)&As[k][ty * 4];
            float4 b = *(const float4*)&Bs[k][tx * 4];
            float ar[4] = {a.x, a.y, a.z, a.w};
            float br[4] = {b.x, b.y, b.z, b.w};
#pragma unroll
            for (int i = 0; i < 4; i++)
#pragma unroll
                for (int j = 0; j < 4; j++) acc[i][j] = fmaf(ar[i], br[j], acc[i][j]);
        }
        __syncthreads();
    }

#pragma unroll
    for (int i = 0; i < 4; i++) {
        int rg = rb + ty * 4 + i;
        if (rg < n) {
            int t = g_elist[e * T_ + rg];
            float* op = out + (size_t)t * D_ + bn + tx * 4;
#pragma unroll
            for (int j = 0; j < 4; j++) atomicAdd(&op[j], acc[i][j]);
        }
    }
}

// ---------------- launch ----------------
extern "C" void kernel_launch(void* const* d_in, const int* in_sizes, int n_in,
                              void* d_out, int out_size) {
    (void)in_sizes; (void)n_in; (void)out_size;
    const float* x    = (const float*)d_in[0];
    const float* Wq   = (const float*)d_in[1];
    const float* Wk   = (const float*)d_in[2];
    const float* Wv   = (const float*)d_in[3];
    const float* Wo   = (const float*)d_in[4];
    const float* ln1s = (const float*)d_in[5];
    const float* ln1b = (const float*)d_in[6];
    const float* ln2s = (const float*)d_in[7];
    const float* ln2b = (const float*)d_in[8];
    const float* Wsel = (const float*)d_in[9];
    const float* W1   = (const float*)d_in[10];
    const float* W2   = (const float*)d_in[11];
    float* out = (float*)d_out;

    __half *wqkvh, *woh, *h1h, *qkvh, *ctxh;
    float *x2p, *h2p;
    cudaGetSymbolAddress((void**)&wqkvh, g_wqkvh);
    cudaGetSymbolAddress((void**)&woh,   g_woh);
    cudaGetSymbolAddress((void**)&h1h,   g_h1h);
    cudaGetSymbolAddress((void**)&qkvh,  g_qkvh);
    cudaGetSymbolAddress((void**)&ctxh,  g_ctxh);
    cudaGetSymbolAddress((void**)&x2p,   g_x2);
    cudaGetSymbolAddress((void**)&h2p,   g_h2);

    const int DD4 = D_ * D_ / 4;
    conv_f2h<<<512, 256>>>((const float4*)Wq, (uint2*)(wqkvh),               DD4);
    conv_f2h<<<512, 256>>>((const float4*)Wk, (uint2*)(wqkvh + D_ * D_),     DD4);
    conv_f2h<<<512, 256>>>((const float4*)Wv, (uint2*)(wqkvh + 2 * D_ * D_), DD4);
    conv_f2h<<<512, 256>>>((const float4*)Wo, (uint2*)(woh),                 DD4);

    zero_cnt_kernel<<<1, 32>>>();
    ln_h_kernel<<<T_, 256>>>(x, ln1s, ln1b, h1h);

    gemm_h<0><<<dim3(D_ / 128, T_ / 128, 3), 256>>>(
        h1h, wqkvh, nullptr, nullptr, nullptr, qkvh, T_, D_, D_);

    attn_h_kernel<<<dim3(S_ / 64, B_ * H_), 128>>>(
        qkvh, qkvh + (size_t)T_ * D_, qkvh + 2 * (size_t)T_ * D_, ctxh);

    gemm_h<1><<<dim3(D_ / 128, T_ / 128, 1), 256>>>(
        ctxh, woh, x, x2p, out, nullptr, T_, D_, D_);

    ln_kernel<<<T_, 256>>>(x2p, ln2s, ln2b, h2p);
    selector_kernel<<<T_ / 4, 128>>>(h2p, Wsel);

    moe_up_kernel<<<dim3(F_ / 64, T_ / 64, E_), 256>>>(h2p, W1);
    moe_down_kernel<<<dim3(D_ / 64, T_ / 64, E_), 256>>>(W2, out);
}

// round 7
// speedup vs baseline: 6.6341x; 1.3960x over previous
#include <cuda_runtime.h>
#include <cuda_fp16.h>
#include <math.h>

#define B_  2
#define S_  2048
#define D_  1024
#define H_  16
#define DH_ 64
#define E_  16
#define F_  256
#define T_  (B_*S_)

// ---------------- scratch ----------------
__device__ __half g_wqkvh[(size_t)3*D_*D_];
__device__ __half g_woh[(size_t)D_*D_];
__device__ __half g_w1h[(size_t)E_*D_*F_];
__device__ __half g_w2h[(size_t)E_*F_*D_];
__device__ __half g_h1h[(size_t)T_*D_];
__device__ __half g_qkvh[(size_t)3*T_*D_];
__device__ __half g_ctxh[(size_t)T_*D_];
__device__ __half g_h2h[(size_t)T_*D_];
__device__ __half g_uph[(size_t)E_*T_*F_];
__device__ float g_x2[(size_t)T_*D_];
__device__ float g_h2[(size_t)T_*D_];
__device__ int   g_cnt[E_];
__device__ int   g_elist[E_*T_];
__device__ float g_egate[E_*T_];

__global__ void zero_cnt_kernel() {
    if (threadIdx.x < E_) g_cnt[threadIdx.x] = 0;
}

// ---------------- helpers ----------------
__device__ __forceinline__ unsigned packh(float lo, float hi) {
    unsigned u;
    asm("cvt.rn.f16x2.f32 %0, %1, %2;" : "=r"(u) : "f"(hi), "f"(lo));
    return u;
}

__device__ __forceinline__ void mma16(float* d, const unsigned* a, unsigned b0, unsigned b1) {
    asm volatile(
        "mma.sync.aligned.m16n8k16.row.col.f32.f16.f16.f32 "
        "{%0,%1,%2,%3},{%4,%5,%6,%7},{%8,%9},{%0,%1,%2,%3};"
        : "+f"(d[0]), "+f"(d[1]), "+f"(d[2]), "+f"(d[3])
        : "r"(a[0]), "r"(a[1]), "r"(a[2]), "r"(a[3]), "r"(b0), "r"(b1));
}

// ---------------- fp32 -> fp16 convert ----------------
__global__ __launch_bounds__(256) void conv_f2h(const float4* __restrict__ s,
                                                uint2* __restrict__ d, int n4) {
    int i = blockIdx.x * blockDim.x + threadIdx.x;
    int stride = gridDim.x * blockDim.x;
    for (; i < n4; i += stride) {
        float4 v = s[i];
        uint2 o;
        o.x = packh(v.x, v.y);
        o.y = packh(v.z, v.w);
        d[i] = o;
    }
}

// ---------------- LayerNorm (fp16 out) ----------------
__global__ __launch_bounds__(256) void ln_h_kernel(const float* __restrict__ x,
                                                   const float* __restrict__ sc,
                                                   const float* __restrict__ bi,
                                                   __half* __restrict__ o) {
    int t = blockIdx.x;
    const float* xr = x + (size_t)t * D_;
    __half* orow = o + (size_t)t * D_;
    float v[4];
    float s = 0.f, s2 = 0.f;
#pragma unroll
    for (int i = 0; i < 4; i++) {
        v[i] = xr[threadIdx.x + i * 256];
        s  += v[i];
        s2 += v[i] * v[i];
    }
#pragma unroll
    for (int off = 16; off; off >>= 1) {
        s  += __shfl_xor_sync(0xffffffffu, s,  off);
        s2 += __shfl_xor_sync(0xffffffffu, s2, off);
    }
    __shared__ float ws[8], ws2[8];
    int w = threadIdx.x >> 5, ln = threadIdx.x & 31;
    if (ln == 0) { ws[w] = s; ws2[w] = s2; }
    __syncthreads();
    float S = 0.f, S2 = 0.f;
#pragma unroll
    for (int i = 0; i < 8; i++) { S += ws[i]; S2 += ws2[i]; }
    float mu  = S * (1.0f / D_);
    float var = S2 * (1.0f / D_) - mu * mu;
    float inv = rsqrtf(var + 1e-5f);
#pragma unroll
    for (int i = 0; i < 4; i++) {
        int d = threadIdx.x + i * 256;
        orow[d] = __float2half((v[i] - mu) * inv * sc[d] + bi[d]);
    }
}

// ---------------- LayerNorm dual output (fp32 + fp16) ----------------
__global__ __launch_bounds__(256) void ln_dual_kernel(const float* __restrict__ x,
                                                      const float* __restrict__ sc,
                                                      const float* __restrict__ bi,
                                                      float* __restrict__ of,
                                                      __half* __restrict__ oh) {
    int t = blockIdx.x;
    const float* xr = x + (size_t)t * D_;
    float v[4];
    float s = 0.f, s2 = 0.f;
#pragma unroll
    for (int i = 0; i < 4; i++) {
        v[i] = xr[threadIdx.x + i * 256];
        s  += v[i];
        s2 += v[i] * v[i];
    }
#pragma unroll
    for (int off = 16; off; off >>= 1) {
        s  += __shfl_xor_sync(0xffffffffu, s,  off);
        s2 += __shfl_xor_sync(0xffffffffu, s2, off);
    }
    __shared__ float ws[8], ws2[8];
    int w = threadIdx.x >> 5, ln = threadIdx.x & 31;
    if (ln == 0) { ws[w] = s; ws2[w] = s2; }
    __syncthreads();
    float S = 0.f, S2 = 0.f;
#pragma unroll
    for (int i = 0; i < 8; i++) { S += ws[i]; S2 += ws2[i]; }
    float mu  = S * (1.0f / D_);
    float var = S2 * (1.0f / D_) - mu * mu;
    float inv = rsqrtf(var + 1e-5f);
#pragma unroll
    for (int i = 0; i < 4; i++) {
        int d = threadIdx.x + i * 256;
        float r = (v[i] - mu) * inv * sc[d] + bi[d];
        of[(size_t)t * D_ + d] = r;
        oh[(size_t)t * D_ + d] = __float2half(r);
    }
}

// ---------------- fp16 tensor-core GEMM: 128x128 block, BK=32 -------------------
template <int MODE>
__global__ __launch_bounds__(256) void gemm_h(const __half* __restrict__ A,
                                              const __half* __restrict__ Bw,
                                              const float* __restrict__ Res,
                                              float* __restrict__ Cf,
                                              float* __restrict__ C2f,
                                              __half* __restrict__ Cb,
                                              int M, int N, int K) {
    __shared__ unsigned As32[128 * 20];
    __shared__ unsigned Bs32[16 * 132];

    const __half* Bz = Bw + (size_t)blockIdx.z * K * N;
    int tid = threadIdx.x, warp = tid >> 5, lane = tid & 31;
    int g = lane >> 2, t4 = lane & 3;
    int wm = warp >> 1, wn = warp & 1;
    int bx = blockIdx.x * 128, by = blockIdx.y * 128;

    float acc[2][8][4];
#pragma unroll
    for (int i = 0; i < 2; i++)
#pragma unroll
        for (int j = 0; j < 8; j++)
#pragma unroll
            for (int q = 0; q < 4; q++) acc[i][j][q] = 0.f;

    int ar = tid >> 1, ah = tid & 1;
    int bk2 = tid >> 4, bc8 = (tid & 15) * 8;

    for (int k0 = 0; k0 < K; k0 += 32) {
        const uint4* ap = (const uint4*)(A + (size_t)(by + ar) * K + k0 + ah * 16);
        uint4 a0 = ap[0], a1 = ap[1];
        const uint4* bp0 = (const uint4*)(Bz + (size_t)(k0 + 2 * bk2) * N + bx + bc8);
        const uint4* bp1 = (const uint4*)(Bz + (size_t)(k0 + 2 * bk2 + 1) * N + bx + bc8);
        uint4 w0 = bp0[0], w1 = bp1[0];
        __syncthreads();
        *(uint4*)&As32[ar * 20 + ah * 8]     = a0;
        *(uint4*)&As32[ar * 20 + ah * 8 + 4] = a1;
        {
            uint4 o03, o47;
            o03.x = __byte_perm(w0.x, w1.x, 0x5410);
            o03.y = __byte_perm(w0.x, w1.x, 0x7632);
            o03.z = __byte_perm(w0.y, w1.y, 0x5410);
            o03.w = __byte_perm(w0.y, w1.y, 0x7632);
            o47.x = __byte_perm(w0.z, w1.z, 0x5410);
            o47.y = __byte_perm(w0.z, w1.z, 0x7632);
            o47.z = __byte_perm(w0.w, w1.w, 0x5410);
            o47.w = __byte_perm(w0.w, w1.w, 0x7632);
            *(uint4*)&Bs32[bk2 * 132 + bc8]     = o03;
            *(uint4*)&Bs32[bk2 * 132 + bc8 + 4] = o47;
        }
        __syncthreads();

#pragma unroll
        for (int kc = 0; kc < 2; kc++) {
            unsigned afr[2][4];
#pragma unroll
            for (int mt = 0; mt < 2; mt++) {
                int r0 = wm * 32 + mt * 16;
                afr[mt][0] = As32[(r0 + g) * 20 + kc * 8 + t4];
                afr[mt][1] = As32[(r0 + g + 8) * 20 + kc * 8 + t4];
                afr[mt][2] = As32[(r0 + g) * 20 + kc * 8 + t4 + 4];
                afr[mt][3] = As32[(r0 + g + 8) * 20 + kc * 8 + t4 + 4];
            }
#pragma unroll
            for (int nt = 0; nt < 8; nt++) {
                int c0 = wn * 64 + nt * 8 + g;
                unsigned bb0 = Bs32[(kc * 8 + t4) * 132 + c0];
                unsigned bb1 = Bs32[(kc * 8 + t4 + 4) * 132 + c0];
                mma16(acc[0][nt], afr[0], bb0, bb1);
                mma16(acc[1][nt], afr[1], bb0, bb1);
            }
        }
    }

    if (MODE == 0) {
        __half* Cz = Cb + (size_t)blockIdx.z * M * N;
#pragma unroll
        for (int mt = 0; mt < 2; mt++) {
#pragma unroll
            for (int nt = 0; nt < 8; nt++) {
                int col = bx + wn * 64 + nt * 8 + 2 * t4;
                size_t r0 = (size_t)(by + wm * 32 + mt * 16 + g);
                *(unsigned*)(Cz + r0 * N + col)       = packh(acc[mt][nt][0], acc[mt][nt][1]);
                *(unsigned*)(Cz + (r0 + 8) * N + col) = packh(acc[mt][nt][2], acc[mt][nt][3]);
            }
        }
    } else {
#pragma unroll
        for (int mt = 0; mt < 2; mt++) {
#pragma unroll
            for (int nt = 0; nt < 8; nt++) {
                int col = bx + wn * 64 + nt * 8 + 2 * t4;
                size_t r0 = (size_t)(by + wm * 32 + mt * 16 + g);
                size_t r1 = r0 + 8;
                float2 v01 = {acc[mt][nt][0], acc[mt][nt][1]};
                float2 v23 = {acc[mt][nt][2], acc[mt][nt][3]};
                float2 q0 = *(const float2*)(Res + r0 * N + col);
                float2 q1 = *(const float2*)(Res + r1 * N + col);
                v01.x += q0.x; v01.y += q0.y;
                v23.x += q1.x; v23.y += q1.y;
                *(float2*)(Cf + r0 * N + col) = v01;
                *(float2*)(Cf + r1 * N + col) = v23;
                *(float2*)(C2f + r0 * N + col) = v01;
                *(float2*)(C2f + r1 * N + col) = v23;
            }
        }
    }
}

// ---------------- MoE fp16 tensor-core GEMM -------------------------------------
// MODE 0 (up):   A = gathered h2h rows via elist, W = W1[e] [D][F], out relu*gate
//                -> fp16 g_uph at list position.   grid (F/128, T/128, E)
// MODE 1 (down): A = g_uph dense (list order), W = W2[e] [F][D],
//                atomicAdd scatter to out by token. grid (D/128, T/128, E)
template <int MODE>
__global__ __launch_bounds__(256) void moe_mma(const __half* __restrict__ Ab,
                                               const __half* __restrict__ Wb,
                                               __half* __restrict__ Uph,
                                               float* __restrict__ out) {
    int e = blockIdx.z;
    int n = g_cnt[e];
    int rb = blockIdx.y * 128;
    if (rb >= n) return;
    const int N = (MODE == 0) ? F_ : D_;
    const int K = (MODE == 0) ? D_ : F_;
    const __half* Wz = Wb + (size_t)e * K * N;

    __shared__ unsigned As32[128 * 20];
    __shared__ unsigned Bs32[16 * 132];
    __shared__ int rows[128];

    int tid = threadIdx.x, warp = tid >> 5, lane = tid & 31;
    int g = lane >> 2, t4 = lane & 3;
    int wm = warp >> 1, wn = warp & 1;
    int bx = blockIdx.x * 128;

    if (MODE == 0) {
        if (tid < 128) {
            int rg = rb + tid;
            rows[tid] = (rg < n) ? g_elist[e * T_ + rg] : 0;
        }
        __syncthreads();
    }

    float acc[2][8][4];
#pragma unroll
    for (int i = 0; i < 2; i++)
#pragma unroll
        for (int j = 0; j < 8; j++)
#pragma unroll
            for (int q = 0; q < 4; q++) acc[i][j][q] = 0.f;

    int ar = tid >> 1, ah = tid & 1;
    int bk2 = tid >> 4, bc8 = (tid & 15) * 8;

    const __half* Abase;
    if (MODE == 0)
        Abase = Ab + (size_t)rows[ar] * D_ + ah * 16;
    else
        Abase = Ab + ((size_t)e * T_ + rb + ar) * F_ + ah * 16;

    for (int k0 = 0; k0 < K; k0 += 32) {
        const uint4* ap = (const uint4*)(Abase + k0);
        uint4 a0 = ap[0], a1 = ap[1];
        const uint4* bp0 = (const uint4*)(Wz + (size_t)(k0 + 2 * bk2) * N + bx + bc8);
        const uint4* bp1 = (const uint4*)(Wz + (size_t)(k0 + 2 * bk2 + 1) * N + bx + bc8);
        uint4 w0 = bp0[0], w1 = bp1[0];
        __syncthreads();
        *(uint4*)&As32[ar * 20 + ah * 8]     = a0;
        *(uint4*)&As32[ar * 20 + ah * 8 + 4] = a1;
        {
            uint4 o03, o47;
            o03.x = __byte_perm(w0.x, w1.x, 0x5410);
            o03.y = __byte_perm(w0.x, w1.x, 0x7632);
            o03.z = __byte_perm(w0.y, w1.y, 0x5410);
            o03.w = __byte_perm(w0.y, w1.y, 0x7632);
            o47.x = __byte_perm(w0.z, w1.z, 0x5410);
            o47.y = __byte_perm(w0.z, w1.z, 0x7632);
            o47.z = __byte_perm(w0.w, w1.w, 0x5410);
            o47.w = __byte_perm(w0.w, w1.w, 0x7632);
            *(uint4*)&Bs32[bk2 * 132 + bc8]     = o03;
            *(uint4*)&Bs32[bk2 * 132 + bc8 + 4] = o47;
        }
        __syncthreads();

#pragma unroll
        for (int kc = 0; kc < 2; kc++) {
            unsigned afr[2][4];
#pragma unroll
            for (int mt = 0; mt < 2; mt++) {
                int r0 = wm * 32 + mt * 16;
                afr[mt][0] = As32[(r0 + g) * 20 + kc * 8 + t4];
                afr[mt][1] = As32[(r0 + g + 8) * 20 + kc * 8 + t4];
                afr[mt][2] = As32[(r0 + g) * 20 + kc * 8 + t4 + 4];
                afr[mt][3] = As32[(r0 + g + 8) * 20 + kc * 8 + t4 + 4];
            }
#pragma unroll
            for (int nt = 0; nt < 8; nt++) {
                int c0 = wn * 64 + nt * 8 + g;
                unsigned bb0 = Bs32[(kc * 8 + t4) * 132 + c0];
                unsigned bb1 = Bs32[(kc * 8 + t4 + 4) * 132 + c0];
                mma16(acc[0][nt], afr[0], bb0, bb1);
                mma16(acc[1][nt], afr[1], bb0, bb1);
            }
        }
    }

    if (MODE == 0) {
#pragma unroll
        for (int mt = 0; mt < 2; mt++) {
            int rg0 = rb + wm * 32 + mt * 16 + g;
            int rg1 = rg0 + 8;
            float gt0 = (rg0 < n) ? g_egate[e * T_ + rg0] : 0.f;
            float gt1 = (rg1 < n) ? g_egate[e * T_ + rg1] : 0.f;
#pragma unroll
            for (int nt = 0; nt < 8; nt++) {
                int col = bx + wn * 64 + nt * 8 + 2 * t4;
                if (rg0 < n)
                    *(unsigned*)(Uph + ((size_t)e * T_ + rg0) * F_ + col) =
                        packh(fmaxf(acc[mt][nt][0], 0.f) * gt0,
                              fmaxf(acc[mt][nt][1], 0.f) * gt0);
                if (rg1 < n)
                    *(unsigned*)(Uph + ((size_t)e * T_ + rg1) * F_ + col) =
                        packh(fmaxf(acc[mt][nt][2], 0.f) * gt1,
                              fmaxf(acc[mt][nt][3], 0.f) * gt1);
            }
        }
    } else {
#pragma unroll
        for (int mt = 0; mt < 2; mt++) {
            int rg0 = rb + wm * 32 + mt * 16 + g;
            int rg1 = rg0 + 8;
            int t0 = (rg0 < n) ? g_elist[e * T_ + rg0] : -1;
            int t1 = (rg1 < n) ? g_elist[e * T_ + rg1] : -1;
#pragma unroll
            for (int nt = 0; nt < 8; nt++) {
                int col = bx + wn * 64 + nt * 8 + 2 * t4;
                if (t0 >= 0) {
                    atomicAdd(out + (size_t)t0 * D_ + col,     acc[mt][nt][0]);
                    atomicAdd(out + (size_t)t0 * D_ + col + 1, acc[mt][nt][1]);
                }
                if (t1 >= 0) {
                    atomicAdd(out + (size_t)t1 * D_ + col,     acc[mt][nt][2]);
                    atomicAdd(out + (size_t)t1 * D_ + col + 1, acc[mt][nt][3]);
                }
            }
        }
    }
}

// ---------------- fp16 flash attention, register-resident P ---------------------
__global__ __launch_bounds__(128) void attn_h_kernel(const __half* __restrict__ Q,
                                                     const __half* __restrict__ Kb,
                                                     const __half* __restrict__ Vb,
                                                     __half* __restrict__ O) {
    __shared__ unsigned Ks32[64 * 36];
    __shared__ unsigned Vs32[32 * 68];

    int bh = blockIdx.y;
    int b = bh >> 4, h = bh & 15;
    int q0 = blockIdx.x * 64;
    int tid = threadIdx.x, warp = tid >> 5, lane = tid & 31;
    int g = lane >> 2, t4 = lane & 3;

#pragma unroll
    for (int i = 0; i < 4; i++) {
        int idx = tid + i * 128;
        int row = idx >> 3, uq = idx & 7;
        *(uint4*)&Ks32[row * 36 + uq * 4] =
            *(const uint4*)(Q + (size_t)(b * S_ + q0 + row) * D_ + h * 64 + uq * 8);
    }
    __syncthreads();
    unsigned qf[4][4];
    {
        int r0 = warp * 16;
#pragma unroll
        for (int kc = 0; kc < 4; kc++) {
            qf[kc][0] = Ks32[(r0 + g) * 36 + kc * 8 + t4];
            qf[kc][1] = Ks32[(r0 + g + 8) * 36 + kc * 8 + t4];
            qf[kc][2] = Ks32[(r0 + g) * 36 + kc * 8 + t4 + 4];
            qf[kc][3] = Ks32[(r0 + g + 8) * 36 + kc * 8 + t4 + 4];
        }
    }

    float oacc[8][4];
#pragma unroll
    for (int i = 0; i < 8; i++)
#pragma unroll
        for (int j = 0; j < 4; j++) oacc[i][j] = 0.f;
    float m0 = -1e30f, m1 = -1e30f, l0 = 0.f, l1 = 0.f;

    for (int kt = 0; kt < S_; kt += 64) {
        __syncthreads();
#pragma unroll
        for (int i = 0; i < 4; i++) {
            int idx = tid + i * 128;
            int row = idx >> 3, uq = idx & 7;
            *(uint4*)&Ks32[row * 36 + uq * 4] =
                *(const uint4*)(Kb + (size_t)(b * S_ + kt + row) * D_ + h * 64 + uq * 8);
        }
#pragma unroll
        for (int i = 0; i < 2; i++) {
            int task = tid + i * 128;
            int tp = task >> 3, uq = task & 7;
            size_t base = (size_t)(b * S_ + kt + 2 * tp) * D_ + h * 64 + uq * 8;
            uint4 w0 = *(const uint4*)(Vb + base);
            uint4 w1 = *(const uint4*)(Vb + base + D_);
            uint4 o03, o47;
            o03.x = __byte_perm(w0.x, w1.x, 0x5410);
            o03.y = __byte_perm(w0.x, w1.x, 0x7632);
            o03.z = __byte_perm(w0.y, w1.y, 0x5410);
            o03.w = __byte_perm(w0.y, w1.y, 0x7632);
            o47.x = __byte_perm(w0.z, w1.z, 0x5410);
            o47.y = __byte_perm(w0.z, w1.z, 0x7632);
            o47.z = __byte_perm(w0.w, w1.w, 0x5410);
            o47.w = __byte_perm(w0.w, w1.w, 0x7632);
            *(uint4*)&Vs32[tp * 68 + uq * 8]     = o03;
            *(uint4*)&Vs32[tp * 68 + uq * 8 + 4] = o47;
        }
        __syncthreads();

        float sacc[8][4];
#pragma unroll
        for (int i = 0; i < 8; i++)
#pragma unroll
            for (int j = 0; j < 4; j++) sacc[i][j] = 0.f;
#pragma unroll
        for (int nt = 0; nt < 8; nt++) {
            int kr = (nt * 8 + g) * 36;
#pragma unroll
            for (int kc = 0; kc < 4; kc++) {
                unsigned bb0 = Ks32[kr + kc * 8 + t4];
                unsigned bb1 = Ks32[kr + kc * 8 + t4 + 4];
                mma16(sacc[nt], qf[kc], bb0, bb1);
            }
        }
#pragma unroll
        for (int nt = 0; nt < 8; nt++)
#pragma unroll
            for (int j = 0; j < 4; j++) sacc[nt][j] *= 0.125f;

        float mx0 = -1e30f, mx1 = -1e30f;
#pragma unroll
        for (int nt = 0; nt < 8; nt++) {
            mx0 = fmaxf(mx0, fmaxf(sacc[nt][0], sacc[nt][1]));
            mx1 = fmaxf(mx1, fmaxf(sacc[nt][2], sacc[nt][3]));
        }
        mx0 = fmaxf(mx0, __shfl_xor_sync(0xffffffffu, mx0, 1));
        mx0 = fmaxf(mx0, __shfl_xor_sync(0xffffffffu, mx0, 2));
        mx1 = fmaxf(mx1, __shfl_xor_sync(0xffffffffu, mx1, 1));
        mx1 = fmaxf(mx1, __shfl_xor_sync(0xffffffffu, mx1, 2));
        float mn0 = fmaxf(m0, mx0), mn1 = fmaxf(m1, mx1);
        float al0 = __expf(m0 - mn0), al1 = __expf(m1 - mn1);
        float rs0 = 0.f, rs1 = 0.f;
#pragma unroll
        for (int nt = 0; nt < 8; nt++) {
            sacc[nt][0] = __expf(sacc[nt][0] - mn0);
            sacc[nt][1] = __expf(sacc[nt][1] - mn0);
            sacc[nt][2] = __expf(sacc[nt][2] - mn1);
            sacc[nt][3] = __expf(sacc[nt][3] - mn1);
            rs0 += sacc[nt][0] + sacc[nt][1];
            rs1 += sacc[nt][2] + sacc[nt][3];
        }
        rs0 += __shfl_xor_sync(0xffffffffu, rs0, 1);
        rs0 += __shfl_xor_sync(0xffffffffu, rs0, 2);
        rs1 += __shfl_xor_sync(0xffffffffu, rs1, 1);
        rs1 += __shfl_xor_sync(0xffffffffu, rs1, 2);
        l0 = l0 * al0 + rs0;
        l1 = l1 * al1 + rs1;
        m0 = mn0; m1 = mn1;
#pragma unroll
        for (int dt = 0; dt < 8; dt++) {
            oacc[dt][0] *= al0; oacc[dt][1] *= al0;
            oacc[dt][2] *= al1; oacc[dt][3] *= al1;
        }

#pragma unroll
        for (int kc = 0; kc < 4; kc++) {
            unsigned pf[4];
            pf[0] = packh(sacc[2 * kc][0],     sacc[2 * kc][1]);
            pf[1] = packh(sacc[2 * kc][2],     sacc[2 * kc][3]);
            pf[2] = packh(sacc[2 * kc + 1][0], sacc[2 * kc + 1][1]);
            pf[3] = packh(sacc[2 * kc + 1][2], sacc[2 * kc + 1][3]);
#pragma unroll
            for (int dt = 0; dt < 8; dt++) {
                unsigned bb0 = Vs32[(kc * 8 + t4) * 68 + dt * 8 + g];
                unsigned bb1 = Vs32[(kc * 8 + t4 + 4) * 68 + dt * 8 + g];
                mma16(oacc[dt], pf, bb0, bb1);
            }
        }
    }

    float il0 = 1.0f / l0, il1 = 1.0f / l1;
    int row = q0 + warp * 16 + g;
#pragma unroll
    for (int dt = 0; dt < 8; dt++) {
        int col = h * 64 + dt * 8 + 2 * t4;
        *(unsigned*)(O + (size_t)(b * S_ + row) * D_ + col) =
            packh(oacc[dt][0] * il0, oacc[dt][1] * il0);
        *(unsigned*)(O + (size_t)(b * S_ + row + 8) * D_ + col) =
            packh(oacc[dt][2] * il1, oacc[dt][3] * il1);
    }
}

// ---------------- Selector ----------------
__global__ __launch_bounds__(128) void selector_kernel(const float* __restrict__ h,
                                                       const float* __restrict__ Wsel) {
    int t = blockIdx.x * 4 + (threadIdx.x >> 5);
    int lane = threadIdx.x & 31;
    float acc[16];
#pragma unroll
    for (int e = 0; e < 16; e++) acc[e] = 0.f;
    const float* hr = h + (size_t)t * D_;
    for (int d = lane; d < D_; d += 32) {
        float hv = hr[d];
        const float4* w = (const float4*)(Wsel + (size_t)d * E_);
        float4 w0 = w[0], w1 = w[1], w2 = w[2], w3 = w[3];
        acc[0]  = fmaf(hv, w0.x, acc[0]);  acc[1]  = fmaf(hv, w0.y, acc[1]);
        acc[2]  = fmaf(hv, w0.z, acc[2]);  acc[3]  = fmaf(hv, w0.w, acc[3]);
        acc[4]  = fmaf(hv, w1.x, acc[4]);  acc[5]  = fmaf(hv, w1.y, acc[5]);
        acc[6]  = fmaf(hv, w1.z, acc[6]);  acc[7]  = fmaf(hv, w1.w, acc[7]);
        acc[8]  = fmaf(hv, w2.x, acc[8]);  acc[9]  = fmaf(hv, w2.y, acc[9]);
        acc[10] = fmaf(hv, w2.z, acc[10]); acc[11] = fmaf(hv, w2.w, acc[11]);
        acc[12] = fmaf(hv, w3.x, acc[12]); acc[13] = fmaf(hv, w3.y, acc[13]);
        acc[14] = fmaf(hv, w3.z, acc[14]); acc[15] = fmaf(hv, w3.w, acc[15]);
    }
#pragma unroll
    for (int e = 0; e < 16; e++)
#pragma unroll
        for (int o = 16; o; o >>= 1) acc[e] += __shfl_xor_sync(0xffffffffu, acc[e], o);
    if (lane == 0) {
        float v1 = -1.f, v2 = -1.f;
        int i1 = 0, i2 = 0;
#pragma unroll
        for (int e = 0; e < 16; e++) {
            float sg = 1.0f / (1.0f + __expf(-acc[e]));
            if (sg > v1) { v2 = v1; i2 = i1; v1 = sg; i1 = e; }
            else if (sg > v2) { v2 = sg; i2 = e; }
        }
        int p1 = atomicAdd(&g_cnt[i1], 1);
        g_elist[i1 * T_ + p1] = t;
        g_egate[i1 * T_ + p1] = v1;
        int p2 = atomicAdd(&g_cnt[i2], 1);
        g_elist[i2 * T_ + p2] = t;
        g_egate[i2 * T_ + p2] = v2;
    }
}

// ---------------- launch ----------------
extern "C" void kernel_launch(void* const* d_in, const int* in_sizes, int n_in,
                              void* d_out, int out_size) {
    (void)in_sizes; (void)n_in; (void)out_size;
    const float* x    = (const float*)d_in[0];
    const float* Wq   = (const float*)d_in[1];
    const float* Wk   = (const float*)d_in[2];
    const float* Wv   = (const float*)d_in[3];
    const float* Wo   = (const float*)d_in[4];
    const float* ln1s = (const float*)d_in[5];
    const float* ln1b = (const float*)d_in[6];
    const float* ln2s = (const float*)d_in[7];
    const float* ln2b = (const float*)d_in[8];
    const float* Wsel = (const float*)d_in[9];
    const float* W1   = (const float*)d_in[10];
    const float* W2   = (const float*)d_in[11];
    float* out = (float*)d_out;

    __half *wqkvh, *woh, *w1h, *w2h, *h1h, *qkvh, *ctxh, *h2h, *uph;
    float *x2p, *h2p;
    cudaGetSymbolAddress((void**)&wqkvh, g_wqkvh);
    cudaGetSymbolAddress((void**)&woh,   g_woh);
    cudaGetSymbolAddress((void**)&w1h,   g_w1h);
    cudaGetSymbolAddress((void**)&w2h,   g_w2h);
    cudaGetSymbolAddress((void**)&h1h,   g_h1h);
    cudaGetSymbolAddress((void**)&qkvh,  g_qkvh);
    cudaGetSymbolAddress((void**)&ctxh,  g_ctxh);
    cudaGetSymbolAddress((void**)&h2h,   g_h2h);
    cudaGetSymbolAddress((void**)&uph,   g_uph);
    cudaGetSymbolAddress((void**)&x2p,   g_x2);
    cudaGetSymbolAddress((void**)&h2p,   g_h2);

    const int DD4 = D_ * D_ / 4;
    const int EDF4 = E_ * D_ * F_ / 4;
    conv_f2h<<<512, 256>>>((const float4*)Wq, (uint2*)(wqkvh),               DD4);
    conv_f2h<<<512, 256>>>((const float4*)Wk, (uint2*)(wqkvh + D_ * D_),     DD4);
    conv_f2h<<<512, 256>>>((const float4*)Wv, (uint2*)(wqkvh + 2 * D_ * D_), DD4);
    conv_f2h<<<512, 256>>>((const float4*)Wo, (uint2*)(woh),                 DD4);
    conv_f2h<<<512, 256>>>((const float4*)W1, (uint2*)(w1h),                 EDF4);
    conv_f2h<<<512, 256>>>((const float4*)W2, (uint2*)(w2h),                 EDF4);

    zero_cnt_kernel<<<1, 32>>>();
    ln_h_kernel<<<T_, 256>>>(x, ln1s, ln1b, h1h);

    gemm_h<0><<<dim3(D_ / 128, T_ / 128, 3), 256>>>(
        h1h, wqkvh, nullptr, nullptr, nullptr, qkvh, T_, D_, D_);

    attn_h_kernel<<<dim3(S_ / 64, B_ * H_), 128>>>(
        qkvh, qkvh + (size_t)T_ * D_, qkvh + 2 * (size_t)T_ * D_, ctxh);

    gemm_h<1><<<dim3(D_ / 128, T_ / 128, 1), 256>>>(
        ctxh, woh, x, x2p, out, nullptr, T_, D_, D_);

    ln_dual_kernel<<<T_, 256>>>(x2p, ln2s, ln2b, h2p, h2h);
    selector_kernel<<<T_ / 4, 128>>>(h2p, Wsel);

    moe_mma<0><<<dim3(F_ / 128, T_ / 128, E_), 256>>>(h2h, w1h, uph, nullptr);
    moe_mma<1><<<dim3(D_ / 128, T_ / 128, E_), 256>>>(uph, w2h, nullptr, out);
}

// round 8
// speedup vs baseline: 6.8403x; 1.0311x over previous
#include <cuda_runtime.h>
#include <cuda_fp16.h>
#include <math.h>

#define B_  2
#define S_  2048
#define D_  1024
#define H_  16
#define DH_ 64
#define E_  16
#define F_  256
#define T_  (B_*S_)

// ---------------- scratch ----------------
__device__ __half g_wqkvh[(size_t)3*D_*D_];
__device__ __half g_woh[(size_t)D_*D_];
__device__ __half g_w1h[(size_t)E_*D_*F_];
__device__ __half g_w2h[(size_t)E_*F_*D_];
__device__ __half g_h1h[(size_t)T_*D_];
__device__ __half g_qkvh[(size_t)3*T_*D_];
__device__ __half g_ctxh[(size_t)T_*D_];
__device__ __half g_h2h[(size_t)T_*D_];
__device__ __half g_uph[(size_t)E_*T_*F_];
__device__ float g_x2[(size_t)T_*D_];
__device__ float g_h2[(size_t)T_*D_];
__device__ int   g_cnt[E_];
__device__ int   g_elist[E_*T_];
__device__ float g_egate[E_*T_];

__global__ void zero_cnt_kernel() {
    if (threadIdx.x < E_) g_cnt[threadIdx.x] = 0;
}

// ---------------- helpers ----------------
__device__ __forceinline__ unsigned packh(float lo, float hi) {
    unsigned u;
    asm("cvt.rn.f16x2.f32 %0, %1, %2;" : "=r"(u) : "f"(hi), "f"(lo));
    return u;
}

__device__ __forceinline__ void mma16(float* d, const unsigned* a, unsigned b0, unsigned b1) {
    asm volatile(
        "mma.sync.aligned.m16n8k16.row.col.f32.f16.f16.f32 "
        "{%0,%1,%2,%3},{%4,%5,%6,%7},{%8,%9},{%0,%1,%2,%3};"
        : "+f"(d[0]), "+f"(d[1]), "+f"(d[2]), "+f"(d[3])
        : "r"(a[0]), "r"(a[1]), "r"(a[2]), "r"(a[3]), "r"(b0), "r"(b1));
}

// ---------------- fp32 -> fp16 convert ----------------
__global__ __launch_bounds__(256) void conv_f2h(const float4* __restrict__ s,
                                                uint2* __restrict__ d, int n4) {
    int i = blockIdx.x * blockDim.x + threadIdx.x;
    int stride = gridDim.x * blockDim.x;
    for (; i < n4; i += stride) {
        float4 v = s[i];
        uint2 o;
        o.x = packh(v.x, v.y);
        o.y = packh(v.z, v.w);
        d[i] = o;
    }
}

// ---------------- LayerNorm (fp16 out) ----------------
__global__ __launch_bounds__(256) void ln_h_kernel(const float* __restrict__ x,
                                                   const float* __restrict__ sc,
                                                   const float* __restrict__ bi,
                                                   __half* __restrict__ o) {
    int t = blockIdx.x;
    const float* xr = x + (size_t)t * D_;
    __half* orow = o + (size_t)t * D_;
    float v[4];
    float s = 0.f, s2 = 0.f;
#pragma unroll
    for (int i = 0; i < 4; i++) {
        v[i] = xr[threadIdx.x + i * 256];
        s  += v[i];
        s2 += v[i] * v[i];
    }
#pragma unroll
    for (int off = 16; off; off >>= 1) {
        s  += __shfl_xor_sync(0xffffffffu, s,  off);
        s2 += __shfl_xor_sync(0xffffffffu, s2, off);
    }
    __shared__ float ws[8], ws2[8];
    int w = threadIdx.x >> 5, ln = threadIdx.x & 31;
    if (ln == 0) { ws[w] = s; ws2[w] = s2; }
    __syncthreads();
    float S = 0.f, S2 = 0.f;
#pragma unroll
    for (int i = 0; i < 8; i++) { S += ws[i]; S2 += ws2[i]; }
    float mu  = S * (1.0f / D_);
    float var = S2 * (1.0f / D_) - mu * mu;
    float inv = rsqrtf(var + 1e-5f);
#pragma unroll
    for (int i = 0; i < 4; i++) {
        int d = threadIdx.x + i * 256;
        orow[d] = __float2half((v[i] - mu) * inv * sc[d] + bi[d]);
    }
}

// ---------------- LayerNorm dual output (fp32 + fp16) ----------------
__global__ __launch_bounds__(256) void ln_dual_kernel(const float* __restrict__ x,
                                                      const float* __restrict__ sc,
                                                      const float* __restrict__ bi,
                                                      float* __restrict__ of,
                                                      __half* __restrict__ oh) {
    int t = blockIdx.x;
    const float* xr = x + (size_t)t * D_;
    float v[4];
    float s = 0.f, s2 = 0.f;
#pragma unroll
    for (int i = 0; i < 4; i++) {
        v[i] = xr[threadIdx.x + i * 256];
        s  += v[i];
        s2 += v[i] * v[i];
    }
#pragma unroll
    for (int off = 16; off; off >>= 1) {
        s  += __shfl_xor_sync(0xffffffffu, s,  off);
        s2 += __shfl_xor_sync(0xffffffffu, s2, off);
    }
    __shared__ float ws[8], ws2[8];
    int w = threadIdx.x >> 5, ln = threadIdx.x & 31;
    if (ln == 0) { ws[w] = s; ws2[w] = s2; }
    __syncthreads();
    float S = 0.f, S2 = 0.f;
#pragma unroll
    for (int i = 0; i < 8; i++) { S += ws[i]; S2 += ws2[i]; }
    float mu  = S * (1.0f / D_);
    float var = S2 * (1.0f / D_) - mu * mu;
    float inv = rsqrtf(var + 1e-5f);
#pragma unroll
    for (int i = 0; i < 4; i++) {
        int d = threadIdx.x + i * 256;
        float r = (v[i] - mu) * inv * sc[d] + bi[d];
        of[(size_t)t * D_ + d] = r;
        oh[(size_t)t * D_ + d] = __float2half(r);
    }
}

// ---------------- fp16 tensor-core GEMM, register double-buffered ---------------
template <int MODE>
__global__ __launch_bounds__(256) void gemm_h(const __half* __restrict__ A,
                                              const __half* __restrict__ Bw,
                                              const float* __restrict__ Res,
                                              float* __restrict__ Cf,
                                              float* __restrict__ C2f,
                                              __half* __restrict__ Cb,
                                              int M, int N, int K) {
    __shared__ unsigned As32[128 * 20];
    __shared__ unsigned Bs32[16 * 132];

    const __half* Bz = Bw + (size_t)blockIdx.z * K * N;
    int tid = threadIdx.x, warp = tid >> 5, lane = tid & 31;
    int g = lane >> 2, t4 = lane & 3;
    int wm = warp >> 1, wn = warp & 1;
    int bx = blockIdx.x * 128, by = blockIdx.y * 128;

    float acc[2][8][4];
#pragma unroll
    for (int i = 0; i < 2; i++)
#pragma unroll
        for (int j = 0; j < 8; j++)
#pragma unroll
            for (int q = 0; q < 4; q++) acc[i][j][q] = 0.f;

    int ar = tid >> 1, ah = tid & 1;
    int bk2 = tid >> 4, bc8 = (tid & 15) * 8;
    const __half* Arow = A + (size_t)(by + ar) * K + ah * 16;

    uint4 a0, a1, w0, w1;
    {   // prologue: tile 0
        const uint4* ap = (const uint4*)(Arow);
        a0 = ap[0]; a1 = ap[1];
        w0 = *(const uint4*)(Bz + (size_t)(2 * bk2) * N + bx + bc8);
        w1 = *(const uint4*)(Bz + (size_t)(2 * bk2 + 1) * N + bx + bc8);
    }

    for (int k0 = 0; k0 < K; k0 += 32) {
        __syncthreads();
        *(uint4*)&As32[ar * 20 + ah * 8]     = a0;
        *(uint4*)&As32[ar * 20 + ah * 8 + 4] = a1;
        {
            uint4 o03, o47;
            o03.x = __byte_perm(w0.x, w1.x, 0x5410);
            o03.y = __byte_perm(w0.x, w1.x, 0x7632);
            o03.z = __byte_perm(w0.y, w1.y, 0x5410);
            o03.w = __byte_perm(w0.y, w1.y, 0x7632);
            o47.x = __byte_perm(w0.z, w1.z, 0x5410);
            o47.y = __byte_perm(w0.z, w1.z, 0x7632);
            o47.z = __byte_perm(w0.w, w1.w, 0x5410);
            o47.w = __byte_perm(w0.w, w1.w, 0x7632);
            *(uint4*)&Bs32[bk2 * 132 + bc8]     = o03;
            *(uint4*)&Bs32[bk2 * 132 + bc8 + 4] = o47;
        }
        __syncthreads();

        {   // prefetch next tile (clamped; last iter reloads same tile, L1-hit)
            int kn = (k0 + 32 < K) ? k0 + 32 : k0;
            const uint4* ap = (const uint4*)(Arow + kn);
            a0 = ap[0]; a1 = ap[1];
            w0 = *(const uint4*)(Bz + (size_t)(kn + 2 * bk2) * N + bx + bc8);
            w1 = *(const uint4*)(Bz + (size_t)(kn + 2 * bk2 + 1) * N + bx + bc8);
        }

#pragma unroll
        for (int kc = 0; kc < 2; kc++) {
            unsigned afr[2][4];
#pragma unroll
            for (int mt = 0; mt < 2; mt++) {
                int r0 = wm * 32 + mt * 16;
                afr[mt][0] = As32[(r0 + g) * 20 + kc * 8 + t4];
                afr[mt][1] = As32[(r0 + g + 8) * 20 + kc * 8 + t4];
                afr[mt][2] = As32[(r0 + g) * 20 + kc * 8 + t4 + 4];
                afr[mt][3] = As32[(r0 + g + 8) * 20 + kc * 8 + t4 + 4];
            }
#pragma unroll
            for (int nt = 0; nt < 8; nt++) {
                int c0 = wn * 64 + nt * 8 + g;
                unsigned bb0 = Bs32[(kc * 8 + t4) * 132 + c0];
                unsigned bb1 = Bs32[(kc * 8 + t4 + 4) * 132 + c0];
                mma16(acc[0][nt], afr[0], bb0, bb1);
                mma16(acc[1][nt], afr[1], bb0, bb1);
            }
        }
    }

    if (MODE == 0) {
        __half* Cz = Cb + (size_t)blockIdx.z * M * N;
#pragma unroll
        for (int mt = 0; mt < 2; mt++) {
#pragma unroll
            for (int nt = 0; nt < 8; nt++) {
                int col = bx + wn * 64 + nt * 8 + 2 * t4;
                size_t r0 = (size_t)(by + wm * 32 + mt * 16 + g);
                *(unsigned*)(Cz + r0 * N + col)       = packh(acc[mt][nt][0], acc[mt][nt][1]);
                *(unsigned*)(Cz + (r0 + 8) * N + col) = packh(acc[mt][nt][2], acc[mt][nt][3]);
            }
        }
    } else {
#pragma unroll
        for (int mt = 0; mt < 2; mt++) {
#pragma unroll
            for (int nt = 0; nt < 8; nt++) {
                int col = bx + wn * 64 + nt * 8 + 2 * t4;
                size_t r0 = (size_t)(by + wm * 32 + mt * 16 + g);
                size_t r1 = r0 + 8;
                float2 v01 = {acc[mt][nt][0], acc[mt][nt][1]};
                float2 v23 = {acc[mt][nt][2], acc[mt][nt][3]};
                float2 q0 = *(const float2*)(Res + r0 * N + col);
                float2 q1 = *(const float2*)(Res + r1 * N + col);
                v01.x += q0.x; v01.y += q0.y;
                v23.x += q1.x; v23.y += q1.y;
                *(float2*)(Cf + r0 * N + col) = v01;
                *(float2*)(Cf + r1 * N + col) = v23;
                *(float2*)(C2f + r0 * N + col) = v01;
                *(float2*)(C2f + r1 * N + col) = v23;
            }
        }
    }
}

// ---------------- MoE fp16 tensor-core GEMM, register double-buffered -----------
template <int MODE>
__global__ __launch_bounds__(256) void moe_mma(const __half* __restrict__ Ab,
                                               const __half* __restrict__ Wb,
                                               __half* __restrict__ Uph,
                                               float* __restrict__ out) {
    int e = blockIdx.z;
    int n = g_cnt[e];
    int rb = blockIdx.y * 128;
    if (rb >= n) return;
    const int N = (MODE == 0) ? F_ : D_;
    const int K = (MODE == 0) ? D_ : F_;
    const __half* Wz = Wb + (size_t)e * K * N;

    __shared__ unsigned As32[128 * 20];
    __shared__ unsigned Bs32[16 * 132];
    __shared__ int rows[128];

    int tid = threadIdx.x, warp = tid >> 5, lane = tid & 31;
    int g = lane >> 2, t4 = lane & 3;
    int wm = warp >> 1, wn = warp & 1;
    int bx = blockIdx.x * 128;

    if (MODE == 0) {
        if (tid < 128) {
            int rg = rb + tid;
            rows[tid] = (rg < n) ? g_elist[e * T_ + rg] : 0;
        }
        __syncthreads();
    }

    float acc[2][8][4];
#pragma unroll
    for (int i = 0; i < 2; i++)
#pragma unroll
        for (int j = 0; j < 8; j++)
#pragma unroll
            for (int q = 0; q < 4; q++) acc[i][j][q] = 0.f;

    int ar = tid >> 1, ah = tid & 1;
    int bk2 = tid >> 4, bc8 = (tid & 15) * 8;

    const __half* Arow;
    if (MODE == 0)
        Arow = Ab + (size_t)rows[ar] * D_ + ah * 16;
    else
        Arow = Ab + ((size_t)e * T_ + rb + ar) * F_ + ah * 16;

    uint4 a0, a1, w0, w1;
    {
        const uint4* ap = (const uint4*)(Arow);
        a0 = ap[0]; a1 = ap[1];
        w0 = *(const uint4*)(Wz + (size_t)(2 * bk2) * N + bx + bc8);
        w1 = *(const uint4*)(Wz + (size_t)(2 * bk2 + 1) * N + bx + bc8);
    }

    for (int k0 = 0; k0 < K; k0 += 32) {
        __syncthreads();
        *(uint4*)&As32[ar * 20 + ah * 8]     = a0;
        *(uint4*)&As32[ar * 20 + ah * 8 + 4] = a1;
        {
            uint4 o03, o47;
            o03.x = __byte_perm(w0.x, w1.x, 0x5410);
            o03.y = __byte_perm(w0.x, w1.x, 0x7632);
            o03.z = __byte_perm(w0.y, w1.y, 0x5410);
            o03.w = __byte_perm(w0.y, w1.y, 0x7632);
            o47.x = __byte_perm(w0.z, w1.z, 0x5410);
            o47.y = __byte_perm(w0.z, w1.z, 0x7632);
            o47.z = __byte_perm(w0.w, w1.w, 0x5410);
            o47.w = __byte_perm(w0.w, w1.w, 0x7632);
            *(uint4*)&Bs32[bk2 * 132 + bc8]     = o03;
            *(uint4*)&Bs32[bk2 * 132 + bc8 + 4] = o47;
        }
        __syncthreads();

        {
            int kn = (k0 + 32 < K) ? k0 + 32 : k0;
            const uint4* ap = (const uint4*)(Arow + kn);
            a0 = ap[0]; a1 = ap[1];
            w0 = *(const uint4*)(Wz + (size_t)(kn + 2 * bk2) * N + bx + bc8);
            w1 = *(const uint4*)(Wz + (size_t)(kn + 2 * bk2 + 1) * N + bx + bc8);
        }

#pragma unroll
        for (int kc = 0; kc < 2; kc++) {
            unsigned afr[2][4];
#pragma unroll
            for (int mt = 0; mt < 2; mt++) {
                int r0 = wm * 32 + mt * 16;
                afr[mt][0] = As32[(r0 + g) * 20 + kc * 8 + t4];
                afr[mt][1] = As32[(r0 + g + 8) * 20 + kc * 8 + t4];
                afr[mt][2] = As32[(r0 + g) * 20 + kc * 8 + t4 + 4];
                afr[mt][3] = As32[(r0 + g + 8) * 20 + kc * 8 + t4 + 4];
            }
#pragma unroll
            for (int nt = 0; nt < 8; nt++) {
                int c0 = wn * 64 + nt * 8 + g;
                unsigned bb0 = Bs32[(kc * 8 + t4) * 132 + c0];
                unsigned bb1 = Bs32[(kc * 8 + t4 + 4) * 132 + c0];
                mma16(acc[0][nt], afr[0], bb0, bb1);
                mma16(acc[1][nt], afr[1], bb0, bb1);
            }
        }
    }

    if (MODE == 0) {
#pragma unroll
        for (int mt = 0; mt < 2; mt++) {
            int rg0 = rb + wm * 32 + mt * 16 + g;
            int rg1 = rg0 + 8;
            float gt0 = (rg0 < n) ? g_egate[e * T_ + rg0] : 0.f;
            float gt1 = (rg1 < n) ? g_egate[e * T_ + rg1] : 0.f;
#pragma unroll
            for (int nt = 0; nt < 8; nt++) {
                int col = bx + wn * 64 + nt * 8 + 2 * t4;
                if (rg0 < n)
                    *(unsigned*)(Uph + ((size_t)e * T_ + rg0) * F_ + col) =
                        packh(fmaxf(acc[mt][nt][0], 0.f) * gt0,
                              fmaxf(acc[mt][nt][1], 0.f) * gt0);
                if (rg1 < n)
                    *(unsigned*)(Uph + ((size_t)e * T_ + rg1) * F_ + col) =
                        packh(fmaxf(acc[mt][nt][2], 0.f) * gt1,
                              fmaxf(acc[mt][nt][3], 0.f) * gt1);
            }
        }
    } else {
#pragma unroll
        for (int mt = 0; mt < 2; mt++) {
            int rg0 = rb + wm * 32 + mt * 16 + g;
            int rg1 = rg0 + 8;
            int t0 = (rg0 < n) ? g_elist[e * T_ + rg0] : -1;
            int t1 = (rg1 < n) ? g_elist[e * T_ + rg1] : -1;
#pragma unroll
            for (int nt = 0; nt < 8; nt++) {
                int col = bx + wn * 64 + nt * 8 + 2 * t4;
                if (t0 >= 0) {
                    atomicAdd(out + (size_t)t0 * D_ + col,     acc[mt][nt][0]);
                    atomicAdd(out + (size_t)t0 * D_ + col + 1, acc[mt][nt][1]);
                }
                if (t1 >= 0) {
                    atomicAdd(out + (size_t)t1 * D_ + col,     acc[mt][nt][2]);
                    atomicAdd(out + (size_t)t1 * D_ + col + 1, acc[mt][nt][3]);
                }
            }
        }
    }
}

// ---------------- fp16 flash attention, register-resident P + K/V prefetch ------
__global__ __launch_bounds__(128) void attn_h_kernel(const __half* __restrict__ Q,
                                                     const __half* __restrict__ Kb,
                                                     const __half* __restrict__ Vb,
                                                     __half* __restrict__ O) {
    __shared__ unsigned Ks32[64 * 36];
    __shared__ unsigned Vs32[32 * 68];

    int bh = blockIdx.y;
    int b = bh >> 4, h = bh & 15;
    int q0 = blockIdx.x * 64;
    int tid = threadIdx.x, warp = tid >> 5, lane = tid & 31;
    int g = lane >> 2, t4 = lane & 3;

    // ---- stage Q tile, read fragments into registers ----
#pragma unroll
    for (int i = 0; i < 4; i++) {
        int idx = tid + i * 128;
        int row = idx >> 3, uq = idx & 7;
        *(uint4*)&Ks32[row * 36 + uq * 4] =
            *(const uint4*)(Q + (size_t)(b * S_ + q0 + row) * D_ + h * 64 + uq * 8);
    }
    __syncthreads();
    unsigned qf[4][4];
    {
        int r0 = warp * 16;
#pragma unroll
        for (int kc = 0; kc < 4; kc++) {
            qf[kc][0] = Ks32[(r0 + g) * 36 + kc * 8 + t4];
            qf[kc][1] = Ks32[(r0 + g + 8) * 36 + kc * 8 + t4];
            qf[kc][2] = Ks32[(r0 + g) * 36 + kc * 8 + t4 + 4];
            qf[kc][3] = Ks32[(r0 + g + 8) * 36 + kc * 8 + t4 + 4];
        }
    }

    // ---- prefetch K/V tile 0 into registers ----
    uint4 kp[4], vpa[2], vpb[2];
#pragma unroll
    for (int i = 0; i < 4; i++) {
        int idx = tid + i * 128;
        int row = idx >> 3, uq = idx & 7;
        kp[i] = *(const uint4*)(Kb + (size_t)(b * S_ + row) * D_ + h * 64 + uq * 8);
    }
#pragma unroll
    for (int i = 0; i < 2; i++) {
        int task = tid + i * 128;
        int tp = task >> 3, uq = task & 7;
        size_t base = (size_t)(b * S_ + 2 * tp) * D_ + h * 64 + uq * 8;
        vpa[i] = *(const uint4*)(Vb + base);
        vpb[i] = *(const uint4*)(Vb + base + D_);
    }

    float oacc[8][4];
#pragma unroll
    for (int i = 0; i < 8; i++)
#pragma unroll
        for (int j = 0; j < 4; j++) oacc[i][j] = 0.f;
    float m0 = -1e30f, m1 = -1e30f, l0 = 0.f, l1 = 0.f;

    for (int kt = 0; kt < S_; kt += 64) {
        __syncthreads();   // qf read done / prior compute done
        // store prefetched K (direct) + V (token-pair interleave)
#pragma unroll
        for (int i = 0; i < 4; i++) {
            int idx = tid + i * 128;
            int row = idx >> 3, uq = idx & 7;
            *(uint4*)&Ks32[row * 36 + uq * 4] = kp[i];
        }
#pragma unroll
        for (int i = 0; i < 2; i++) {
            int task = tid + i * 128;
            int tp = task >> 3, uq = task & 7;
            uint4 w0 = vpa[i], w1 = vpb[i];
            uint4 o03, o47;
            o03.x = __byte_perm(w0.x, w1.x, 0x5410);
            o03.y = __byte_perm(w0.x, w1.x, 0x7632);
            o03.z = __byte_perm(w0.y, w1.y, 0x5410);
            o03.w = __byte_perm(w0.y, w1.y, 0x7632);
            o47.x = __byte_perm(w0.z, w1.z, 0x5410);
            o47.y = __byte_perm(w0.z, w1.z, 0x7632);
            o47.z = __byte_perm(w0.w, w1.w, 0x5410);
            o47.w = __byte_perm(w0.w, w1.w, 0x7632);
            *(uint4*)&Vs32[tp * 68 + uq * 8]     = o03;
            *(uint4*)&Vs32[tp * 68 + uq * 8 + 4] = o47;
        }
        __syncthreads();

        // prefetch next K/V tile
        {
            int ktn = (kt + 64 < S_) ? kt + 64 : kt;
#pragma unroll
            for (int i = 0; i < 4; i++) {
                int idx = tid + i * 128;
                int row = idx >> 3, uq = idx & 7;
                kp[i] = *(const uint4*)(Kb + (size_t)(b * S_ + ktn + row) * D_ + h * 64 + uq * 8);
            }
#pragma unroll
            for (int i = 0; i < 2; i++) {
                int task = tid + i * 128;
                int tp = task >> 3, uq = task & 7;
                size_t base = (size_t)(b * S_ + ktn + 2 * tp) * D_ + h * 64 + uq * 8;
                vpa[i] = *(const uint4*)(Vb + base);
                vpb[i] = *(const uint4*)(Vb + base + D_);
            }
        }

        // ---- S = Q @ K^T ----
        float sacc[8][4];
#pragma unroll
        for (int i = 0; i < 8; i++)
#pragma unroll
            for (int j = 0; j < 4; j++) sacc[i][j] = 0.f;
#pragma unroll
        for (int nt = 0; nt < 8; nt++) {
            int kr = (nt * 8 + g) * 36;
#pragma unroll
            for (int kc = 0; kc < 4; kc++) {
                unsigned bb0 = Ks32[kr + kc * 8 + t4];
                unsigned bb1 = Ks32[kr + kc * 8 + t4 + 4];
                mma16(sacc[nt], qf[kc], bb0, bb1);
            }
        }
#pragma unroll
        for (int nt = 0; nt < 8; nt++)
#pragma unroll
            for (int j = 0; j < 4; j++) sacc[nt][j] *= 0.125f;

        // ---- online softmax ----
        float mx0 = -1e30f, mx1 = -1e30f;
#pragma unroll
        for (int nt = 0; nt < 8; nt++) {
            mx0 = fmaxf(mx0, fmaxf(sacc[nt][0], sacc[nt][1]));
            mx1 = fmaxf(mx1, fmaxf(sacc[nt][2], sacc[nt][3]));
        }
        mx0 = fmaxf(mx0, __shfl_xor_sync(0xffffffffu, mx0, 1));
        mx0 = fmaxf(mx0, __shfl_xor_sync(0xffffffffu, mx0, 2));
        mx1 = fmaxf(mx1, __shfl_xor_sync(0xffffffffu, mx1, 1));
        mx1 = fmaxf(mx1, __shfl_xor_sync(0xffffffffu, mx1, 2));
        float mn0 = fmaxf(m0, mx0), mn1 = fmaxf(m1, mx1);
        float al0 = __expf(m0 - mn0), al1 = __expf(m1 - mn1);
        float rs0 = 0.f, rs1 = 0.f;
#pragma unroll
        for (int nt = 0; nt < 8; nt++) {
            sacc[nt][0] = __expf(sacc[nt][0] - mn0);
            sacc[nt][1] = __expf(sacc[nt][1] - mn0);
            sacc[nt][2] = __expf(sacc[nt][2] - mn1);
            sacc[nt][3] = __expf(sacc[nt][3] - mn1);
            rs0 += sacc[nt][0] + sacc[nt][1];
            rs1 += sacc[nt][2] + sacc[nt][3];
        }
        rs0 += __shfl_xor_sync(0xffffffffu, rs0, 1);
        rs0 += __shfl_xor_sync(0xffffffffu, rs0, 2);
        rs1 += __shfl_xor_sync(0xffffffffu, rs1, 1);
        rs1 += __shfl_xor_sync(0xffffffffu, rs1, 2);
        l0 = l0 * al0 + rs0;
        l1 = l1 * al1 + rs1;
        m0 = mn0; m1 = mn1;
#pragma unroll
        for (int dt = 0; dt < 8; dt++) {
            oacc[dt][0] *= al0; oacc[dt][1] *= al0;
            oacc[dt][2] *= al1; oacc[dt][3] *= al1;
        }

        // ---- O += P @ V ----
#pragma unroll
        for (int kc = 0; kc < 4; kc++) {
            unsigned pf[4];
            pf[0] = packh(sacc[2 * kc][0],     sacc[2 * kc][1]);
            pf[1] = packh(sacc[2 * kc][2],     sacc[2 * kc][3]);
            pf[2] = packh(sacc[2 * kc + 1][0], sacc[2 * kc + 1][1]);
            pf[3] = packh(sacc[2 * kc + 1][2], sacc[2 * kc + 1][3]);
#pragma unroll
            for (int dt = 0; dt < 8; dt++) {
                unsigned bb0 = Vs32[(kc * 8 + t4) * 68 + dt * 8 + g];
                unsigned bb1 = Vs32[(kc * 8 + t4 + 4) * 68 + dt * 8 + g];
                mma16(oacc[dt], pf, bb0, bb1);
            }
        }
    }

    float il0 = 1.0f / l0, il1 = 1.0f / l1;
    int row = q0 + warp * 16 + g;
#pragma unroll
    for (int dt = 0; dt < 8; dt++) {
        int col = h * 64 + dt * 8 + 2 * t4;
        *(unsigned*)(O + (size_t)(b * S_ + row) * D_ + col) =
            packh(oacc[dt][0] * il0, oacc[dt][1] * il0);
        *(unsigned*)(O + (size_t)(b * S_ + row + 8) * D_ + col) =
            packh(oacc[dt][2] * il1, oacc[dt][3] * il1);
    }
}

// ---------------- Selector ----------------
__global__ __launch_bounds__(128) void selector_kernel(const float* __restrict__ h,
                                                       const float* __restrict__ Wsel) {
    int t = blockIdx.x * 4 + (threadIdx.x >> 5);
    int lane = threadIdx.x & 31;
    float acc[16];
#pragma unroll
    for (int e = 0; e < 16; e++) acc[e] = 0.f;
    const float* hr = h + (size_t)t * D_;
    for (int d = lane; d < D_; d += 32) {
        float hv = hr[d];
        const float4* w = (const float4*)(Wsel + (size_t)d * E_);
        float4 w0 = w[0], w1 = w[1], w2 = w[2], w3 = w[3];
        acc[0]  = fmaf(hv, w0.x, acc[0]);  acc[1]  = fmaf(hv, w0.y, acc[1]);
        acc[2]  = fmaf(hv, w0.z, acc[2]);  acc[3]  = fmaf(hv, w0.w, acc[3]);
        acc[4]  = fmaf(hv, w1.x, acc[4]);  acc[5]  = fmaf(hv, w1.y, acc[5]);
        acc[6]  = fmaf(hv, w1.z, acc[6]);  acc[7]  = fmaf(hv, w1.w, acc[7]);
        acc[8]  = fmaf(hv, w2.x, acc[8]);  acc[9]  = fmaf(hv, w2.y, acc[9]);
        acc[10] = fmaf(hv, w2.z, acc[10]); acc[11] = fmaf(hv, w2.w, acc[11]);
        acc[12] = fmaf(hv, w3.x, acc[12]); acc[13] = fmaf(hv, w3.y, acc[13]);
        acc[14] = fmaf(hv, w3.z, acc[14]); acc[15] = fmaf(hv, w3.w, acc[15]);
    }
#pragma unroll
    for (int e = 0; e < 16; e++)
#pragma unroll
        for (int o = 16; o; o >>= 1) acc[e] += __shfl_xor_sync(0xffffffffu, acc[e], o);
    if (lane == 0) {
        float v1 = -1.f, v2 = -1.f;
        int i1 = 0, i2 = 0;
#pragma unroll
        for (int e = 0; e < 16; e++) {
            float sg = 1.0f / (1.0f + __expf(-acc[e]));
            if (sg > v1) { v2 = v1; i2 = i1; v1 = sg; i1 = e; }
            else if (sg > v2) { v2 = sg; i2 = e; }
        }
        int p1 = atomicAdd(&g_cnt[i1], 1);
        g_elist[i1 * T_ + p1] = t;
        g_egate[i1 * T_ + p1] = v1;
        int p2 = atomicAdd(&g_cnt[i2], 1);
        g_elist[i2 * T_ + p2] = t;
        g_egate[i2 * T_ + p2] = v2;
    }
}

// ---------------- launch ----------------
extern "C" void kernel_launch(void* const* d_in, const int* in_sizes, int n_in,
                              void* d_out, int out_size) {
    (void)in_sizes; (void)n_in; (void)out_size;
    const float* x    = (const float*)d_in[0];
    const float* Wq   = (const float*)d_in[1];
    const float* Wk   = (const float*)d_in[2];
    const float* Wv   = (const float*)d_in[3];
    const float* Wo   = (const float*)d_in[4];
    const float* ln1s = (const float*)d_in[5];
    const float* ln1b = (const float*)d_in[6];
    const float* ln2s = (const float*)d_in[7];
    const float* ln2b = (const float*)d_in[8];
    const float* Wsel = (const float*)d_in[9];
    const float* W1   = (const float*)d_in[10];
    const float* W2   = (const float*)d_in[11];
    float* out = (float*)d_out;

    __half *wqkvh, *woh, *w1h, *w2h, *h1h, *qkvh, *ctxh, *h2h, *uph;
    float *x2p, *h2p;
    cudaGetSymbolAddress((void**)&wqkvh, g_wqkvh);
    cudaGetSymbolAddress((void**)&woh,   g_woh);
    cudaGetSymbolAddress((void**)&w1h,   g_w1h);
    cudaGetSymbolAddress((void**)&w2h,   g_w2h);
    cudaGetSymbolAddress((void**)&h1h,   g_h1h);
    cudaGetSymbolAddress((void**)&qkvh,  g_qkvh);
    cudaGetSymbolAddress((void**)&ctxh,  g_ctxh);
    cudaGetSymbolAddress((void**)&h2h,   g_h2h);
    cudaGetSymbolAddress((void**)&uph,   g_uph);
    cudaGetSymbolAddress((void**)&x2p,   g_x2);
    cudaGetSymbolAddress((void**)&h2p,   g_h2);

    // side stream for off-critical-path weight conversion (created once, before
    // any capture; only launches/events happen during capture)
    static cudaStream_t s_side = nullptr;
    static cudaEvent_t ev_fork = nullptr, ev_join = nullptr;
    if (s_side == nullptr) {
        cudaStreamCreateWithFlags(&s_side, cudaStreamNonBlocking);
        cudaEventCreateWithFlags(&ev_fork, cudaEventDisableTiming);
        cudaEventCreateWithFlags(&ev_join, cudaEventDisableTiming);
    }

    const int DD4 = D_ * D_ / 4;
    const int EDF4 = E_ * D_ * F_ / 4;

    // fork: Wo/W1/W2 conversions overlap the QKV+attention critical path
    cudaEventRecord(ev_fork, 0);
    cudaStreamWaitEvent(s_side, ev_fork, 0);
    conv_f2h<<<512, 256, 0, s_side>>>((const float4*)Wo, (uint2*)(woh), DD4);
    conv_f2h<<<512, 256, 0, s_side>>>((const float4*)W1, (uint2*)(w1h), EDF4);
    conv_f2h<<<512, 256, 0, s_side>>>((const float4*)W2, (uint2*)(w2h), EDF4);
    cudaEventRecord(ev_join, s_side);

    // main path
    conv_f2h<<<512, 256>>>((const float4*)Wq, (uint2*)(wqkvh),               DD4);
    conv_f2h<<<512, 256>>>((const float4*)Wk, (uint2*)(wqkvh + D_ * D_),     DD4);
    conv_f2h<<<512, 256>>>((const float4*)Wv, (uint2*)(wqkvh + 2 * D_ * D_), DD4);
    zero_cnt_kernel<<<1, 32>>>();
    ln_h_kernel<<<T_, 256>>>(x, ln1s, ln1b, h1h);

    gemm_h<0><<<dim3(D_ / 128, T_ / 128, 3), 256>>>(
        h1h, wqkvh, nullptr, nullptr, nullptr, qkvh, T_, D_, D_);

    attn_h_kernel<<<dim3(S_ / 64, B_ * H_), 128>>>(
        qkvh, qkvh + (size_t)T_ * D_, qkvh + 2 * (size_t)T_ * D_, ctxh);

    // join side stream before consuming woh/w1h/w2h
    cudaStreamWaitEvent(0, ev_join, 0);

    gemm_h<1><<<dim3(D_ / 128, T_ / 128, 1), 256>>>(
        ctxh, woh, x, x2p, out, nullptr, T_, D_, D_);

    ln_dual_kernel<<<T_, 256>>>(x2p, ln2s, ln2b, h2p, h2h);
    selector_kernel<<<T_ / 4, 128>>>(h2p, Wsel);

    moe_mma<0><<<dim3(F_ / 128, T_ / 128, E_), 256>>>(h2h, w1h, uph, nullptr);
    moe_mma<1><<<dim3(D_ / 128, T_ / 128, E_), 256>>>(uph, w2h, nullptr, out);
}

// round 11
// speedup vs baseline: 7.3297x; 1.0715x over previous
#include <cuda_runtime.h>
#include <cuda_fp16.h>
#include <stdint.h>
#include <cstdint>
#include <math.h>

#define B_  2
#define S_  2048
#define D_  1024
#define H_  16
#define DH_ 64
#define E_  16
#define F_  256
#define T_  (B_*S_)

// ---------------- scratch ----------------
__device__ __half g_wqkvT[(size_t)3*D_*D_];   // transposed [N][K] per matrix
__device__ __half g_woT[(size_t)D_*D_];
__device__ __half g_w1h[(size_t)E_*D_*F_];
__device__ __half g_w2h[(size_t)E_*F_*D_];
__device__ __half g_h1h[(size_t)T_*D_];
__device__ __half g_qkvh[(size_t)3*T_*D_];
__device__ __half g_ctxh[(size_t)T_*D_];
__device__ __half g_h2h[(size_t)T_*D_];
__device__ __half g_uph[(size_t)E_*T_*F_];
__device__ float g_x2[(size_t)T_*D_];
__device__ float g_h2[(size_t)T_*D_];
__device__ int   g_cnt[E_];
__device__ int   g_elist[E_*T_];
__device__ float g_egate[E_*T_];

__global__ void zero_cnt_kernel() {
    if (threadIdx.x < E_) g_cnt[threadIdx.x] = 0;
}

// ---------------- helpers ----------------
__device__ __forceinline__ unsigned packh(float lo, float hi) {
    unsigned u;
    asm("cvt.rn.f16x2.f32 %0, %1, %2;" : "=r"(u) : "f"(hi), "f"(lo));
    return u;
}

__device__ __forceinline__ void mma16(float* d, const unsigned* a, unsigned b0, unsigned b1) {
    asm volatile(
        "mma.sync.aligned.m16n8k16.row.col.f32.f16.f16.f32 "
        "{%0,%1,%2,%3},{%4,%5,%6,%7},{%8,%9},{%0,%1,%2,%3};"
        : "+f"(d[0]), "+f"(d[1]), "+f"(d[2]), "+f"(d[3])
        : "r"(a[0]), "r"(a[1]), "r"(a[2]), "r"(a[3]), "r"(b0), "r"(b1));
}

__device__ __forceinline__ uint32_t smem_u32(const void* p) {
    uint32_t a;
    asm("{ .reg .u64 t; cvta.to.shared.u64 t, %1; cvt.u32.u64 %0, t; }" : "=r"(a) : "l"(p));
    return a;
}

__device__ __forceinline__ void ldsm4(unsigned* r, uint32_t addr) {
    asm volatile("ldmatrix.sync.aligned.m8n8.x4.shared.b16 {%0,%1,%2,%3}, [%4];"
                 : "=r"(r[0]), "=r"(r[1]), "=r"(r[2]), "=r"(r[3]) : "r"(addr));
}

__device__ __forceinline__ void ldsm4t(unsigned* r, uint32_t addr) {
    asm volatile("ldmatrix.sync.aligned.m8n8.x4.trans.shared.b16 {%0,%1,%2,%3}, [%4];"
                 : "=r"(r[0]), "=r"(r[1]), "=r"(r[2]), "=r"(r[3]) : "r"(addr));
}

#define CP_ASYNC16(dst, src) \
    asm volatile("cp.async.cg.shared.global [%0], [%1], 16;" :: "r"(dst), "l"(src))
#define CP_COMMIT() asm volatile("cp.async.commit_group;")
#define CP_WAIT(n)  asm volatile("cp.async.wait_group %0;" :: "n"(n))

// ---------------- fp32 -> fp16 convert ----------------
__global__ __launch_bounds__(256) void conv_f2h(const float4* __restrict__ s,
                                                uint2* __restrict__ d, int n4) {
    int i = blockIdx.x * blockDim.x + threadIdx.x;
    int stride = gridDim.x * blockDim.x;
    for (; i < n4; i += stride) {
        float4 v = s[i];
        uint2 o;
        o.x = packh(v.x, v.y);
        o.y = packh(v.z, v.w);
        d[i] = o;
    }
}

// ---------------- fp32 [1024][1024] -> transposed fp16 [N][K] -------------------
__global__ __launch_bounds__(256) void conv_f2h_T(const float* __restrict__ s,
                                                  __half* __restrict__ d) {
    __shared__ float t[32][33];
    int bx = blockIdx.x * 32;
    int by = blockIdx.y * 32;
    int lx = threadIdx.x & 31, ly = threadIdx.x >> 5;
#pragma unroll
    for (int i = 0; i < 4; i++) {
        int r = ly + i * 8;
        t[r][lx] = s[(size_t)(by + r) * 1024 + bx + lx];
    }
    __syncthreads();
#pragma unroll
    for (int i = 0; i < 4; i++) {
        int r = ly + i * 8;
        d[(size_t)(bx + r) * 1024 + by + lx] = __float2half(t[lx][r]);
    }
}

// ---------------- LayerNorm (fp16 out) ----------------
__global__ __launch_bounds__(256) void ln_h_kernel(const float* __restrict__ x,
                                                   const float* __restrict__ sc,
                                                   const float* __restrict__ bi,
                                                   __half* __restrict__ o) {
    int t = blockIdx.x;
    const float* xr = x + (size_t)t * D_;
    __half* orow = o + (size_t)t * D_;
    float v[4];
    float s = 0.f, s2 = 0.f;
#pragma unroll
    for (int i = 0; i < 4; i++) {
        v[i] = xr[threadIdx.x + i * 256];
        s  += v[i];
        s2 += v[i] * v[i];
    }
#pragma unroll
    for (int off = 16; off; off >>= 1) {
        s  += __shfl_xor_sync(0xffffffffu, s,  off);
        s2 += __shfl_xor_sync(0xffffffffu, s2, off);
    }
    __shared__ float ws[8], ws2[8];
    int w = threadIdx.x >> 5, ln = threadIdx.x & 31;
    if (ln == 0) { ws[w] = s; ws2[w] = s2; }
    __syncthreads();
    float S = 0.f, S2 = 0.f;
#pragma unroll
    for (int i = 0; i < 8; i++) { S += ws[i]; S2 += ws2[i]; }
    float mu  = S * (1.0f / D_);
    float var = S2 * (1.0f / D_) - mu * mu;
    float inv = rsqrtf(var + 1e-5f);
#pragma unroll
    for (int i = 0; i < 4; i++) {
        int d = threadIdx.x + i * 256;
        orow[d] = __float2half((v[i] - mu) * inv * sc[d] + bi[d]);
    }
}

// ---------------- LayerNorm dual output (fp32 + fp16) ----------------
__global__ __launch_bounds__(256) void ln_dual_kernel(const float* __restrict__ x,
                                                      const float* __restrict__ sc,
                                                      const float* __restrict__ bi,
                                                      float* __restrict__ of,
                                                      __half* __restrict__ oh) {
    int t = blockIdx.x;
    const float* xr = x + (size_t)t * D_;
    float v[4];
    float s = 0.f, s2 = 0.f;
#pragma unroll
    for (int i = 0; i < 4; i++) {
        v[i] = xr[threadIdx.x + i * 256];
        s  += v[i];
        s2 += v[i] * v[i];
    }
#pragma unroll
    for (int off = 16; off; off >>= 1) {
        s  += __shfl_xor_sync(0xffffffffu, s,  off);
        s2 += __shfl_xor_sync(0xffffffffu, s2, off);
    }
    __shared__ float ws[8], ws2[8];
    int w = threadIdx.x >> 5, ln = threadIdx.x & 31;
    if (ln == 0) { ws[w] = s; ws2[w] = s2; }
    __syncthreads();
    float S = 0.f, S2 = 0.f;
#pragma unroll
    for (int i = 0; i < 8; i++) { S += ws[i]; S2 += ws2[i]; }
    float mu  = S * (1.0f / D_);
    float var = S2 * (1.0f / D_) - mu * mu;
    float inv = rsqrtf(var + 1e-5f);
#pragma unroll
    for (int i = 0; i < 4; i++) {
        int d = threadIdx.x + i * 256;
        float r = (v[i] - mu) * inv * sc[d] + bi[d];
        of[(size_t)t * D_ + d] = r;
        oh[(size_t)t * D_ + d] = __float2half(r);
    }
}

// ---------------- GEMM: ldmatrix + cp.async double-buffer, BK=64 ----------------
// A [M][1024] fp16; Bt [N=1024][1024] fp16 (pre-transposed weights), z-indexed.
// Smem per stage: A 128 rows x 144B + B 128 rows x 144B = 36864; 2 stages = 73728.
#define TCSM 73728
#define STG_ 36864

template <int MODE>
__global__ __launch_bounds__(256) void gemm_ld(const __half* __restrict__ A,
                                               const __half* __restrict__ Bt,
                                               const float* __restrict__ Res,
                                               float* __restrict__ Cf,
                                               float* __restrict__ C2f,
                                               __half* __restrict__ Cb) {
    extern __shared__ char dsm[];
    uint32_t smb = smem_u32(dsm);

    int tid = threadIdx.x, warp = tid >> 5, lane = tid & 31;
    int g = lane >> 2, t4 = lane & 3;
    int wm = warp >> 1, wn = warp & 1;          // 4x2 warps, warp tile 32x64
    int bx = blockIdx.x * 128, by = blockIdx.y * 128;
    const __half* Bz = Bt + (size_t)blockIdx.z * D_ * D_;

    float acc[2][8][4];
#pragma unroll
    for (int i = 0; i < 2; i++)
#pragma unroll
        for (int j = 0; j < 8; j++)
#pragma unroll
            for (int q = 0; q < 4; q++) acc[i][j][q] = 0.f;

    // loader: 2 threads per row, 64B each
    int lr = tid >> 1;
    int lsh = (tid & 1) * 32;     // halves
    int lsb = (tid & 1) * 64;     // bytes
    const __half* gA = A  + (size_t)(by + lr) * D_ + lsh;
    const __half* gB = Bz + (size_t)(bx + lr) * D_ + lsh;
    uint32_t sA = smb + lr * 144 + lsb;
    uint32_t sB = smb + 18432 + lr * 144 + lsb;

    // stage 0
#pragma unroll
    for (int j = 0; j < 4; j++) {
        CP_ASYNC16(sA + j * 16, gA + j * 8);
        CP_ASYNC16(sB + j * 16, gB + j * 8);
    }
    CP_COMMIT();

    // fragment address components
    uint32_t a_off = (uint32_t)((wm * 32 + (lane & 15)) * 144 + (lane >> 4) * 16);
    uint32_t b_row = (uint32_t)(wn * 64 + ((lane >> 4) & 1) * 8 + (lane & 7));
    uint32_t b_khb = ((lane >> 3) & 1) * 16;

    for (int i = 0; i < 16; i++) {
        int s = i & 1;
        if (i + 1 < 16) {
            int s2 = (i + 1) & 1;
            int k0 = (i + 1) * 64;
#pragma unroll
            for (int j = 0; j < 4; j++) {
                CP_ASYNC16(sA + s2 * STG_ + j * 16, gA + k0 + j * 8);
                CP_ASYNC16(sB + s2 * STG_ + j * 16, gB + k0 + j * 8);
            }
            CP_COMMIT();
            CP_WAIT(1);
        } else {
            CP_WAIT(0);
        }
        __syncthreads();

        uint32_t ab = smb + s * STG_;
        uint32_t bb = ab + 18432;
#pragma unroll
        for (int kc = 0; kc < 4; kc++) {
            unsigned afr0[4], afr1[4];
            ldsm4(afr0, ab + a_off + kc * 32);
            ldsm4(afr1, ab + a_off + 16 * 144 + kc * 32);
#pragma unroll
            for (int p = 0; p < 4; p++) {
                unsigned bfr[4];
                ldsm4(bfr, bb + (b_row + p * 16) * 144 + b_khb + kc * 32);
                mma16(acc[0][2 * p],     afr0, bfr[0], bfr[1]);
                mma16(acc[0][2 * p + 1], afr0, bfr[2], bfr[3]);
                mma16(acc[1][2 * p],     afr1, bfr[0], bfr[1]);
                mma16(acc[1][2 * p + 1], afr1, bfr[2], bfr[3]);
            }
        }
        __syncthreads();
    }

    if (MODE == 0) {
        __half* Cz = Cb + (size_t)blockIdx.z * T_ * D_;
#pragma unroll
        for (int mt = 0; mt < 2; mt++) {
#pragma unroll
            for (int nt = 0; nt < 8; nt++) {
                int col = bx + wn * 64 + nt * 8 + 2 * t4;
                size_t r0 = (size_t)(by + wm * 32 + mt * 16 + g);
                *(unsigned*)(Cz + r0 * D_ + col)       = packh(acc[mt][nt][0], acc[mt][nt][1]);
                *(unsigned*)(Cz + (r0 + 8) * D_ + col) = packh(acc[mt][nt][2], acc[mt][nt][3]);
            }
        }
    } else {
#pragma unroll
        for (int mt = 0; mt < 2; mt++) {
#pragma unroll
            for (int nt = 0; nt < 8; nt++) {
                int col = bx + wn * 64 + nt * 8 + 2 * t4;
                size_t r0 = (size_t)(by + wm * 32 + mt * 16 + g);
                size_t r1 = r0 + 8;
                float2 v01 = {acc[mt][nt][0], acc[mt][nt][1]};
                float2 v23 = {acc[mt][nt][2], acc[mt][nt][3]};
                float2 q0 = *(const float2*)(Res + r0 * D_ + col);
                float2 q1 = *(const float2*)(Res + r1 * D_ + col);
                v01.x += q0.x; v01.y += q0.y;
                v23.x += q1.x; v23.y += q1.y;
                *(float2*)(Cf + r0 * D_ + col) = v01;
                *(float2*)(Cf + r1 * D_ + col) = v23;
                *(float2*)(C2f + r0 * D_ + col) = v01;
                *(float2*)(C2f + r1 * D_ + col) = v23;
            }
        }
    }
}

// ---------------- MoE fp16 mma.sync GEMM (R8, unchanged) ------------------------
template <int MODE>
__global__ __launch_bounds__(256) void moe_mma(const __half* __restrict__ Ab,
                                               const __half* __restrict__ Wb,
                                               __half* __restrict__ Uph,
                                               float* __restrict__ out) {
    int e = blockIdx.z;
    int n = g_cnt[e];
    int rb = blockIdx.y * 128;
    if (rb >= n) return;
    const int N = (MODE == 0) ? F_ : D_;
    const int K = (MODE == 0) ? D_ : F_;
    const __half* Wz = Wb + (size_t)e * K * N;

    __shared__ unsigned As32[128 * 20];
    __shared__ unsigned Bs32[16 * 132];
    __shared__ int rows[128];

    int tid = threadIdx.x, warp = tid >> 5, lane = tid & 31;
    int g = lane >> 2, t4 = lane & 3;
    int wm = warp >> 1, wn = warp & 1;
    int bx = blockIdx.x * 128;

    if (MODE == 0) {
        if (tid < 128) {
            int rg = rb + tid;
            rows[tid] = (rg < n) ? g_elist[e * T_ + rg] : 0;
        }
        __syncthreads();
    }

    float acc[2][8][4];
#pragma unroll
    for (int i = 0; i < 2; i++)
#pragma unroll
        for (int j = 0; j < 8; j++)
#pragma unroll
            for (int q = 0; q < 4; q++) acc[i][j][q] = 0.f;

    int ar = tid >> 1, ah = tid & 1;
    int bk2 = tid >> 4, bc8 = (tid & 15) * 8;

    const __half* Arow;
    if (MODE == 0)
        Arow = Ab + (size_t)rows[ar] * D_ + ah * 16;
    else
        Arow = Ab + ((size_t)e * T_ + rb + ar) * F_ + ah * 16;

    uint4 a0, a1, w0, w1;
    {
        const uint4* ap = (const uint4*)(Arow);
        a0 = ap[0]; a1 = ap[1];
        w0 = *(const uint4*)(Wz + (size_t)(2 * bk2) * N + bx + bc8);
        w1 = *(const uint4*)(Wz + (size_t)(2 * bk2 + 1) * N + bx + bc8);
    }

    for (int k0 = 0; k0 < K; k0 += 32) {
        __syncthreads();
        *(uint4*)&As32[ar * 20 + ah * 8]     = a0;
        *(uint4*)&As32[ar * 20 + ah * 8 + 4] = a1;
        {
            uint4 o03, o47;
            o03.x = __byte_perm(w0.x, w1.x, 0x5410);
            o03.y = __byte_perm(w0.x, w1.x, 0x7632);
            o03.z = __byte_perm(w0.y, w1.y, 0x5410);
            o03.w = __byte_perm(w0.y, w1.y, 0x7632);
            o47.x = __byte_perm(w0.z, w1.z, 0x5410);
            o47.y = __byte_perm(w0.z, w1.z, 0x7632);
            o47.z = __byte_perm(w0.w, w1.w, 0x5410);
            o47.w = __byte_perm(w0.w, w1.w, 0x7632);
            *(uint4*)&Bs32[bk2 * 132 + bc8]     = o03;
            *(uint4*)&Bs32[bk2 * 132 + bc8 + 4] = o47;
        }
        __syncthreads();

        {
            int kn = (k0 + 32 < K) ? k0 + 32 : k0;
            const uint4* ap = (const uint4*)(Arow + kn);
            a0 = ap[0]; a1 = ap[1];
            w0 = *(const uint4*)(Wz + (size_t)(kn + 2 * bk2) * N + bx + bc8);
            w1 = *(const uint4*)(Wz + (size_t)(kn + 2 * bk2 + 1) * N + bx + bc8);
        }

#pragma unroll
        for (int kc = 0; kc < 2; kc++) {
            unsigned afr[2][4];
#pragma unroll
            for (int mt = 0; mt < 2; mt++) {
                int r0 = wm * 32 + mt * 16;
                afr[mt][0] = As32[(r0 + g) * 20 + kc * 8 + t4];
                afr[mt][1] = As32[(r0 + g + 8) * 20 + kc * 8 + t4];
                afr[mt][2] = As32[(r0 + g) * 20 + kc * 8 + t4 + 4];
                afr[mt][3] = As32[(r0 + g + 8) * 20 + kc * 8 + t4 + 4];
            }
#pragma unroll
            for (int nt = 0; nt < 8; nt++) {
                int c0 = wn * 64 + nt * 8 + g;
                unsigned bb0 = Bs32[(kc * 8 + t4) * 132 + c0];
                unsigned bb1 = Bs32[(kc * 8 + t4 + 4) * 132 + c0];
                mma16(acc[0][nt], afr[0], bb0, bb1);
                mma16(acc[1][nt], afr[1], bb0, bb1);
            }
        }
    }

    if (MODE == 0) {
#pragma unroll
        for (int mt = 0; mt < 2; mt++) {
            int rg0 = rb + wm * 32 + mt * 16 + g;
            int rg1 = rg0 + 8;
            float gt0 = (rg0 < n) ? g_egate[e * T_ + rg0] : 0.f;
            float gt1 = (rg1 < n) ? g_egate[e * T_ + rg1] : 0.f;
#pragma unroll
            for (int nt = 0; nt < 8; nt++) {
                int col = bx + wn * 64 + nt * 8 + 2 * t4;
                if (rg0 < n)
                    *(unsigned*)(Uph + ((size_t)e * T_ + rg0) * F_ + col) =
                        packh(fmaxf(acc[mt][nt][0], 0.f) * gt0,
                              fmaxf(acc[mt][nt][1], 0.f) * gt0);
                if (rg1 < n)
                    *(unsigned*)(Uph + ((size_t)e * T_ + rg1) * F_ + col) =
                        packh(fmaxf(acc[mt][nt][2], 0.f) * gt1,
                              fmaxf(acc[mt][nt][3], 0.f) * gt1);
            }
        }
    } else {
#pragma unroll
        for (int mt = 0; mt < 2; mt++) {
            int rg0 = rb + wm * 32 + mt * 16 + g;
            int rg1 = rg0 + 8;
            int t0 = (rg0 < n) ? g_elist[e * T_ + rg0] : -1;
            int t1 = (rg1 < n) ? g_elist[e * T_ + rg1] : -1;
#pragma unroll
            for (int nt = 0; nt < 8; nt++) {
                int col = bx + wn * 64 + nt * 8 + 2 * t4;
                if (t0 >= 0) {
                    atomicAdd(out + (size_t)t0 * D_ + col,     acc[mt][nt][0]);
                    atomicAdd(out + (size_t)t0 * D_ + col + 1, acc[mt][nt][1]);
                }
                if (t1 >= 0) {
                    atomicAdd(out + (size_t)t1 * D_ + col,     acc[mt][nt][2]);
                    atomicAdd(out + (size_t)t1 * D_ + col + 1, acc[mt][nt][3]);
                }
            }
        }
    }
}

// ---------------- fp16 flash attention: ldmatrix frags, plain V -----------------
// Ks/Vs: [row][d] halves, row stride 72 halves (144 B).
__global__ __launch_bounds__(128) void attn_h_kernel(const __half* __restrict__ Q,
                                                     const __half* __restrict__ Kb,
                                                     const __half* __restrict__ Vb,
                                                     __half* __restrict__ O) {
    __shared__ unsigned Ks32[64 * 36];
    __shared__ unsigned Vs32[64 * 36];

    int bh = blockIdx.y;
    int b = bh >> 4, h = bh & 15;
    int q0 = blockIdx.x * 64;
    int tid = threadIdx.x, warp = tid >> 5, lane = tid & 31;
    int g = lane >> 2, t4 = lane & 3;

    uint32_t ksb = smem_u32(Ks32);
    uint32_t vsb = smem_u32(Vs32);

    // ---- stage Q tile into Ks, read fragments into registers ----
#pragma unroll
    for (int i = 0; i < 4; i++) {
        int idx = tid + i * 128;
        int row = idx >> 3, uq = idx & 7;
        *(uint4*)&Ks32[row * 36 + uq * 4] =
            *(const uint4*)(Q + (size_t)(b * S_ + q0 + row) * D_ + h * 64 + uq * 8);
    }
    __syncthreads();
    unsigned qf[4][4];
    {
        uint32_t qa = ksb + (warp * 16 + (lane & 15)) * 144 + (lane >> 4) * 16;
#pragma unroll
        for (int kc = 0; kc < 4; kc++) ldsm4(qf[kc], qa + kc * 32);
    }

    // ---- prefetch K/V tile 0 into registers ----
    uint4 kp[4], vp[4];
#pragma unroll
    for (int i = 0; i < 4; i++) {
        int idx = tid + i * 128;
        int row = idx >> 3, uq = idx & 7;
        size_t base = (size_t)(b * S_ + row) * D_ + h * 64 + uq * 8;
        kp[i] = *(const uint4*)(Kb + base);
        vp[i] = *(const uint4*)(Vb + base);
    }

    float oacc[8][4];
#pragma unroll
    for (int i = 0; i < 8; i++)
#pragma unroll
        for (int j = 0; j < 4; j++) oacc[i][j] = 0.f;
    float m0 = -1e30f, m1 = -1e30f, l0 = 0.f, l1 = 0.f;

    // fragment address components
    uint32_t k_row = ((lane >> 4) & 1) * 8 + (lane & 7);
    uint32_t k_khb = ((lane >> 3) & 1) * 16;
    uint32_t v_tok = ((lane >> 3) & 1) * 8 + (lane & 7);
    uint32_t v_dcb = ((lane >> 4) & 1) * 16;

    for (int kt = 0; kt < S_; kt += 64) {
        __syncthreads();
#pragma unroll
        for (int i = 0; i < 4; i++) {
            int idx = tid + i * 128;
            int row = idx >> 3, uq = idx & 7;
            *(uint4*)&Ks32[row * 36 + uq * 4] = kp[i];
            *(uint4*)&Vs32[row * 36 + uq * 4] = vp[i];
        }
        __syncthreads();

        // prefetch next K/V tile
        {
            int ktn = (kt + 64 < S_) ? kt + 64 : kt;
#pragma unroll
            for (int i = 0; i < 4; i++) {
                int idx = tid + i * 128;
                int row = idx >> 3, uq = idx & 7;
                size_t base = (size_t)(b * S_ + ktn + row) * D_ + h * 64 + uq * 8;
                kp[i] = *(const uint4*)(Kb + base);
                vp[i] = *(const uint4*)(Vb + base);
            }
        }

        // ---- S = Q @ K^T ----
        float sacc[8][4];
#pragma unroll
        for (int i = 0; i < 8; i++)
#pragma unroll
            for (int j = 0; j < 4; j++) sacc[i][j] = 0.f;
#pragma unroll
        for (int kc = 0; kc < 4; kc++) {
#pragma unroll
            for (int p = 0; p < 4; p++) {
                unsigned kb[4];
                ldsm4(kb, ksb + (k_row + p * 16) * 144 + k_khb + kc * 32);
                mma16(sacc[2 * p],     qf[kc], kb[0], kb[1]);
                mma16(sacc[2 * p + 1], qf[kc], kb[2], kb[3]);
            }
        }
#pragma unroll
        for (int nt = 0; nt < 8; nt++)
#pragma unroll
            for (int j = 0; j < 4; j++) sacc[nt][j] *= 0.125f;

        // ---- online softmax ----
        float mx0 = -1e30f, mx1 = -1e30f;
#pragma unroll
        for (int nt = 0; nt < 8; nt++) {
            mx0 = fmaxf(mx0, fmaxf(sacc[nt][0], sacc[nt][1]));
            mx1 = fmaxf(mx1, fmaxf(sacc[nt][2], sacc[nt][3]));
        }
        mx0 = fmaxf(mx0, __shfl_xor_sync(0xffffffffu, mx0, 1));
        mx0 = fmaxf(mx0, __shfl_xor_sync(0xffffffffu, mx0, 2));
        mx1 = fmaxf(mx1, __shfl_xor_sync(0xffffffffu, mx1, 1));
        mx1 = fmaxf(mx1, __shfl_xor_sync(0xffffffffu, mx1, 2));
        float mn0 = fmaxf(m0, mx0), mn1 = fmaxf(m1, mx1);
        float al0 = __expf(m0 - mn0), al1 = __expf(m1 - mn1);
        float rs0 = 0.f, rs1 = 0.f;
#pragma unroll
        for (int nt = 0; nt < 8; nt++) {
            sacc[nt][0] = __expf(sacc[nt][0] - mn0);
            sacc[nt][1] = __expf(sacc[nt][1] - mn0);
            sacc[nt][2] = __expf(sacc[nt][2] - mn1);
            sacc[nt][3] = __expf(sacc[nt][3] - mn1);
            rs0 += sacc[nt][0] + sacc[nt][1];
            rs1 += sacc[nt][2] + sacc[nt][3];
        }
        rs0 += __shfl_xor_sync(0xffffffffu, rs0, 1);
        rs0 += __shfl_xor_sync(0xffffffffu, rs0, 2);
        rs1 += __shfl_xor_sync(0xffffffffu, rs1, 1);
        rs1 += __shfl_xor_sync(0xffffffffu, rs1, 2);
        l0 = l0 * al0 + rs0;
        l1 = l1 * al1 + rs1;
        m0 = mn0; m1 = mn1;
#pragma unroll
        for (int dt = 0; dt < 8; dt++) {
            oacc[dt][0] *= al0; oacc[dt][1] *= al0;
            oacc[dt][2] *= al1; oacc[dt][3] *= al1;
        }

        // ---- O += P @ V (trans ldmatrix B-frags) ----
#pragma unroll
        for (int kc = 0; kc < 4; kc++) {
            unsigned pf[4];
            pf[0] = packh(sacc[2 * kc][0],     sacc[2 * kc][1]);
            pf[1] = packh(sacc[2 * kc][2],     sacc[2 * kc][3]);
            pf[2] = packh(sacc[2 * kc + 1][0], sacc[2 * kc + 1][1]);
            pf[3] = packh(sacc[2 * kc + 1][2], sacc[2 * kc + 1][3]);
#pragma unroll
            for (int p = 0; p < 4; p++) {
                unsigned vb[4];
                ldsm4t(vb, vsb + (v_tok + kc * 16) * 144 + v_dcb + p * 32);
                mma16(oacc[2 * p],     pf, vb[0], vb[1]);
                mma16(oacc[2 * p + 1], pf, vb[2], vb[3]);
            }
        }
    }

    float il0 = 1.0f / l0, il1 = 1.0f / l1;
    int row = q0 + warp * 16 + g;
#pragma unroll
    for (int dt = 0; dt < 8; dt++) {
        int col = h * 64 + dt * 8 + 2 * t4;
        *(unsigned*)(O + (size_t)(b * S_ + row) * D_ + col) =
            packh(oacc[dt][0] * il0, oacc[dt][1] * il0);
        *(unsigned*)(O + (size_t)(b * S_ + row + 8) * D_ + col) =
            packh(oacc[dt][2] * il1, oacc[dt][3] * il1);
    }
}

// ---------------- Selector ----------------
__global__ __launch_bounds__(128) void selector_kernel(const float* __restrict__ h,
                                                       const float* __restrict__ Wsel) {
    int t = blockIdx.x * 4 + (threadIdx.x >> 5);
    int lane = threadIdx.x & 31;
    float acc[16];
#pragma unroll
    for (int e = 0; e < 16; e++) acc[e] = 0.f;
    const float* hr = h + (size_t)t * D_;
    for (int d = lane; d < D_; d += 32) {
        float hv = hr[d];
        const float4* w = (const float4*)(Wsel + (size_t)d * E_);
        float4 w0 = w[0], w1 = w[1], w2 = w[2], w3 = w[3];
        acc[0]  = fmaf(hv, w0.x, acc[0]);  acc[1]  = fmaf(hv, w0.y, acc[1]);
        acc[2]  = fmaf(hv, w0.z, acc[2]);  acc[3]  = fmaf(hv, w0.w, acc[3]);
        acc[4]  = fmaf(hv, w1.x, acc[4]);  acc[5]  = fmaf(hv, w1.y, acc[5]);
        acc[6]  = fmaf(hv, w1.z, acc[6]);  acc[7]  = fmaf(hv, w1.w, acc[7]);
        acc[8]  = fmaf(hv, w2.x, acc[8]);  acc[9]  = fmaf(hv, w2.y, acc[9]);
        acc[10] = fmaf(hv, w2.z, acc[10]); acc[11] = fmaf(hv, w2.w, acc[11]);
        acc[12] = fmaf(hv, w3.x, acc[12]); acc[13] = fmaf(hv, w3.y, acc[13]);
        acc[14] = fmaf(hv, w3.z, acc[14]); acc[15] = fmaf(hv, w3.w, acc[15]);
    }
#pragma unroll
    for (int e = 0; e < 16; e++)
#pragma unroll
        for (int o = 16; o; o >>= 1) acc[e] += __shfl_xor_sync(0xffffffffu, acc[e], o);
    if (lane == 0) {
        float v1 = -1.f, v2 = -1.f;
        int i1 = 0, i2 = 0;
#pragma unroll
        for (int e = 0; e < 16; e++) {
            float sg = 1.0f / (1.0f + __expf(-acc[e]));
            if (sg > v1) { v2 = v1; i2 = i1; v1 = sg; i1 = e; }
            else if (sg > v2) { v2 = sg; i2 = e; }
        }
        int p1 = atomicAdd(&g_cnt[i1], 1);
        g_elist[i1 * T_ + p1] = t;
        g_egate[i1 * T_ + p1] = v1;
        int p2 = atomicAdd(&g_cnt[i2], 1);
        g_elist[i2 * T_ + p2] = t;
        g_egate[i2 * T_ + p2] = v2;
    }
}

// ---------------- launch ----------------
extern "C" void kernel_launch(void* const* d_in, const int* in_sizes, int n_in,
                              void* d_out, int out_size) {
    (void)in_sizes; (void)n_in; (void)out_size;
    const float* x    = (const float*)d_in[0];
    const float* Wq   = (const float*)d_in[1];
    const float* Wk   = (const float*)d_in[2];
    const float* Wv   = (const float*)d_in[3];
    const float* Wo   = (const float*)d_in[4];
    const float* ln1s = (const float*)d_in[5];
    const float* ln1b = (const float*)d_in[6];
    const float* ln2s = (const float*)d_in[7];
    const float* ln2b = (const float*)d_in[8];
    const float* Wsel = (const float*)d_in[9];
    const float* W1   = (const float*)d_in[10];
    const float* W2   = (const float*)d_in[11];
    float* out = (float*)d_out;

    __half *wqkvT, *woT, *w1h, *w2h, *h1h, *qkvh, *ctxh, *h2h, *uph;
    float *x2p, *h2p;
    cudaGetSymbolAddress((void**)&wqkvT, g_wqkvT);
    cudaGetSymbolAddress((void**)&woT,   g_woT);
    cudaGetSymbolAddress((void**)&w1h,   g_w1h);
    cudaGetSymbolAddress((void**)&w2h,   g_w2h);
    cudaGetSymbolAddress((void**)&h1h,   g_h1h);
    cudaGetSymbolAddress((void**)&qkvh,  g_qkvh);
    cudaGetSymbolAddress((void**)&ctxh,  g_ctxh);
    cudaGetSymbolAddress((void**)&h2h,   g_h2h);
    cudaGetSymbolAddress((void**)&uph,   g_uph);
    cudaGetSymbolAddress((void**)&x2p,   g_x2);
    cudaGetSymbolAddress((void**)&h2p,   g_h2);

    static cudaStream_t s_side = nullptr;
    static cudaEvent_t ev_fork = nullptr, ev_join = nullptr;
    static int attrs_set = 0;
    if (s_side == nullptr) {
        cudaStreamCreateWithFlags(&s_side, cudaStreamNonBlocking);
        cudaEventCreateWithFlags(&ev_fork, cudaEventDisableTiming);
        cudaEventCreateWithFlags(&ev_join, cudaEventDisableTiming);
    }
    if (!attrs_set) {
        cudaFuncSetAttribute(gemm_ld<0>, cudaFuncAttributeMaxDynamicSharedMemorySize, TCSM);
        cudaFuncSetAttribute(gemm_ld<1>, cudaFuncAttributeMaxDynamicSharedMemorySize, TCSM);
        attrs_set = 1;
    }

    const int EDF4 = E_ * D_ * F_ / 4;

    // fork: Wo transpose + MoE weight conversions overlap QKV+attention
    cudaEventRecord(ev_fork, 0);
    cudaStreamWaitEvent(s_side, ev_fork, 0);
    conv_f2h_T<<<dim3(32, 32), 256, 0, s_side>>>(Wo, woT);
    conv_f2h<<<512, 256, 0, s_side>>>((const float4*)W1, (uint2*)(w1h), EDF4);
    conv_f2h<<<512, 256, 0, s_side>>>((const float4*)W2, (uint2*)(w2h), EDF4);
    cudaEventRecord(ev_join, s_side);

    // main path
    conv_f2h_T<<<dim3(32, 32), 256>>>(Wq, wqkvT);
    conv_f2h_T<<<dim3(32, 32), 256>>>(Wk, wqkvT + (size_t)D_ * D_);
    conv_f2h_T<<<dim3(32, 32), 256>>>(Wv, wqkvT + 2 * (size_t)D_ * D_);
    zero_cnt_kernel<<<1, 32>>>();
    ln_h_kernel<<<T_, 256>>>(x, ln1s, ln1b, h1h);

    gemm_ld<0><<<dim3(8, 32, 3), 256, TCSM>>>(
        h1h, wqkvT, nullptr, nullptr, nullptr, qkvh);

    attn_h_kernel<<<dim3(S_ / 64, B_ * H_), 128>>>(
        qkvh, qkvh + (size_t)T_ * D_, qkvh + 2 * (size_t)T_ * D_, ctxh);

    cudaStreamWaitEvent(0, ev_join, 0);

    gemm_ld<1><<<dim3(8, 32, 1), 256, TCSM>>>(
        ctxh, woT, x, x2p, out, nullptr);

    ln_dual_kernel<<<T_, 256>>>(x2p, ln2s, ln2b, h2p, h2h);
    selector_kernel<<<T_ / 4, 128>>>(h2p, Wsel);

    moe_mma<0><<<dim3(F_ / 128, T_ / 128, E_), 256>>>(h2h, w1h, uph, nullptr);
    moe_mma<1><<<dim3(D_ / 128, T_ / 128, E_), 256>>>(uph, w2h, nullptr, out);
}

// round 12
// speedup vs baseline: 7.4160x; 1.0118x over previous
#include <cuda_runtime.h>
#include <cuda_fp16.h>
#include <stdint.h>
#include <cstdint>
#include <math.h>

#define B_  2
#define S_  2048
#define D_  1024
#define H_  16
#define DH_ 64
#define E_  16
#define F_  256
#define T_  (B_*S_)

// ---------------- scratch ----------------
__device__ __half g_wqkvT[(size_t)3*D_*D_];   // transposed [N][K] per matrix
__device__ __half g_woT[(size_t)D_*D_];
__device__ __half g_w1h[(size_t)E_*D_*F_];
__device__ __half g_w2h[(size_t)E_*F_*D_];
__device__ __half g_h1h[(size_t)T_*D_];
__device__ __half g_qkvh[(size_t)3*T_*D_];
__device__ __half g_ctxh[(size_t)T_*D_];
__device__ __half g_h2h[(size_t)T_*D_];
__device__ __half g_uph[(size_t)E_*T_*F_];
__device__ float g_x2[(size_t)T_*D_];
__device__ float g_h2[(size_t)T_*D_];
__device__ int   g_cnt[E_];
__device__ int   g_elist[E_*T_];
__device__ float g_egate[E_*T_];

__global__ void zero_cnt_kernel() {
    if (threadIdx.x < E_) g_cnt[threadIdx.x] = 0;
}

// ---------------- helpers ----------------
__device__ __forceinline__ unsigned packh(float lo, float hi) {
    unsigned u;
    asm("cvt.rn.f16x2.f32 %0, %1, %2;" : "=r"(u) : "f"(hi), "f"(lo));
    return u;
}

__device__ __forceinline__ void mma16(float* d, const unsigned* a, unsigned b0, unsigned b1) {
    asm volatile(
        "mma.sync.aligned.m16n8k16.row.col.f32.f16.f16.f32 "
        "{%0,%1,%2,%3},{%4,%5,%6,%7},{%8,%9},{%0,%1,%2,%3};"
        : "+f"(d[0]), "+f"(d[1]), "+f"(d[2]), "+f"(d[3])
        : "r"(a[0]), "r"(a[1]), "r"(a[2]), "r"(a[3]), "r"(b0), "r"(b1));
}

__device__ __forceinline__ uint32_t smem_u32(const void* p) {
    uint32_t a;
    asm("{ .reg .u64 t; cvta.to.shared.u64 t, %1; cvt.u32.u64 %0, t; }" : "=r"(a) : "l"(p));
    return a;
}

__device__ __forceinline__ void ldsm4(unsigned* r, uint32_t addr) {
    asm volatile("ldmatrix.sync.aligned.m8n8.x4.shared.b16 {%0,%1,%2,%3}, [%4];"
                 : "=r"(r[0]), "=r"(r[1]), "=r"(r[2]), "=r"(r[3]) : "r"(addr));
}

__device__ __forceinline__ void ldsm4t(unsigned* r, uint32_t addr) {
    asm volatile("ldmatrix.sync.aligned.m8n8.x4.trans.shared.b16 {%0,%1,%2,%3}, [%4];"
                 : "=r"(r[0]), "=r"(r[1]), "=r"(r[2]), "=r"(r[3]) : "r"(addr));
}

#define CP_ASYNC16(dst, src) \
    asm volatile("cp.async.cg.shared.global [%0], [%1], 16;" :: "r"(dst), "l"(src))
#define CP_COMMIT() asm volatile("cp.async.commit_group;")
#define CP_WAIT(n)  asm volatile("cp.async.wait_group %0;" :: "n"(n))

// ---------------- fp32 -> fp16 convert ----------------
__global__ __launch_bounds__(256) void conv_f2h(const float4* __restrict__ s,
                                                uint2* __restrict__ d, int n4) {
    int i = blockIdx.x * blockDim.x + threadIdx.x;
    int stride = gridDim.x * blockDim.x;
    for (; i < n4; i += stride) {
        float4 v = s[i];
        uint2 o;
        o.x = packh(v.x, v.y);
        o.y = packh(v.z, v.w);
        d[i] = o;
    }
}

// ---------------- fp32 [1024][1024] -> transposed fp16 [N][K] -------------------
__global__ __launch_bounds__(256) void conv_f2h_T(const float* __restrict__ s,
                                                  __half* __restrict__ d) {
    __shared__ float t[32][33];
    int bx = blockIdx.x * 32;
    int by = blockIdx.y * 32;
    int lx = threadIdx.x & 31, ly = threadIdx.x >> 5;
#pragma unroll
    for (int i = 0; i < 4; i++) {
        int r = ly + i * 8;
        t[r][lx] = s[(size_t)(by + r) * 1024 + bx + lx];
    }
    __syncthreads();
#pragma unroll
    for (int i = 0; i < 4; i++) {
        int r = ly + i * 8;
        d[(size_t)(bx + r) * 1024 + by + lx] = __float2half(t[lx][r]);
    }
}

// ---------------- fused QKV transpose (z selects matrix) -----------------------
__global__ __launch_bounds__(256) void conv_f2h_T3(const float* __restrict__ s0,
                                                   const float* __restrict__ s1,
                                                   const float* __restrict__ s2,
                                                   __half* __restrict__ d) {
    const float* s = (blockIdx.z == 0) ? s0 : ((blockIdx.z == 1) ? s1 : s2);
    __half* dz = d + (size_t)blockIdx.z * 1024 * 1024;
    __shared__ float t[32][33];
    int bx = blockIdx.x * 32;
    int by = blockIdx.y * 32;
    int lx = threadIdx.x & 31, ly = threadIdx.x >> 5;
#pragma unroll
    for (int i = 0; i < 4; i++) {
        int r = ly + i * 8;
        t[r][lx] = s[(size_t)(by + r) * 1024 + bx + lx];
    }
    __syncthreads();
#pragma unroll
    for (int i = 0; i < 4; i++) {
        int r = ly + i * 8;
        dz[(size_t)(bx + r) * 1024 + by + lx] = __float2half(t[lx][r]);
    }
}

// ---------------- LayerNorm (fp16 out) ----------------
__global__ __launch_bounds__(256) void ln_h_kernel(const float* __restrict__ x,
                                                   const float* __restrict__ sc,
                                                   const float* __restrict__ bi,
                                                   __half* __restrict__ o) {
    int t = blockIdx.x;
    const float* xr = x + (size_t)t * D_;
    __half* orow = o + (size_t)t * D_;
    float v[4];
    float s = 0.f, s2 = 0.f;
#pragma unroll
    for (int i = 0; i < 4; i++) {
        v[i] = xr[threadIdx.x + i * 256];
        s  += v[i];
        s2 += v[i] * v[i];
    }
#pragma unroll
    for (int off = 16; off; off >>= 1) {
        s  += __shfl_xor_sync(0xffffffffu, s,  off);
        s2 += __shfl_xor_sync(0xffffffffu, s2, off);
    }
    __shared__ float ws[8], ws2[8];
    int w = threadIdx.x >> 5, ln = threadIdx.x & 31;
    if (ln == 0) { ws[w] = s; ws2[w] = s2; }
    __syncthreads();
    float S = 0.f, S2 = 0.f;
#pragma unroll
    for (int i = 0; i < 8; i++) { S += ws[i]; S2 += ws2[i]; }
    float mu  = S * (1.0f / D_);
    float var = S2 * (1.0f / D_) - mu * mu;
    float inv = rsqrtf(var + 1e-5f);
#pragma unroll
    for (int i = 0; i < 4; i++) {
        int d = threadIdx.x + i * 256;
        orow[d] = __float2half((v[i] - mu) * inv * sc[d] + bi[d]);
    }
}

// ---------------- LayerNorm dual output (fp32 + fp16) ----------------
__global__ __launch_bounds__(256) void ln_dual_kernel(const float* __restrict__ x,
                                                      const float* __restrict__ sc,
                                                      const float* __restrict__ bi,
                                                      float* __restrict__ of,
                                                      __half* __restrict__ oh) {
    int t = blockIdx.x;
    const float* xr = x + (size_t)t * D_;
    float v[4];
    float s = 0.f, s2 = 0.f;
#pragma unroll
    for (int i = 0; i < 4; i++) {
        v[i] = xr[threadIdx.x + i * 256];
        s  += v[i];
        s2 += v[i] * v[i];
    }
#pragma unroll
    for (int off = 16; off; off >>= 1) {
        s  += __shfl_xor_sync(0xffffffffu, s,  off);
        s2 += __shfl_xor_sync(0xffffffffu, s2, off);
    }
    __shared__ float ws[8], ws2[8];
    int w = threadIdx.x >> 5, ln = threadIdx.x & 31;
    if (ln == 0) { ws[w] = s; ws2[w] = s2; }
    __syncthreads();
    float S = 0.f, S2 = 0.f;
#pragma unroll
    for (int i = 0; i < 8; i++) { S += ws[i]; S2 += ws2[i]; }
    float mu  = S * (1.0f / D_);
    float var = S2 * (1.0f / D_) - mu * mu;
    float inv = rsqrtf(var + 1e-5f);
#pragma unroll
    for (int i = 0; i < 4; i++) {
        int d = threadIdx.x + i * 256;
        float r = (v[i] - mu) * inv * sc[d] + bi[d];
        of[(size_t)t * D_ + d] = r;
        oh[(size_t)t * D_ + d] = __float2half(r);
    }
}

// ---------------- GEMM: ldmatrix + cp.async 3-stage pipeline, BK=64 -------------
#define STG_ 36864
#define TCSM (3 * STG_)

template <int MODE>
__global__ __launch_bounds__(256) void gemm_ld(const __half* __restrict__ A,
                                               const __half* __restrict__ Bt,
                                               const float* __restrict__ Res,
                                               float* __restrict__ Cf,
                                               float* __restrict__ C2f,
                                               __half* __restrict__ Cb) {
    extern __shared__ char dsm[];
    uint32_t smb = smem_u32(dsm);

    int tid = threadIdx.x, warp = tid >> 5, lane = tid & 31;
    int g = lane >> 2, t4 = lane & 3;
    int wm = warp >> 1, wn = warp & 1;          // 4x2 warps, warp tile 32x64
    int bx = blockIdx.x * 128, by = blockIdx.y * 128;
    const __half* Bz = Bt + (size_t)blockIdx.z * D_ * D_;

    float acc[2][8][4];
#pragma unroll
    for (int i = 0; i < 2; i++)
#pragma unroll
        for (int j = 0; j < 8; j++)
#pragma unroll
            for (int q = 0; q < 4; q++) acc[i][j][q] = 0.f;

    // loader: 2 threads per row, 64B each
    int lr = tid >> 1;
    int lsh = (tid & 1) * 32;
    int lsb = (tid & 1) * 64;
    const __half* gA = A  + (size_t)(by + lr) * D_ + lsh;
    const __half* gB = Bz + (size_t)(bx + lr) * D_ + lsh;
    uint32_t sA = smb + lr * 144 + lsb;
    uint32_t sB = smb + 18432 + lr * 144 + lsb;

    // prologue: stages 0 and 1
#pragma unroll
    for (int j = 0; j < 4; j++) {
        CP_ASYNC16(sA + j * 16, gA + j * 8);
        CP_ASYNC16(sB + j * 16, gB + j * 8);
    }
    CP_COMMIT();
#pragma unroll
    for (int j = 0; j < 4; j++) {
        CP_ASYNC16(sA + STG_ + j * 16, gA + 64 + j * 8);
        CP_ASYNC16(sB + STG_ + j * 16, gB + 64 + j * 8);
    }
    CP_COMMIT();

    // fragment address components
    uint32_t a_off = (uint32_t)((wm * 32 + (lane & 15)) * 144 + (lane >> 4) * 16);
    uint32_t b_row = (uint32_t)(wn * 64 + ((lane >> 4) & 1) * 8 + (lane & 7));
    uint32_t b_khb = ((lane >> 3) & 1) * 16;

    for (int i = 0; i < 16; i++) {
        int s = i % 3;
        if (i + 2 < 16) {
            int s2 = (i + 2) % 3;
            int k0 = (i + 2) * 64;
#pragma unroll
            for (int j = 0; j < 4; j++) {
                CP_ASYNC16(sA + s2 * STG_ + j * 16, gA + k0 + j * 8);
                CP_ASYNC16(sB + s2 * STG_ + j * 16, gB + k0 + j * 8);
            }
            CP_COMMIT();
        }
        if (i < 14)      { CP_WAIT(2); }
        else if (i == 14){ CP_WAIT(1); }
        else             { CP_WAIT(0); }
        __syncthreads();

        uint32_t ab = smb + s * STG_;
        uint32_t bb = ab + 18432;
#pragma unroll
        for (int kc = 0; kc < 4; kc++) {
            unsigned afr0[4], afr1[4];
            ldsm4(afr0, ab + a_off + kc * 32);
            ldsm4(afr1, ab + a_off + 16 * 144 + kc * 32);
#pragma unroll
            for (int p = 0; p < 4; p++) {
                unsigned bfr[4];
                ldsm4(bfr, bb + (b_row + p * 16) * 144 + b_khb + kc * 32);
                mma16(acc[0][2 * p],     afr0, bfr[0], bfr[1]);
                mma16(acc[0][2 * p + 1], afr0, bfr[2], bfr[3]);
                mma16(acc[1][2 * p],     afr1, bfr[0], bfr[1]);
                mma16(acc[1][2 * p + 1], afr1, bfr[2], bfr[3]);
            }
        }
        __syncthreads();
    }

    if (MODE == 0) {
        __half* Cz = Cb + (size_t)blockIdx.z * T_ * D_;
#pragma unroll
        for (int mt = 0; mt < 2; mt++) {
#pragma unroll
            for (int nt = 0; nt < 8; nt++) {
                int col = bx + wn * 64 + nt * 8 + 2 * t4;
                size_t r0 = (size_t)(by + wm * 32 + mt * 16 + g);
                *(unsigned*)(Cz + r0 * D_ + col)       = packh(acc[mt][nt][0], acc[mt][nt][1]);
                *(unsigned*)(Cz + (r0 + 8) * D_ + col) = packh(acc[mt][nt][2], acc[mt][nt][3]);
            }
        }
    } else {
#pragma unroll
        for (int mt = 0; mt < 2; mt++) {
#pragma unroll
            for (int nt = 0; nt < 8; nt++) {
                int col = bx + wn * 64 + nt * 8 + 2 * t4;
                size_t r0 = (size_t)(by + wm * 32 + mt * 16 + g);
                size_t r1 = r0 + 8;
                float2 v01 = {acc[mt][nt][0], acc[mt][nt][1]};
                float2 v23 = {acc[mt][nt][2], acc[mt][nt][3]};
                float2 q0 = *(const float2*)(Res + r0 * D_ + col);
                float2 q1 = *(const float2*)(Res + r1 * D_ + col);
                v01.x += q0.x; v01.y += q0.y;
                v23.x += q1.x; v23.y += q1.y;
                *(float2*)(Cf + r0 * D_ + col) = v01;
                *(float2*)(Cf + r1 * D_ + col) = v23;
                *(float2*)(C2f + r0 * D_ + col) = v01;
                *(float2*)(C2f + r1 * D_ + col) = v23;
            }
        }
    }
}

// ---------------- MoE fp16 mma.sync GEMM (unchanged) ----------------------------
template <int MODE>
__global__ __launch_bounds__(256) void moe_mma(const __half* __restrict__ Ab,
                                               const __half* __restrict__ Wb,
                                               __half* __restrict__ Uph,
                                               float* __restrict__ out) {
    int e = blockIdx.z;
    int n = g_cnt[e];
    int rb = blockIdx.y * 128;
    if (rb >= n) return;
    const int N = (MODE == 0) ? F_ : D_;
    const int K = (MODE == 0) ? D_ : F_;
    const __half* Wz = Wb + (size_t)e * K * N;

    __shared__ unsigned As32[128 * 20];
    __shared__ unsigned Bs32[16 * 132];
    __shared__ int rows[128];

    int tid = threadIdx.x, warp = tid >> 5, lane = tid & 31;
    int g = lane >> 2, t4 = lane & 3;
    int wm = warp >> 1, wn = warp & 1;
    int bx = blockIdx.x * 128;

    if (MODE == 0) {
        if (tid < 128) {
            int rg = rb + tid;
            rows[tid] = (rg < n) ? g_elist[e * T_ + rg] : 0;
        }
        __syncthreads();
    }

    float acc[2][8][4];
#pragma unroll
    for (int i = 0; i < 2; i++)
#pragma unroll
        for (int j = 0; j < 8; j++)
#pragma unroll
            for (int q = 0; q < 4; q++) acc[i][j][q] = 0.f;

    int ar = tid >> 1, ah = tid & 1;
    int bk2 = tid >> 4, bc8 = (tid & 15) * 8;

    const __half* Arow;
    if (MODE == 0)
        Arow = Ab + (size_t)rows[ar] * D_ + ah * 16;
    else
        Arow = Ab + ((size_t)e * T_ + rb + ar) * F_ + ah * 16;

    uint4 a0, a1, w0, w1;
    {
        const uint4* ap = (const uint4*)(Arow);
        a0 = ap[0]; a1 = ap[1];
        w0 = *(const uint4*)(Wz + (size_t)(2 * bk2) * N + bx + bc8);
        w1 = *(const uint4*)(Wz + (size_t)(2 * bk2 + 1) * N + bx + bc8);
    }

    for (int k0 = 0; k0 < K; k0 += 32) {
        __syncthreads();
        *(uint4*)&As32[ar * 20 + ah * 8]     = a0;
        *(uint4*)&As32[ar * 20 + ah * 8 + 4] = a1;
        {
            uint4 o03, o47;
            o03.x = __byte_perm(w0.x, w1.x, 0x5410);
            o03.y = __byte_perm(w0.x, w1.x, 0x7632);
            o03.z = __byte_perm(w0.y, w1.y, 0x5410);
            o03.w = __byte_perm(w0.y, w1.y, 0x7632);
            o47.x = __byte_perm(w0.z, w1.z, 0x5410);
            o47.y = __byte_perm(w0.z, w1.z, 0x7632);
            o47.z = __byte_perm(w0.w, w1.w, 0x5410);
            o47.w = __byte_perm(w0.w, w1.w, 0x7632);
            *(uint4*)&Bs32[bk2 * 132 + bc8]     = o03;
            *(uint4*)&Bs32[bk2 * 132 + bc8 + 4] = o47;
        }
        __syncthreads();

        {
            int kn = (k0 + 32 < K) ? k0 + 32 : k0;
            const uint4* ap = (const uint4*)(Arow + kn);
            a0 = ap[0]; a1 = ap[1];
            w0 = *(const uint4*)(Wz + (size_t)(kn + 2 * bk2) * N + bx + bc8);
            w1 = *(const uint4*)(Wz + (size_t)(kn + 2 * bk2 + 1) * N + bx + bc8);
        }

#pragma unroll
        for (int kc = 0; kc < 2; kc++) {
            unsigned afr[2][4];
#pragma unroll
            for (int mt = 0; mt < 2; mt++) {
                int r0 = wm * 32 + mt * 16;
                afr[mt][0] = As32[(r0 + g) * 20 + kc * 8 + t4];
                afr[mt][1] = As32[(r0 + g + 8) * 20 + kc * 8 + t4];
                afr[mt][2] = As32[(r0 + g) * 20 + kc * 8 + t4 + 4];
                afr[mt][3] = As32[(r0 + g + 8) * 20 + kc * 8 + t4 + 4];
            }
#pragma unroll
            for (int nt = 0; nt < 8; nt++) {
                int c0 = wn * 64 + nt * 8 + g;
                unsigned bb0 = Bs32[(kc * 8 + t4) * 132 + c0];
                unsigned bb1 = Bs32[(kc * 8 + t4 + 4) * 132 + c0];
                mma16(acc[0][nt], afr[0], bb0, bb1);
                mma16(acc[1][nt], afr[1], bb0, bb1);
            }
        }
    }

    if (MODE == 0) {
#pragma unroll
        for (int mt = 0; mt < 2; mt++) {
            int rg0 = rb + wm * 32 + mt * 16 + g;
            int rg1 = rg0 + 8;
            float gt0 = (rg0 < n) ? g_egate[e * T_ + rg0] : 0.f;
            float gt1 = (rg1 < n) ? g_egate[e * T_ + rg1] : 0.f;
#pragma unroll
            for (int nt = 0; nt < 8; nt++) {
                int col = bx + wn * 64 + nt * 8 + 2 * t4;
                if (rg0 < n)
                    *(unsigned*)(Uph + ((size_t)e * T_ + rg0) * F_ + col) =
                        packh(fmaxf(acc[mt][nt][0], 0.f) * gt0,
                              fmaxf(acc[mt][nt][1], 0.f) * gt0);
                if (rg1 < n)
                    *(unsigned*)(Uph + ((size_t)e * T_ + rg1) * F_ + col) =
                        packh(fmaxf(acc[mt][nt][2], 0.f) * gt1,
                              fmaxf(acc[mt][nt][3], 0.f) * gt1);
            }
        }
    } else {
#pragma unroll
        for (int mt = 0; mt < 2; mt++) {
            int rg0 = rb + wm * 32 + mt * 16 + g;
            int rg1 = rg0 + 8;
            int t0 = (rg0 < n) ? g_elist[e * T_ + rg0] : -1;
            int t1 = (rg1 < n) ? g_elist[e * T_ + rg1] : -1;
#pragma unroll
            for (int nt = 0; nt < 8; nt++) {
                int col = bx + wn * 64 + nt * 8 + 2 * t4;
                if (t0 >= 0) {
                    atomicAdd(out + (size_t)t0 * D_ + col,     acc[mt][nt][0]);
                    atomicAdd(out + (size_t)t0 * D_ + col + 1, acc[mt][nt][1]);
                }
                if (t1 >= 0) {
                    atomicAdd(out + (size_t)t1 * D_ + col,     acc[mt][nt][2]);
                    atomicAdd(out + (size_t)t1 * D_ + col + 1, acc[mt][nt][3]);
                }
            }
        }
    }
}

// ---------------- fp16 flash attention: 128-q tile, 8 warps ---------------------
// KVs: rows 0-63 = K tile (also Q rows 0-63 at start), rows 64-127 = V tile
// (Q rows 64-127 at start). Row stride 144 B.
__global__ __launch_bounds__(256) void attn_h_kernel(const __half* __restrict__ Q,
                                                     const __half* __restrict__ Kb,
                                                     const __half* __restrict__ Vb,
                                                     __half* __restrict__ O) {
    __shared__ unsigned KVs[128 * 36];

    int bh = blockIdx.y;
    int b = bh >> 4, h = bh & 15;
    int q0 = blockIdx.x * 128;
    int tid = threadIdx.x, warp = tid >> 5, lane = tid & 31;
    int g = lane >> 2, t4 = lane & 3;

    uint32_t ksb = smem_u32(KVs);
    uint32_t vsb = ksb + 64 * 144;

    // ---- stage Q tile (128 rows) into KVs, read fragments into registers ----
#pragma unroll
    for (int i = 0; i < 4; i++) {
        int idx = tid + i * 256;
        int row = idx >> 3, uq = idx & 7;
        *(uint4*)&KVs[row * 36 + uq * 4] =
            *(const uint4*)(Q + (size_t)(b * S_ + q0 + row) * D_ + h * 64 + uq * 8);
    }
    __syncthreads();
    unsigned qf[4][4];
    {
        uint32_t qa = ksb + (warp * 16 + (lane & 15)) * 144 + (lane >> 4) * 16;
#pragma unroll
        for (int kc = 0; kc < 4; kc++) ldsm4(qf[kc], qa + kc * 32);
    }

    // ---- prefetch K/V tile 0 into registers ----
    uint4 kp[2], vp[2];
#pragma unroll
    for (int i = 0; i < 2; i++) {
        int idx = tid + i * 256;
        int row = idx >> 3, uq = idx & 7;
        size_t base = (size_t)(b * S_ + row) * D_ + h * 64 + uq * 8;
        kp[i] = *(const uint4*)(Kb + base);
        vp[i] = *(const uint4*)(Vb + base);
    }

    float oacc[8][4];
#pragma unroll
    for (int i = 0; i < 8; i++)
#pragma unroll
        for (int j = 0; j < 4; j++) oacc[i][j] = 0.f;
    float m0 = -1e30f, m1 = -1e30f, l0 = 0.f, l1 = 0.f;

    // fragment address components
    uint32_t k_row = ((lane >> 4) & 1) * 8 + (lane & 7);
    uint32_t k_khb = ((lane >> 3) & 1) * 16;
    uint32_t v_tok = ((lane >> 3) & 1) * 8 + (lane & 7);
    uint32_t v_dcb = ((lane >> 4) & 1) * 16;

    for (int kt = 0; kt < S_; kt += 64) {
        __syncthreads();
#pragma unroll
        for (int i = 0; i < 2; i++) {
            int idx = tid + i * 256;
            int row = idx >> 3, uq = idx & 7;
            *(uint4*)&KVs[row * 36 + uq * 4]        = kp[i];
            *(uint4*)&KVs[(64 + row) * 36 + uq * 4] = vp[i];
        }
        __syncthreads();

        // prefetch next K/V tile
        {
            int ktn = (kt + 64 < S_) ? kt + 64 : kt;
#pragma unroll
            for (int i = 0; i < 2; i++) {
                int idx = tid + i * 256;
                int row = idx >> 3, uq = idx & 7;
                size_t base = (size_t)(b * S_ + ktn + row) * D_ + h * 64 + uq * 8;
                kp[i] = *(const uint4*)(Kb + base);
                vp[i] = *(const uint4*)(Vb + base);
            }
        }

        // ---- S = Q @ K^T ----
        float sacc[8][4];
#pragma unroll
        for (int i = 0; i < 8; i++)
#pragma unroll
            for (int j = 0; j < 4; j++) sacc[i][j] = 0.f;
#pragma unroll
        for (int kc = 0; kc < 4; kc++) {
#pragma unroll
            for (int p = 0; p < 4; p++) {
                unsigned kb[4];
                ldsm4(kb, ksb + (k_row + p * 16) * 144 + k_khb + kc * 32);
                mma16(sacc[2 * p],     qf[kc], kb[0], kb[1]);
                mma16(sacc[2 * p + 1], qf[kc], kb[2], kb[3]);
            }
        }
#pragma unroll
        for (int nt = 0; nt < 8; nt++)
#pragma unroll
            for (int j = 0; j < 4; j++) sacc[nt][j] *= 0.125f;

        // ---- online softmax ----
        float mx0 = -1e30f, mx1 = -1e30f;
#pragma unroll
        for (int nt = 0; nt < 8; nt++) {
            mx0 = fmaxf(mx0, fmaxf(sacc[nt][0], sacc[nt][1]));
            mx1 = fmaxf(mx1, fmaxf(sacc[nt][2], sacc[nt][3]));
        }
        mx0 = fmaxf(mx0, __shfl_xor_sync(0xffffffffu, mx0, 1));
        mx0 = fmaxf(mx0, __shfl_xor_sync(0xffffffffu, mx0, 2));
        mx1 = fmaxf(mx1, __shfl_xor_sync(0xffffffffu, mx1, 1));
        mx1 = fmaxf(mx1, __shfl_xor_sync(0xffffffffu, mx1, 2));
        float mn0 = fmaxf(m0, mx0), mn1 = fmaxf(m1, mx1);
        float al0 = __expf(m0 - mn0), al1 = __expf(m1 - mn1);
        float rs0 = 0.f, rs1 = 0.f;
#pragma unroll
        for (int nt = 0; nt < 8; nt++) {
            sacc[nt][0] = __expf(sacc[nt][0] - mn0);
            sacc[nt][1] = __expf(sacc[nt][1] - mn0);
            sacc[nt][2] = __expf(sacc[nt][2] - mn1);
            sacc[nt][3] = __expf(sacc[nt][3] - mn1);
            rs0 += sacc[nt][0] + sacc[nt][1];
            rs1 += sacc[nt][2] + sacc[nt][3];
        }
        rs0 += __shfl_xor_sync(0xffffffffu, rs0, 1);
        rs0 += __shfl_xor_sync(0xffffffffu, rs0, 2);
        rs1 += __shfl_xor_sync(0xffffffffu, rs1, 1);
        rs1 += __shfl_xor_sync(0xffffffffu, rs1, 2);
        l0 = l0 * al0 + rs0;
        l1 = l1 * al1 + rs1;
        m0 = mn0; m1 = mn1;
#pragma unroll
        for (int dt = 0; dt < 8; dt++) {
            oacc[dt][0] *= al0; oacc[dt][1] *= al0;
            oacc[dt][2] *= al1; oacc[dt][3] *= al1;
        }

        // ---- O += P @ V (trans ldmatrix B-frags) ----
#pragma unroll
        for (int kc = 0; kc < 4; kc++) {
            unsigned pf[4];
            pf[0] = packh(sacc[2 * kc][0],     sacc[2 * kc][1]);
            pf[1] = packh(sacc[2 * kc][2],     sacc[2 * kc][3]);
            pf[2] = packh(sacc[2 * kc + 1][0], sacc[2 * kc + 1][1]);
            pf[3] = packh(sacc[2 * kc + 1][2], sacc[2 * kc + 1][3]);
#pragma unroll
            for (int p = 0; p < 4; p++) {
                unsigned vb[4];
                ldsm4t(vb, vsb + (v_tok + kc * 16) * 144 + v_dcb + p * 32);
                mma16(oacc[2 * p],     pf, vb[0], vb[1]);
                mma16(oacc[2 * p + 1], pf, vb[2], vb[3]);
            }
        }
    }

    float il0 = 1.0f / l0, il1 = 1.0f / l1;
    int row = q0 + warp * 16 + g;
#pragma unroll
    for (int dt = 0; dt < 8; dt++) {
        int col = h * 64 + dt * 8 + 2 * t4;
        *(unsigned*)(O + (size_t)(b * S_ + row) * D_ + col) =
            packh(oacc[dt][0] * il0, oacc[dt][1] * il0);
        *(unsigned*)(O + (size_t)(b * S_ + row + 8) * D_ + col) =
            packh(oacc[dt][2] * il1, oacc[dt][3] * il1);
    }
}

// ---------------- Selector ----------------
__global__ __launch_bounds__(128) void selector_kernel(const float* __restrict__ h,
                                                       const float* __restrict__ Wsel) {
    int t = blockIdx.x * 4 + (threadIdx.x >> 5);
    int lane = threadIdx.x & 31;
    float acc[16];
#pragma unroll
    for (int e = 0; e < 16; e++) acc[e] = 0.f;
    const float* hr = h + (size_t)t * D_;
    for (int d = lane; d < D_; d += 32) {
        float hv = hr[d];
        const float4* w = (const float4*)(Wsel + (size_t)d * E_);
        float4 w0 = w[0], w1 = w[1], w2 = w[2], w3 = w[3];
        acc[0]  = fmaf(hv, w0.x, acc[0]);  acc[1]  = fmaf(hv, w0.y, acc[1]);
        acc[2]  = fmaf(hv, w0.z, acc[2]);  acc[3]  = fmaf(hv, w0.w, acc[3]);
        acc[4]  = fmaf(hv, w1.x, acc[4]);  acc[5]  = fmaf(hv, w1.y, acc[5]);
        acc[6]  = fmaf(hv, w1.z, acc[6]);  acc[7]  = fmaf(hv, w1.w, acc[7]);
        acc[8]  = fmaf(hv, w2.x, acc[8]);  acc[9]  = fmaf(hv, w2.y, acc[9]);
        acc[10] = fmaf(hv, w2.z, acc[10]); acc[11] = fmaf(hv, w2.w, acc[11]);
        acc[12] = fmaf(hv, w3.x, acc[12]); acc[13] = fmaf(hv, w3.y, acc[13]);
        acc[14] = fmaf(hv, w3.z, acc[14]); acc[15] = fmaf(hv, w3.w, acc[15]);
    }
#pragma unroll
    for (int e = 0; e < 16; e++)
#pragma unroll
        for (int o = 16; o; o >>= 1) acc[e] += __shfl_xor_sync(0xffffffffu, acc[e], o);
    if (lane == 0) {
        float v1 = -1.f, v2 = -1.f;
        int i1 = 0, i2 = 0;
#pragma unroll
        for (int e = 0; e < 16; e++) {
            float sg = 1.0f / (1.0f + __expf(-acc[e]));
            if (sg > v1) { v2 = v1; i2 = i1; v1 = sg; i1 = e; }
            else if (sg > v2) { v2 = sg; i2 = e; }
        }
        int p1 = atomicAdd(&g_cnt[i1], 1);
        g_elist[i1 * T_ + p1] = t;
        g_egate[i1 * T_ + p1] = v1;
        int p2 = atomicAdd(&g_cnt[i2], 1);
        g_elist[i2 * T_ + p2] = t;
        g_egate[i2 * T_ + p2] = v2;
    }
}

// ---------------- launch ----------------
extern "C" void kernel_launch(void* const* d_in, const int* in_sizes, int n_in,
                              void* d_out, int out_size) {
    (void)in_sizes; (void)n_in; (void)out_size;
    const float* x    = (const float*)d_in[0];
    const float* Wq   = (const float*)d_in[1];
    const float* Wk   = (const float*)d_in[2];
    const float* Wv   = (const float*)d_in[3];
    const float* Wo   = (const float*)d_in[4];
    const float* ln1s = (const float*)d_in[5];
    const float* ln1b = (const float*)d_in[6];
    const float* ln2s = (const float*)d_in[7];
    const float* ln2b = (const float*)d_in[8];
    const float* Wsel = (const float*)d_in[9];
    const float* W1   = (const float*)d_in[10];
    const float* W2   = (const float*)d_in[11];
    float* out = (float*)d_out;

    __half *wqkvT, *woT, *w1h, *w2h, *h1h, *qkvh, *ctxh, *h2h, *uph;
    float *x2p, *h2p;
    cudaGetSymbolAddress((void**)&wqkvT, g_wqkvT);
    cudaGetSymbolAddress((void**)&woT,   g_woT);
    cudaGetSymbolAddress((void**)&w1h,   g_w1h);
    cudaGetSymbolAddress((void**)&w2h,   g_w2h);
    cudaGetSymbolAddress((void**)&h1h,   g_h1h);
    cudaGetSymbolAddress((void**)&qkvh,  g_qkvh);
    cudaGetSymbolAddress((void**)&ctxh,  g_ctxh);
    cudaGetSymbolAddress((void**)&h2h,   g_h2h);
    cudaGetSymbolAddress((void**)&uph,   g_uph);
    cudaGetSymbolAddress((void**)&x2p,   g_x2);
    cudaGetSymbolAddress((void**)&h2p,   g_h2);

    static cudaStream_t s_side = nullptr;
    static cudaEvent_t ev_fork = nullptr, ev_join = nullptr;
    static int attrs_set = 0;
    if (s_side == nullptr) {
        cudaStreamCreateWithFlags(&s_side, cudaStreamNonBlocking);
        cudaEventCreateWithFlags(&ev_fork, cudaEventDisableTiming);
        cudaEventCreateWithFlags(&ev_join, cudaEventDisableTiming);
    }
    if (!attrs_set) {
        cudaFuncSetAttribute(gemm_ld<0>, cudaFuncAttributeMaxDynamicSharedMemorySize, TCSM);
        cudaFuncSetAttribute(gemm_ld<1>, cudaFuncAttributeMaxDynamicSharedMemorySize, TCSM);
        attrs_set = 1;
    }

    const int EDF4 = E_ * D_ * F_ / 4;

    // fork: Wo transpose + MoE weight conversions overlap QKV+attention
    cudaEventRecord(ev_fork, 0);
    cudaStreamWaitEvent(s_side, ev_fork, 0);
    conv_f2h_T<<<dim3(32, 32), 256, 0, s_side>>>(Wo, woT);
    conv_f2h<<<512, 256, 0, s_side>>>((const float4*)W1, (uint2*)(w1h), EDF4);
    conv_f2h<<<512, 256, 0, s_side>>>((const float4*)W2, (uint2*)(w2h), EDF4);
    cudaEventRecord(ev_join, s_side);

    // main path
    conv_f2h_T3<<<dim3(32, 32, 3), 256>>>(Wq, Wk, Wv, wqkvT);
    zero_cnt_kernel<<<1, 32>>>();
    ln_h_kernel<<<T_, 256>>>(x, ln1s, ln1b, h1h);

    gemm_ld<0><<<dim3(8, 32, 3), 256, TCSM>>>(
        h1h, wqkvT, nullptr, nullptr, nullptr, qkvh);

    attn_h_kernel<<<dim3(S_ / 128, B_ * H_), 256>>>(
        qkvh, qkvh + (size_t)T_ * D_, qkvh + 2 * (size_t)T_ * D_, ctxh);

    cudaStreamWaitEvent(0, ev_join, 0);

    gemm_ld<1><<<dim3(8, 32, 1), 256, TCSM>>>(
        ctxh, woT, x, x2p, out, nullptr);

    ln_dual_kernel<<<T_, 256>>>(x2p, ln2s, ln2b, h2p, h2h);
    selector_kernel<<<T_ / 4, 128>>>(h2p, Wsel);

    moe_mma<0><<<dim3(F_ / 128, T_ / 128, E_), 256>>>(h2h, w1h, uph, nullptr);
    moe_mma<1><<<dim3(D_ / 128, T_ / 128, E_), 256>>>(uph, w2h, nullptr, out);
}

// round 13
// speedup vs baseline: 7.4185x; 1.0003x over previous
#include <cuda_runtime.h>
#include <cuda_fp16.h>
#include <stdint.h>
#include <cstdint>
#include <math.h>

#define B_  2
#define S_  2048
#define D_  1024
#define H_  16
#define DH_ 64
#define E_  16
#define F_  256
#define T_  (B_*S_)

// ---------------- scratch ----------------
__device__ __half g_wqkvT[(size_t)3*D_*D_];   // transposed [N][K] per matrix
__device__ __half g_woT[(size_t)D_*D_];
__device__ __half g_w1T[(size_t)E_*F_*D_];    // per-expert [F][D]
__device__ __half g_w2T[(size_t)E_*D_*F_];    // per-expert [D][F]
__device__ __half g_h1h[(size_t)T_*D_];
__device__ __half g_qkvh[(size_t)3*T_*D_];
__device__ __half g_ctxh[(size_t)T_*D_];
__device__ __half g_h2h[(size_t)T_*D_];
__device__ __half g_uph[(size_t)E_*T_*F_];
__device__ float g_x2[(size_t)T_*D_];
__device__ float g_h2[(size_t)T_*D_];
__device__ int   g_cnt[E_];
__device__ int   g_elist[E_*T_];
__device__ float g_egate[E_*T_];

__global__ void zero_cnt_kernel() {
    if (threadIdx.x < E_) g_cnt[threadIdx.x] = 0;
}

// ---------------- helpers ----------------
__device__ __forceinline__ unsigned packh(float lo, float hi) {
    unsigned u;
    asm("cvt.rn.f16x2.f32 %0, %1, %2;" : "=r"(u) : "f"(hi), "f"(lo));
    return u;
}

__device__ __forceinline__ void mma16(float* d, const unsigned* a, unsigned b0, unsigned b1) {
    asm volatile(
        "mma.sync.aligned.m16n8k16.row.col.f32.f16.f16.f32 "
        "{%0,%1,%2,%3},{%4,%5,%6,%7},{%8,%9},{%0,%1,%2,%3};"
        : "+f"(d[0]), "+f"(d[1]), "+f"(d[2]), "+f"(d[3])
        : "r"(a[0]), "r"(a[1]), "r"(a[2]), "r"(a[3]), "r"(b0), "r"(b1));
}

__device__ __forceinline__ uint32_t smem_u32(const void* p) {
    uint32_t a;
    asm("{ .reg .u64 t; cvta.to.shared.u64 t, %1; cvt.u32.u64 %0, t; }" : "=r"(a) : "l"(p));
    return a;
}

__device__ __forceinline__ void ldsm4(unsigned* r, uint32_t addr) {
    asm volatile("ldmatrix.sync.aligned.m8n8.x4.shared.b16 {%0,%1,%2,%3}, [%4];"
                 : "=r"(r[0]), "=r"(r[1]), "=r"(r[2]), "=r"(r[3]) : "r"(addr));
}

__device__ __forceinline__ void ldsm4t(unsigned* r, uint32_t addr) {
    asm volatile("ldmatrix.sync.aligned.m8n8.x4.trans.shared.b16 {%0,%1,%2,%3}, [%4];"
                 : "=r"(r[0]), "=r"(r[1]), "=r"(r[2]), "=r"(r[3]) : "r"(addr));
}

#define CP_ASYNC16(dst, src) \
    asm volatile("cp.async.cg.shared.global [%0], [%1], 16;" :: "r"(dst), "l"(src))
#define CP_COMMIT() asm volatile("cp.async.commit_group;")
#define CP_WAIT(n)  asm volatile("cp.async.wait_group %0;" :: "n"(n))

// ---------------- fp32 [1024][1024] -> transposed fp16 [N][K] -------------------
__global__ __launch_bounds__(256) void conv_f2h_T(const float* __restrict__ s,
                                                  __half* __restrict__ d) {
    __shared__ float t[32][33];
    int bx = blockIdx.x * 32;
    int by = blockIdx.y * 32;
    int lx = threadIdx.x & 31, ly = threadIdx.x >> 5;
#pragma unroll
    for (int i = 0; i < 4; i++) {
        int r = ly + i * 8;
        t[r][lx] = s[(size_t)(by + r) * 1024 + bx + lx];
    }
    __syncthreads();
#pragma unroll
    for (int i = 0; i < 4; i++) {
        int r = ly + i * 8;
        d[(size_t)(bx + r) * 1024 + by + lx] = __float2half(t[lx][r]);
    }
}

// ---------------- fused QKV transpose (z selects matrix) -----------------------
__global__ __launch_bounds__(256) void conv_f2h_T3(const float* __restrict__ s0,
                                                   const float* __restrict__ s1,
                                                   const float* __restrict__ s2,
                                                   __half* __restrict__ d) {
    const float* s = (blockIdx.z == 0) ? s0 : ((blockIdx.z == 1) ? s1 : s2);
    __half* dz = d + (size_t)blockIdx.z * 1024 * 1024;
    __shared__ float t[32][33];
    int bx = blockIdx.x * 32;
    int by = blockIdx.y * 32;
    int lx = threadIdx.x & 31, ly = threadIdx.x >> 5;
#pragma unroll
    for (int i = 0; i < 4; i++) {
        int r = ly + i * 8;
        t[r][lx] = s[(size_t)(by + r) * 1024 + bx + lx];
    }
    __syncthreads();
#pragma unroll
    for (int i = 0; i < 4; i++) {
        int r = ly + i * 8;
        dz[(size_t)(bx + r) * 1024 + by + lx] = __float2half(t[lx][r]);
    }
}

// ---------------- per-expert fp32 [R][C] -> fp16 [C][R] ------------------------
__global__ __launch_bounds__(256) void conv_TE(const float* __restrict__ s,
                                               __half* __restrict__ d,
                                               int R, int C) {
    const float* se = s + (size_t)blockIdx.z * R * C;
    __half* de = d + (size_t)blockIdx.z * R * C;
    __shared__ float t[32][33];
    int bx = blockIdx.x * 32;   // col
    int by = blockIdx.y * 32;   // row
    int lx = threadIdx.x & 31, ly = threadIdx.x >> 5;
#pragma unroll
    for (int i = 0; i < 4; i++) {
        int r = ly + i * 8;
        t[r][lx] = se[(size_t)(by + r) * C + bx + lx];
    }
    __syncthreads();
#pragma unroll
    for (int i = 0; i < 4; i++) {
        int r = ly + i * 8;
        de[(size_t)(bx + r) * R + by + lx] = __float2half(t[lx][r]);
    }
}

// ---------------- LayerNorm (fp16 out) ----------------
__global__ __launch_bounds__(256) void ln_h_kernel(const float* __restrict__ x,
                                                   const float* __restrict__ sc,
                                                   const float* __restrict__ bi,
                                                   __half* __restrict__ o) {
    int t = blockIdx.x;
    const float* xr = x + (size_t)t * D_;
    __half* orow = o + (size_t)t * D_;
    float v[4];
    float s = 0.f, s2 = 0.f;
#pragma unroll
    for (int i = 0; i < 4; i++) {
        v[i] = xr[threadIdx.x + i * 256];
        s  += v[i];
        s2 += v[i] * v[i];
    }
#pragma unroll
    for (int off = 16; off; off >>= 1) {
        s  += __shfl_xor_sync(0xffffffffu, s,  off);
        s2 += __shfl_xor_sync(0xffffffffu, s2, off);
    }
    __shared__ float ws[8], ws2[8];
    int w = threadIdx.x >> 5, ln = threadIdx.x & 31;
    if (ln == 0) { ws[w] = s; ws2[w] = s2; }
    __syncthreads();
    float S = 0.f, S2 = 0.f;
#pragma unroll
    for (int i = 0; i < 8; i++) { S += ws[i]; S2 += ws2[i]; }
    float mu  = S * (1.0f / D_);
    float var = S2 * (1.0f / D_) - mu * mu;
    float inv = rsqrtf(var + 1e-5f);
#pragma unroll
    for (int i = 0; i < 4; i++) {
        int d = threadIdx.x + i * 256;
        orow[d] = __float2half((v[i] - mu) * inv * sc[d] + bi[d]);
    }
}

// ---------------- LayerNorm dual output (fp32 + fp16) ----------------
__global__ __launch_bounds__(256) void ln_dual_kernel(const float* __restrict__ x,
                                                      const float* __restrict__ sc,
                                                      const float* __restrict__ bi,
                                                      float* __restrict__ of,
                                                      __half* __restrict__ oh) {
    int t = blockIdx.x;
    const float* xr = x + (size_t)t * D_;
    float v[4];
    float s = 0.f, s2 = 0.f;
#pragma unroll
    for (int i = 0; i < 4; i++) {
        v[i] = xr[threadIdx.x + i * 256];
        s  += v[i];
        s2 += v[i] * v[i];
    }
#pragma unroll
    for (int off = 16; off; off >>= 1) {
        s  += __shfl_xor_sync(0xffffffffu, s,  off);
        s2 += __shfl_xor_sync(0xffffffffu, s2, off);
    }
    __shared__ float ws[8], ws2[8];
    int w = threadIdx.x >> 5, ln = threadIdx.x & 31;
    if (ln == 0) { ws[w] = s; ws2[w] = s2; }
    __syncthreads();
    float S = 0.f, S2 = 0.f;
#pragma unroll
    for (int i = 0; i < 8; i++) { S += ws[i]; S2 += ws2[i]; }
    float mu  = S * (1.0f / D_);
    float var = S2 * (1.0f / D_) - mu * mu;
    float inv = rsqrtf(var + 1e-5f);
#pragma unroll
    for (int i = 0; i < 4; i++) {
        int d = threadIdx.x + i * 256;
        float r = (v[i] - mu) * inv * sc[d] + bi[d];
        of[(size_t)t * D_ + d] = r;
        oh[(size_t)t * D_ + d] = __float2half(r);
    }
}

// ---------------- GEMM: ldmatrix + cp.async 3-stage, single-sync loop -----------
#define STG_ 36864
#define TCSM (3 * STG_)

template <int MODE>
__global__ __launch_bounds__(256) void gemm_ld(const __half* __restrict__ A,
                                               const __half* __restrict__ Bt,
                                               const float* __restrict__ Res,
                                               float* __restrict__ Cf,
                                               float* __restrict__ C2f,
                                               __half* __restrict__ Cb) {
    extern __shared__ char dsm[];
    uint32_t smb = smem_u32(dsm);

    int tid = threadIdx.x, warp = tid >> 5, lane = tid & 31;
    int g = lane >> 2, t4 = lane & 3;
    int wm = warp >> 1, wn = warp & 1;
    int bx = blockIdx.x * 128, by = blockIdx.y * 128;
    const __half* Bz = Bt + (size_t)blockIdx.z * D_ * D_;

    float acc[2][8][4];
#pragma unroll
    for (int i = 0; i < 2; i++)
#pragma unroll
        for (int j = 0; j < 8; j++)
#pragma unroll
            for (int q = 0; q < 4; q++) acc[i][j][q] = 0.f;

    int lr = tid >> 1;
    int lsh = (tid & 1) * 32;
    int lsb = (tid & 1) * 64;
    const __half* gA = A  + (size_t)(by + lr) * D_ + lsh;
    const __half* gB = Bz + (size_t)(bx + lr) * D_ + lsh;
    uint32_t sA = smb + lr * 144 + lsb;
    uint32_t sB = smb + 18432 + lr * 144 + lsb;

#pragma unroll
    for (int j = 0; j < 4; j++) {
        CP_ASYNC16(sA + j * 16, gA + j * 8);
        CP_ASYNC16(sB + j * 16, gB + j * 8);
    }
    CP_COMMIT();
#pragma unroll
    for (int j = 0; j < 4; j++) {
        CP_ASYNC16(sA + STG_ + j * 16, gA + 64 + j * 8);
        CP_ASYNC16(sB + STG_ + j * 16, gB + 64 + j * 8);
    }
    CP_COMMIT();

    uint32_t a_off = (uint32_t)((wm * 32 + (lane & 15)) * 144 + (lane >> 4) * 16);
    uint32_t b_row = (uint32_t)(wn * 64 + ((lane >> 4) & 1) * 8 + (lane & 7));
    uint32_t b_khb = ((lane >> 3) & 1) * 16;

    for (int i = 0; i < 16; i++) {
        int s = i % 3;
        if (i < 15) { CP_WAIT(1); } else { CP_WAIT(0); }
        __syncthreads();
        if (i + 2 < 16) {
            int s2 = (i + 2) % 3;
            int k0 = (i + 2) * 64;
#pragma unroll
            for (int j = 0; j < 4; j++) {
                CP_ASYNC16(sA + s2 * STG_ + j * 16, gA + k0 + j * 8);
                CP_ASYNC16(sB + s2 * STG_ + j * 16, gB + k0 + j * 8);
            }
            CP_COMMIT();
        }

        uint32_t ab = smb + s * STG_;
        uint32_t bb = ab + 18432;
#pragma unroll
        for (int kc = 0; kc < 4; kc++) {
            unsigned afr0[4], afr1[4];
            ldsm4(afr0, ab + a_off + kc * 32);
            ldsm4(afr1, ab + a_off + 16 * 144 + kc * 32);
#pragma unroll
            for (int p = 0; p < 4; p++) {
                unsigned bfr[4];
                ldsm4(bfr, bb + (b_row + p * 16) * 144 + b_khb + kc * 32);
                mma16(acc[0][2 * p],     afr0, bfr[0], bfr[1]);
                mma16(acc[0][2 * p + 1], afr0, bfr[2], bfr[3]);
                mma16(acc[1][2 * p],     afr1, bfr[0], bfr[1]);
                mma16(acc[1][2 * p + 1], afr1, bfr[2], bfr[3]);
            }
        }
    }

    if (MODE == 0) {
        __half* Cz = Cb + (size_t)blockIdx.z * T_ * D_;
#pragma unroll
        for (int mt = 0; mt < 2; mt++) {
#pragma unroll
            for (int nt = 0; nt < 8; nt++) {
                int col = bx + wn * 64 + nt * 8 + 2 * t4;
                size_t r0 = (size_t)(by + wm * 32 + mt * 16 + g);
                *(unsigned*)(Cz + r0 * D_ + col)       = packh(acc[mt][nt][0], acc[mt][nt][1]);
                *(unsigned*)(Cz + (r0 + 8) * D_ + col) = packh(acc[mt][nt][2], acc[mt][nt][3]);
            }
        }
    } else {
#pragma unroll
        for (int mt = 0; mt < 2; mt++) {
#pragma unroll
            for (int nt = 0; nt < 8; nt++) {
                int col = bx + wn * 64 + nt * 8 + 2 * t4;
                size_t r0 = (size_t)(by + wm * 32 + mt * 16 + g);
                size_t r1 = r0 + 8;
                float2 v01 = {acc[mt][nt][0], acc[mt][nt][1]};
                float2 v23 = {acc[mt][nt][2], acc[mt][nt][3]};
                float2 q0 = *(const float2*)(Res + r0 * D_ + col);
                float2 q1 = *(const float2*)(Res + r1 * D_ + col);
                v01.x += q0.x; v01.y += q0.y;
                v23.x += q1.x; v23.y += q1.y;
                *(float2*)(Cf + r0 * D_ + col) = v01;
                *(float2*)(Cf + r1 * D_ + col) = v23;
                *(float2*)(C2f + r0 * D_ + col) = v01;
                *(float2*)(C2f + r1 * D_ + col) = v23;
            }
        }
    }
}

// ---------------- MoE GEMM: ldmatrix + cp.async, gather/scatter -----------------
// MODE 0 (up):   A = h2h rows via elist, Bt = w1T[e] [F][D]; N=256, K=1024.
// MODE 1 (down): A = uph dense, Bt = w2T[e] [D][F]; N=1024, K=256.
template <int MODE>
__global__ __launch_bounds__(256) void moe_ld(const __half* __restrict__ Ab,
                                              const __half* __restrict__ Wt,
                                              __half* __restrict__ Uph,
                                              float* __restrict__ out) {
    const int Nn = (MODE == 0) ? F_ : D_;
    const int Kk = (MODE == 0) ? D_ : F_;
    const int NT = Kk / 64;
    int e = blockIdx.z;
    int n = g_cnt[e];
    int rb = blockIdx.y * 128;
    if (rb >= n) return;

    extern __shared__ char dsm[];
    uint32_t smb = smem_u32(dsm);

    int tid = threadIdx.x, warp = tid >> 5, lane = tid & 31;
    int g = lane >> 2, t4 = lane & 3;
    int wm = warp >> 1, wn = warp & 1;
    int bx = blockIdx.x * 128;
    const __half* Wz = Wt + (size_t)e * Kk * Nn;

    float acc[2][8][4];
#pragma unroll
    for (int i = 0; i < 2; i++)
#pragma unroll
        for (int j = 0; j < 8; j++)
#pragma unroll
            for (int q = 0; q < 4; q++) acc[i][j][q] = 0.f;

    int lr = tid >> 1;
    int lsh = (tid & 1) * 32;
    int lsb = (tid & 1) * 64;
    const __half* gA;
    if (MODE == 0) {
        int rg = rb + lr;
        int row = (rg < n) ? g_elist[e * T_ + rg] : 0;
        gA = Ab + (size_t)row * D_ + lsh;
    } else {
        gA = Ab + ((size_t)e * T_ + rb + lr) * F_ + lsh;
    }
    const __half* gB = Wz + (size_t)(bx + lr) * Kk + lsh;
    uint32_t sA = smb + lr * 144 + lsb;
    uint32_t sB = smb + 18432 + lr * 144 + lsb;

#pragma unroll
    for (int j = 0; j < 4; j++) {
        CP_ASYNC16(sA + j * 16, gA + j * 8);
        CP_ASYNC16(sB + j * 16, gB + j * 8);
    }
    CP_COMMIT();
#pragma unroll
    for (int j = 0; j < 4; j++) {
        CP_ASYNC16(sA + STG_ + j * 16, gA + 64 + j * 8);
        CP_ASYNC16(sB + STG_ + j * 16, gB + 64 + j * 8);
    }
    CP_COMMIT();

    uint32_t a_off = (uint32_t)((wm * 32 + (lane & 15)) * 144 + (lane >> 4) * 16);
    uint32_t b_row = (uint32_t)(wn * 64 + ((lane >> 4) & 1) * 8 + (lane & 7));
    uint32_t b_khb = ((lane >> 3) & 1) * 16;

    for (int i = 0; i < NT; i++) {
        int s = i % 3;
        if (i < NT - 1) { CP_WAIT(1); } else { CP_WAIT(0); }
        __syncthreads();
        if (i + 2 < NT) {
            int s2 = (i + 2) % 3;
            int k0 = (i + 2) * 64;
#pragma unroll
            for (int j = 0; j < 4; j++) {
                CP_ASYNC16(sA + s2 * STG_ + j * 16, gA + k0 + j * 8);
                CP_ASYNC16(sB + s2 * STG_ + j * 16, gB + k0 + j * 8);
            }
            CP_COMMIT();
        }

        uint32_t ab = smb + s * STG_;
        uint32_t bb = ab + 18432;
#pragma unroll
        for (int kc = 0; kc < 4; kc++) {
            unsigned afr0[4], afr1[4];
            ldsm4(afr0, ab + a_off + kc * 32);
            ldsm4(afr1, ab + a_off + 16 * 144 + kc * 32);
#pragma unroll
            for (int p = 0; p < 4; p++) {
                unsigned bfr[4];
                ldsm4(bfr, bb + (b_row + p * 16) * 144 + b_khb + kc * 32);
                mma16(acc[0][2 * p],     afr0, bfr[0], bfr[1]);
                mma16(acc[0][2 * p + 1], afr0, bfr[2], bfr[3]);
                mma16(acc[1][2 * p],     afr1, bfr[0], bfr[1]);
                mma16(acc[1][2 * p + 1], afr1, bfr[2], bfr[3]);
            }
        }
    }

    if (MODE == 0) {
#pragma unroll
        for (int mt = 0; mt < 2; mt++) {
            int rg0 = rb + wm * 32 + mt * 16 + g;
            int rg1 = rg0 + 8;
            float gt0 = (rg0 < n) ? g_egate[e * T_ + rg0] : 0.f;
            float gt1 = (rg1 < n) ? g_egate[e * T_ + rg1] : 0.f;
#pragma unroll
            for (int nt = 0; nt < 8; nt++) {
                int col = bx + wn * 64 + nt * 8 + 2 * t4;
                if (rg0 < n)
                    *(unsigned*)(Uph + ((size_t)e * T_ + rg0) * F_ + col) =
                        packh(fmaxf(acc[mt][nt][0], 0.f) * gt0,
                              fmaxf(acc[mt][nt][1], 0.f) * gt0);
                if (rg1 < n)
                    *(unsigned*)(Uph + ((size_t)e * T_ + rg1) * F_ + col) =
                        packh(fmaxf(acc[mt][nt][2], 0.f) * gt1,
                              fmaxf(acc[mt][nt][3], 0.f) * gt1);
            }
        }
    } else {
#pragma unroll
        for (int mt = 0; mt < 2; mt++) {
            int rg0 = rb + wm * 32 + mt * 16 + g;
            int rg1 = rg0 + 8;
            int t0 = (rg0 < n) ? g_elist[e * T_ + rg0] : -1;
            int t1 = (rg1 < n) ? g_elist[e * T_ + rg1] : -1;
#pragma unroll
            for (int nt = 0; nt < 8; nt++) {
                int col = bx + wn * 64 + nt * 8 + 2 * t4;
                if (t0 >= 0) {
                    atomicAdd(out + (size_t)t0 * D_ + col,     acc[mt][nt][0]);
                    atomicAdd(out + (size_t)t0 * D_ + col + 1, acc[mt][nt][1]);
                }
                if (t1 >= 0) {
                    atomicAdd(out + (size_t)t1 * D_ + col,     acc[mt][nt][2]);
                    atomicAdd(out + (size_t)t1 * D_ + col + 1, acc[mt][nt][3]);
                }
            }
        }
    }
}

// ---------------- fp16 flash attention: 128-q tile, double-buffered KV ----------
__global__ __launch_bounds__(256) void attn_h_kernel(const __half* __restrict__ Q,
                                                     const __half* __restrict__ Kb,
                                                     const __half* __restrict__ Vb,
                                                     __half* __restrict__ O) {
    __shared__ unsigned KVs[2 * 128 * 36];

    int bh = blockIdx.y;
    int b = bh >> 4, h = bh & 15;
    int q0 = blockIdx.x * 128;
    int tid = threadIdx.x, warp = tid >> 5, lane = tid & 31;
    int g = lane >> 2, t4 = lane & 3;

    uint32_t ksb = smem_u32(KVs);

    // ---- stage Q tile (128 rows) into buffer 0, read fragments ----
#pragma unroll
    for (int i = 0; i < 4; i++) {
        int idx = tid + i * 256;
        int row = idx >> 3, uq = idx & 7;
        *(uint4*)&KVs[row * 36 + uq * 4] =
            *(const uint4*)(Q + (size_t)(b * S_ + q0 + row) * D_ + h * 64 + uq * 8);
    }
    __syncthreads();
    unsigned qf[4][4];
    {
        uint32_t qa = ksb + (warp * 16 + (lane & 15)) * 144 + (lane >> 4) * 16;
#pragma unroll
        for (int kc = 0; kc < 4; kc++) ldsm4(qf[kc], qa + kc * 32);
    }
    __syncthreads();   // qf reads complete before buffer 0 is overwritten

    // ---- prefetch K/V tile 0 into registers ----
    uint4 kp[2], vp[2];
#pragma unroll
    for (int i = 0; i < 2; i++) {
        int idx = tid + i * 256;
        int row = idx >> 3, uq = idx & 7;
        size_t base = (size_t)(b * S_ + row) * D_ + h * 64 + uq * 8;
        kp[i] = *(const uint4*)(Kb + base);
        vp[i] = *(const uint4*)(Vb + base);
    }

    float oacc[8][4];
#pragma unroll
    for (int i = 0; i < 8; i++)
#pragma unroll
        for (int j = 0; j < 4; j++) oacc[i][j] = 0.f;
    float m0 = -1e30f, m1 = -1e30f, l0 = 0.f, l1 = 0.f;

    uint32_t k_row = ((lane >> 4) & 1) * 8 + (lane & 7);
    uint32_t k_khb = ((lane >> 3) & 1) * 16;
    uint32_t v_tok = ((lane >> 3) & 1) * 8 + (lane & 7);
    uint32_t v_dcb = ((lane >> 4) & 1) * 16;

    for (int kt = 0; kt < S_; kt += 64) {
        int buf = (kt >> 6) & 1;
        // store prefetched K/V into this buffer
#pragma unroll
        for (int i = 0; i < 2; i++) {
            int idx = tid + i * 256;
            int row = idx >> 3, uq = idx & 7;
            *(uint4*)&KVs[buf * 4608 + row * 36 + uq * 4]        = kp[i];
            *(uint4*)&KVs[buf * 4608 + (64 + row) * 36 + uq * 4] = vp[i];
        }
        __syncthreads();

        // prefetch next tile
        {
            int ktn = (kt + 64 < S_) ? kt + 64 : kt;
#pragma unroll
            for (int i = 0; i < 2; i++) {
                int idx = tid + i * 256;
                int row = idx >> 3, uq = idx & 7;
                size_t base = (size_t)(b * S_ + ktn + row) * D_ + h * 64 + uq * 8;
                kp[i] = *(const uint4*)(Kb + base);
                vp[i] = *(const uint4*)(Vb + base);
            }
        }

        uint32_t kbase = ksb + buf * 18432;
        uint32_t vbase = kbase + 64 * 144;

        // ---- S = Q @ K^T ----
        float sacc[8][4];
#pragma unroll
        for (int i = 0; i < 8; i++)
#pragma unroll
            for (int j = 0; j < 4; j++) sacc[i][j] = 0.f;
#pragma unroll
        for (int kc = 0; kc < 4; kc++) {
#pragma unroll
            for (int p = 0; p < 4; p++) {
                unsigned kb[4];
                ldsm4(kb, kbase + (k_row + p * 16) * 144 + k_khb + kc * 32);
                mma16(sacc[2 * p],     qf[kc], kb[0], kb[1]);
                mma16(sacc[2 * p + 1], qf[kc], kb[2], kb[3]);
            }
        }
#pragma unroll
        for (int nt = 0; nt < 8; nt++)
#pragma unroll
            for (int j = 0; j < 4; j++) sacc[nt][j] *= 0.125f;

        // ---- online softmax ----
        float mx0 = -1e30f, mx1 = -1e30f;
#pragma unroll
        for (int nt = 0; nt < 8; nt++) {
            mx0 = fmaxf(mx0, fmaxf(sacc[nt][0], sacc[nt][1]));
            mx1 = fmaxf(mx1, fmaxf(sacc[nt][2], sacc[nt][3]));
        }
        mx0 = fmaxf(mx0, __shfl_xor_sync(0xffffffffu, mx0, 1));
        mx0 = fmaxf(mx0, __shfl_xor_sync(0xffffffffu, mx0, 2));
        mx1 = fmaxf(mx1, __shfl_xor_sync(0xffffffffu, mx1, 1));
        mx1 = fmaxf(mx1, __shfl_xor_sync(0xffffffffu, mx1, 2));
        float mn0 = fmaxf(m0, mx0), mn1 = fmaxf(m1, mx1);
        float al0 = __expf(m0 - mn0), al1 = __expf(m1 - mn1);
        float rs0 = 0.f, rs1 = 0.f;
#pragma unroll
        for (int nt = 0; nt < 8; nt++) {
            sacc[nt][0] = __expf(sacc[nt][0] - mn0);
            sacc[nt][1] = __expf(sacc[nt][1] - mn0);
            sacc[nt][2] = __expf(sacc[nt][2] - mn1);
            sacc[nt][3] = __expf(sacc[nt][3] - mn1);
            rs0 += sacc[nt][0] + sacc[nt][1];
            rs1 += sacc[nt][2] + sacc[nt][3];
        }
        rs0 += __shfl_xor_sync(0xffffffffu, rs0, 1);
        rs0 += __shfl_xor_sync(0xffffffffu, rs0, 2);
        rs1 += __shfl_xor_sync(0xffffffffu, rs1, 1);
        rs1 += __shfl_xor_sync(0xffffffffu, rs1, 2);
        l0 = l0 * al0 + rs0;
        l1 = l1 * al1 + rs1;
        m0 = mn0; m1 = mn1;
#pragma unroll
        for (int dt = 0; dt < 8; dt++) {
            oacc[dt][0] *= al0; oacc[dt][1] *= al0;
            oacc[dt][2] *= al1; oacc[dt][3] *= al1;
        }

        // ---- O += P @ V ----
#pragma unroll
        for (int kc = 0; kc < 4; kc++) {
            unsigned pf[4];
            pf[0] = packh(sacc[2 * kc][0],     sacc[2 * kc][1]);
            pf[1] = packh(sacc[2 * kc][2],     sacc[2 * kc][3]);
            pf[2] = packh(sacc[2 * kc + 1][0], sacc[2 * kc + 1][1]);
            pf[3] = packh(sacc[2 * kc + 1][2], sacc[2 * kc + 1][3]);
#pragma unroll
            for (int p = 0; p < 4; p++) {
                unsigned vb[4];
                ldsm4t(vb, vbase + (v_tok + kc * 16) * 144 + v_dcb + p * 32);
                mma16(oacc[2 * p],     pf, vb[0], vb[1]);
                mma16(oacc[2 * p + 1], pf, vb[2], vb[3]);
            }
        }
    }

    float il0 = 1.0f / l0, il1 = 1.0f / l1;
    int row = q0 + warp * 16 + g;
#pragma unroll
    for (int dt = 0; dt < 8; dt++) {
        int col = h * 64 + dt * 8 + 2 * t4;
        *(unsigned*)(O + (size_t)(b * S_ + row) * D_ + col) =
            packh(oacc[dt][0] * il0, oacc[dt][1] * il0);
        *(unsigned*)(O + (size_t)(b * S_ + row + 8) * D_ + col) =
            packh(oacc[dt][2] * il1, oacc[dt][3] * il1);
    }
}

// ---------------- Selector ----------------
__global__ __launch_bounds__(128) void selector_kernel(const float* __restrict__ h,
                                                       const float* __restrict__ Wsel) {
    int t = blockIdx.x * 4 + (threadIdx.x >> 5);
    int lane = threadIdx.x & 31;
    float acc[16];
#pragma unroll
    for (int e = 0; e < 16; e++) acc[e] = 0.f;
    const float* hr = h + (size_t)t * D_;
    for (int d = lane; d < D_; d += 32) {
        float hv = hr[d];
        const float4* w = (const float4*)(Wsel + (size_t)d * E_);
        float4 w0 = w[0], w1 = w[1], w2 = w[2], w3 = w[3];
        acc[0]  = fmaf(hv, w0.x, acc[0]);  acc[1]  = fmaf(hv, w0.y, acc[1]);
        acc[2]  = fmaf(hv, w0.z, acc[2]);  acc[3]  = fmaf(hv, w0.w, acc[3]);
        acc[4]  = fmaf(hv, w1.x, acc[4]);  acc[5]  = fmaf(hv, w1.y, acc[5]);
        acc[6]  = fmaf(hv, w1.z, acc[6]);  acc[7]  = fmaf(hv, w1.w, acc[7]);
        acc[8]  = fmaf(hv, w2.x, acc[8]);  acc[9]  = fmaf(hv, w2.y, acc[9]);
        acc[10] = fmaf(hv, w2.z, acc[10]); acc[11] = fmaf(hv, w2.w, acc[11]);
        acc[12] = fmaf(hv, w3.x, acc[12]); acc[13] = fmaf(hv, w3.y, acc[13]);
        acc[14] = fmaf(hv, w3.z, acc[14]); acc[15] = fmaf(hv, w3.w, acc[15]);
    }
#pragma unroll
    for (int e = 0; e < 16; e++)
#pragma unroll
        for (int o = 16; o; o >>= 1) acc[e] += __shfl_xor_sync(0xffffffffu, acc[e], o);
    if (lane == 0) {
        float v1 = -1.f, v2 = -1.f;
        int i1 = 0, i2 = 0;
#pragma unroll
        for (int e = 0; e < 16; e++) {
            float sg = 1.0f / (1.0f + __expf(-acc[e]));
            if (sg > v1) { v2 = v1; i2 = i1; v1 = sg; i1 = e; }
            else if (sg > v2) { v2 = sg; i2 = e; }
        }
        int p1 = atomicAdd(&g_cnt[i1], 1);
        g_elist[i1 * T_ + p1] = t;
        g_egate[i1 * T_ + p1] = v1;
        int p2 = atomicAdd(&g_cnt[i2], 1);
        g_elist[i2 * T_ + p2] = t;
        g_egate[i2 * T_ + p2] = v2;
    }
}

// ---------------- launch ----------------
extern "C" void kernel_launch(void* const* d_in, const int* in_sizes, int n_in,
                              void* d_out, int out_size) {
    (void)in_sizes; (void)n_in; (void)out_size;
    const float* x    = (const float*)d_in[0];
    const float* Wq   = (const float*)d_in[1];
    const float* Wk   = (const float*)d_in[2];
    const float* Wv   = (const float*)d_in[3];
    const float* Wo   = (const float*)d_in[4];
    const float* ln1s = (const float*)d_in[5];
    const float* ln1b = (const float*)d_in[6];
    const float* ln2s = (const float*)d_in[7];
    const float* ln2b = (const float*)d_in[8];
    const float* Wsel = (const float*)d_in[9];
    const float* W1   = (const float*)d_in[10];
    const float* W2   = (const float*)d_in[11];
    float* out = (float*)d_out;

    __half *wqkvT, *woT, *w1T, *w2T, *h1h, *qkvh, *ctxh, *h2h, *uph;
    float *x2p, *h2p;
    cudaGetSymbolAddress((void**)&wqkvT, g_wqkvT);
    cudaGetSymbolAddress((void**)&woT,   g_woT);
    cudaGetSymbolAddress((void**)&w1T,   g_w1T);
    cudaGetSymbolAddress((void**)&w2T,   g_w2T);
    cudaGetSymbolAddress((void**)&h1h,   g_h1h);
    cudaGetSymbolAddress((void**)&qkvh,  g_qkvh);
    cudaGetSymbolAddress((void**)&ctxh,  g_ctxh);
    cudaGetSymbolAddress((void**)&h2h,   g_h2h);
    cudaGetSymbolAddress((void**)&uph,   g_uph);
    cudaGetSymbolAddress((void**)&x2p,   g_x2);
    cudaGetSymbolAddress((void**)&h2p,   g_h2);

    static cudaStream_t s_side = nullptr;
    static cudaEvent_t ev_fork = nullptr, ev_join = nullptr;
    static int attrs_set = 0;
    if (s_side == nullptr) {
        cudaStreamCreateWithFlags(&s_side, cudaStreamNonBlocking);
        cudaEventCreateWithFlags(&ev_fork, cudaEventDisableTiming);
        cudaEventCreateWithFlags(&ev_join, cudaEventDisableTiming);
    }
    if (!attrs_set) {
        cudaFuncSetAttribute(gemm_ld<0>, cudaFuncAttributeMaxDynamicSharedMemorySize, TCSM);
        cudaFuncSetAttribute(gemm_ld<1>, cudaFuncAttributeMaxDynamicSharedMemorySize, TCSM);
        cudaFuncSetAttribute(moe_ld<0>, cudaFuncAttributeMaxDynamicSharedMemorySize, TCSM);
        cudaFuncSetAttribute(moe_ld<1>, cudaFuncAttributeMaxDynamicSharedMemorySize, TCSM);
        attrs_set = 1;
    }

    // fork: Wo transpose + per-expert MoE weight transposes overlap QKV+attention
    cudaEventRecord(ev_fork, 0);
    cudaStreamWaitEvent(s_side, ev_fork, 0);
    conv_f2h_T<<<dim3(32, 32), 256, 0, s_side>>>(Wo, woT);
    conv_TE<<<dim3(8, 32, E_), 256, 0, s_side>>>(W1, w1T, 1024, 256);
    conv_TE<<<dim3(32, 8, E_), 256, 0, s_side>>>(W2, w2T, 256, 1024);
    cudaEventRecord(ev_join, s_side);

    // main path
    conv_f2h_T3<<<dim3(32, 32, 3), 256>>>(Wq, Wk, Wv, wqkvT);
    zero_cnt_kernel<<<1, 32>>>();
    ln_h_kernel<<<T_, 256>>>(x, ln1s, ln1b, h1h);

    gemm_ld<0><<<dim3(8, 32, 3), 256, TCSM>>>(
        h1h, wqkvT, nullptr, nullptr, nullptr, qkvh);

    attn_h_kernel<<<dim3(S_ / 128, B_ * H_), 256>>>(
        qkvh, qkvh + (size_t)T_ * D_, qkvh + 2 * (size_t)T_ * D_, ctxh);

    cudaStreamWaitEvent(0, ev_join, 0);

    gemm_ld<1><<<dim3(8, 32, 1), 256, TCSM>>>(
        ctxh, woT, x, x2p, out, nullptr);

    ln_dual_kernel<<<T_, 256>>>(x2p, ln2s, ln2b, h2p, h2h);
    selector_kernel<<<T_ / 4, 128>>>(h2p, Wsel);

    moe_ld<0><<<dim3(F_ / 128, T_ / 128, E_), 256, TCSM>>>(h2h, w1T, uph, nullptr);
    moe_ld<1><<<dim3(D_ / 128, T_ / 128, E_), 256, TCSM>>>(uph, w2T, nullptr, out);
}

// round 14
// speedup vs baseline: 7.6403x; 1.0299x over previous
#include <cuda_runtime.h>
#include <cuda_fp16.h>
#include <stdint.h>
#include <cstdint>
#include <math.h>

#define B_  2
#define S_  2048
#define D_  1024
#define H_  16
#define DH_ 64
#define E_  16
#define F_  256
#define T_  (B_*S_)

// ---------------- scratch ----------------
__device__ __half g_wqkvT[(size_t)3*D_*D_];   // transposed [N][K] per matrix
__device__ __half g_woT[(size_t)D_*D_];
__device__ __half g_w1T[(size_t)E_*F_*D_];    // per-expert [F][D]
__device__ __half g_w2T[(size_t)E_*D_*F_];    // per-expert [D][F]
__device__ __half g_h1h[(size_t)T_*D_];
__device__ __half g_qkvh[(size_t)3*T_*D_];
__device__ __half g_ctxh[(size_t)T_*D_];
__device__ __half g_h2h[(size_t)T_*D_];
__device__ __half g_uph[(size_t)E_*T_*F_];
__device__ float g_h2[(size_t)T_*D_];
__device__ int   g_cnt[E_];
__device__ int   g_elist[E_*T_];
__device__ float g_egate[E_*T_];

__global__ void zero_cnt_kernel() {
    if (threadIdx.x < E_) g_cnt[threadIdx.x] = 0;
}

// ---------------- helpers ----------------
__device__ __forceinline__ unsigned packh(float lo, float hi) {
    unsigned u;
    asm("cvt.rn.f16x2.f32 %0, %1, %2;" : "=r"(u) : "f"(hi), "f"(lo));
    return u;
}

__device__ __forceinline__ void mma16(float* d, const unsigned* a, unsigned b0, unsigned b1) {
    asm volatile(
        "mma.sync.aligned.m16n8k16.row.col.f32.f16.f16.f32 "
        "{%0,%1,%2,%3},{%4,%5,%6,%7},{%8,%9},{%0,%1,%2,%3};"
        : "+f"(d[0]), "+f"(d[1]), "+f"(d[2]), "+f"(d[3])
        : "r"(a[0]), "r"(a[1]), "r"(a[2]), "r"(a[3]), "r"(b0), "r"(b1));
}

__device__ __forceinline__ uint32_t smem_u32(const void* p) {
    uint32_t a;
    asm("{ .reg .u64 t; cvta.to.shared.u64 t, %1; cvt.u32.u64 %0, t; }" : "=r"(a) : "l"(p));
    return a;
}

__device__ __forceinline__ void ldsm4(unsigned* r, uint32_t addr) {
    asm volatile("ldmatrix.sync.aligned.m8n8.x4.shared.b16 {%0,%1,%2,%3}, [%4];"
                 : "=r"(r[0]), "=r"(r[1]), "=r"(r[2]), "=r"(r[3]) : "r"(addr));
}

__device__ __forceinline__ void ldsm4t(unsigned* r, uint32_t addr) {
    asm volatile("ldmatrix.sync.aligned.m8n8.x4.trans.shared.b16 {%0,%1,%2,%3}, [%4];"
                 : "=r"(r[0]), "=r"(r[1]), "=r"(r[2]), "=r"(r[3]) : "r"(addr));
}

#define CP_ASYNC16(dst, src) \
    asm volatile("cp.async.cg.shared.global [%0], [%1], 16;" :: "r"(dst), "l"(src))
#define CP_COMMIT() asm volatile("cp.async.commit_group;")
#define CP_WAIT(n)  asm volatile("cp.async.wait_group %0;" :: "n"(n))

// ---------------- fp32 [1024][1024] -> transposed fp16 [N][K] -------------------
__global__ __launch_bounds__(256) void conv_f2h_T(const float* __restrict__ s,
                                                  __half* __restrict__ d) {
    __shared__ float t[32][33];
    int bx = blockIdx.x * 32;
    int by = blockIdx.y * 32;
    int lx = threadIdx.x & 31, ly = threadIdx.x >> 5;
#pragma unroll
    for (int i = 0; i < 4; i++) {
        int r = ly + i * 8;
        t[r][lx] = s[(size_t)(by + r) * 1024 + bx + lx];
    }
    __syncthreads();
#pragma unroll
    for (int i = 0; i < 4; i++) {
        int r = ly + i * 8;
        d[(size_t)(bx + r) * 1024 + by + lx] = __float2half(t[lx][r]);
    }
}

// ---------------- fused QKV transpose (z selects matrix) -----------------------
__global__ __launch_bounds__(256) void conv_f2h_T3(const float* __restrict__ s0,
                                                   const float* __restrict__ s1,
                                                   const float* __restrict__ s2,
                                                   __half* __restrict__ d) {
    const float* s = (blockIdx.z == 0) ? s0 : ((blockIdx.z == 1) ? s1 : s2);
    __half* dz = d + (size_t)blockIdx.z * 1024 * 1024;
    __shared__ float t[32][33];
    int bx = blockIdx.x * 32;
    int by = blockIdx.y * 32;
    int lx = threadIdx.x & 31, ly = threadIdx.x >> 5;
#pragma unroll
    for (int i = 0; i < 4; i++) {
        int r = ly + i * 8;
        t[r][lx] = s[(size_t)(by + r) * 1024 + bx + lx];
    }
    __syncthreads();
#pragma unroll
    for (int i = 0; i < 4; i++) {
        int r = ly + i * 8;
        dz[(size_t)(bx + r) * 1024 + by + lx] = __float2half(t[lx][r]);
    }
}

// ---------------- per-expert fp32 [R][C] -> fp16 [C][R] ------------------------
__global__ __launch_bounds__(256) void conv_TE(const float* __restrict__ s,
                                               __half* __restrict__ d,
                                               int R, int C) {
    const float* se = s + (size_t)blockIdx.z * R * C;
    __half* de = d + (size_t)blockIdx.z * R * C;
    __shared__ float t[32][33];
    int bx = blockIdx.x * 32;
    int by = blockIdx.y * 32;
    int lx = threadIdx.x & 31, ly = threadIdx.x >> 5;
#pragma unroll
    for (int i = 0; i < 4; i++) {
        int r = ly + i * 8;
        t[r][lx] = se[(size_t)(by + r) * C + bx + lx];
    }
    __syncthreads();
#pragma unroll
    for (int i = 0; i < 4; i++) {
        int r = ly + i * 8;
        de[(size_t)(bx + r) * R + by + lx] = __float2half(t[lx][r]);
    }
}

// ---------------- LayerNorm (fp16 out) ----------------
__global__ __launch_bounds__(256) void ln_h_kernel(const float* __restrict__ x,
                                                   const float* __restrict__ sc,
                                                   const float* __restrict__ bi,
                                                   __half* __restrict__ o) {
    int t = blockIdx.x;
    const float* xr = x + (size_t)t * D_;
    __half* orow = o + (size_t)t * D_;
    float v[4];
    float s = 0.f, s2 = 0.f;
#pragma unroll
    for (int i = 0; i < 4; i++) {
        v[i] = xr[threadIdx.x + i * 256];
        s  += v[i];
        s2 += v[i] * v[i];
    }
#pragma unroll
    for (int off = 16; off; off >>= 1) {
        s  += __shfl_xor_sync(0xffffffffu, s,  off);
        s2 += __shfl_xor_sync(0xffffffffu, s2, off);
    }
    __shared__ float ws[8], ws2[8];
    int w = threadIdx.x >> 5, ln = threadIdx.x & 31;
    if (ln == 0) { ws[w] = s; ws2[w] = s2; }
    __syncthreads();
    float S = 0.f, S2 = 0.f;
#pragma unroll
    for (int i = 0; i < 8; i++) { S += ws[i]; S2 += ws2[i]; }
    float mu  = S * (1.0f / D_);
    float var = S2 * (1.0f / D_) - mu * mu;
    float inv = rsqrtf(var + 1e-5f);
#pragma unroll
    for (int i = 0; i < 4; i++) {
        int d = threadIdx.x + i * 256;
        orow[d] = __float2half((v[i] - mu) * inv * sc[d] + bi[d]);
    }
}

// ---------------- LayerNorm dual output (fp32 + fp16) ----------------
__global__ __launch_bounds__(256) void ln_dual_kernel(const float* __restrict__ x,
                                                      const float* __restrict__ sc,
                                                      const float* __restrict__ bi,
                                                      float* __restrict__ of,
                                                      __half* __restrict__ oh) {
    int t = blockIdx.x;
    const float* xr = x + (size_t)t * D_;
    float v[4];
    float s = 0.f, s2 = 0.f;
#pragma unroll
    for (int i = 0; i < 4; i++) {
        v[i] = xr[threadIdx.x + i * 256];
        s  += v[i];
        s2 += v[i] * v[i];
    }
#pragma unroll
    for (int off = 16; off; off >>= 1) {
        s  += __shfl_xor_sync(0xffffffffu, s,  off);
        s2 += __shfl_xor_sync(0xffffffffu, s2, off);
    }
    __shared__ float ws[8], ws2[8];
    int w = threadIdx.x >> 5, ln = threadIdx.x & 31;
    if (ln == 0) { ws[w] = s; ws2[w] = s2; }
    __syncthreads();
    float S = 0.f, S2 = 0.f;
#pragma unroll
    for (int i = 0; i < 8; i++) { S += ws[i]; S2 += ws2[i]; }
    float mu  = S * (1.0f / D_);
    float var = S2 * (1.0f / D_) - mu * mu;
    float inv = rsqrtf(var + 1e-5f);
#pragma unroll
    for (int i = 0; i < 4; i++) {
        int d = threadIdx.x + i * 256;
        float r = (v[i] - mu) * inv * sc[d] + bi[d];
        of[(size_t)t * D_ + d] = r;
        oh[(size_t)t * D_ + d] = __float2half(r);
    }
}

// ---------------- GEMM: ldmatrix + cp.async 3-stage, occ-2 ----------------------
#define STG_ 36864
#define TCSM (3 * STG_)

template <int MODE>
__global__ __launch_bounds__(256, 2) void gemm_ld(const __half* __restrict__ A,
                                                  const __half* __restrict__ Bt,
                                                  const float* __restrict__ Res,
                                                  float* __restrict__ Cf,
                                                  __half* __restrict__ Cb) {
    extern __shared__ char dsm[];
    uint32_t smb = smem_u32(dsm);

    int tid = threadIdx.x, warp = tid >> 5, lane = tid & 31;
    int g = lane >> 2, t4 = lane & 3;
    int wm = warp >> 1, wn = warp & 1;
    int bx = blockIdx.x * 128, by = blockIdx.y * 128;
    const __half* Bz = Bt + (size_t)blockIdx.z * D_ * D_;

    float acc[2][8][4];
#pragma unroll
    for (int i = 0; i < 2; i++)
#pragma unroll
        for (int j = 0; j < 8; j++)
#pragma unroll
            for (int q = 0; q < 4; q++) acc[i][j][q] = 0.f;

    int lr = tid >> 1;
    int lsh = (tid & 1) * 32;
    int lsb = (tid & 1) * 64;
    const __half* gA = A  + (size_t)(by + lr) * D_ + lsh;
    const __half* gB = Bz + (size_t)(bx + lr) * D_ + lsh;
    uint32_t sA = smb + lr * 144 + lsb;
    uint32_t sB = smb + 18432 + lr * 144 + lsb;

#pragma unroll
    for (int j = 0; j < 4; j++) {
        CP_ASYNC16(sA + j * 16, gA + j * 8);
        CP_ASYNC16(sB + j * 16, gB + j * 8);
    }
    CP_COMMIT();
#pragma unroll
    for (int j = 0; j < 4; j++) {
        CP_ASYNC16(sA + STG_ + j * 16, gA + 64 + j * 8);
        CP_ASYNC16(sB + STG_ + j * 16, gB + 64 + j * 8);
    }
    CP_COMMIT();

    uint32_t a_off = (uint32_t)((wm * 32 + (lane & 15)) * 144 + (lane >> 4) * 16);
    uint32_t b_row = (uint32_t)(wn * 64 + ((lane >> 4) & 1) * 8 + (lane & 7));
    uint32_t b_khb = ((lane >> 3) & 1) * 16;

    for (int i = 0; i < 16; i++) {
        int s = i % 3;
        if (i < 15) { CP_WAIT(1); } else { CP_WAIT(0); }
        __syncthreads();
        if (i + 2 < 16) {
            int s2 = (i + 2) % 3;
            int k0 = (i + 2) * 64;
#pragma unroll
            for (int j = 0; j < 4; j++) {
                CP_ASYNC16(sA + s2 * STG_ + j * 16, gA + k0 + j * 8);
                CP_ASYNC16(sB + s2 * STG_ + j * 16, gB + k0 + j * 8);
            }
            CP_COMMIT();
        }

        uint32_t ab = smb + s * STG_;
        uint32_t bb = ab + 18432;
#pragma unroll
        for (int kc = 0; kc < 4; kc++) {
            unsigned afr0[4], afr1[4];
            ldsm4(afr0, ab + a_off + kc * 32);
            ldsm4(afr1, ab + a_off + 16 * 144 + kc * 32);
#pragma unroll
            for (int p = 0; p < 4; p++) {
                unsigned bfr[4];
                ldsm4(bfr, bb + (b_row + p * 16) * 144 + b_khb + kc * 32);
                mma16(acc[0][2 * p],     afr0, bfr[0], bfr[1]);
                mma16(acc[0][2 * p + 1], afr0, bfr[2], bfr[3]);
                mma16(acc[1][2 * p],     afr1, bfr[0], bfr[1]);
                mma16(acc[1][2 * p + 1], afr1, bfr[2], bfr[3]);
            }
        }
    }

    if (MODE == 0) {
        __half* Cz = Cb + (size_t)blockIdx.z * T_ * D_;
#pragma unroll
        for (int mt = 0; mt < 2; mt++) {
#pragma unroll
            for (int nt = 0; nt < 8; nt++) {
                int col = bx + wn * 64 + nt * 8 + 2 * t4;
                size_t r0 = (size_t)(by + wm * 32 + mt * 16 + g);
                *(unsigned*)(Cz + r0 * D_ + col)       = packh(acc[mt][nt][0], acc[mt][nt][1]);
                *(unsigned*)(Cz + (r0 + 8) * D_ + col) = packh(acc[mt][nt][2], acc[mt][nt][3]);
            }
        }
    } else {
#pragma unroll
        for (int mt = 0; mt < 2; mt++) {
#pragma unroll
            for (int nt = 0; nt < 8; nt++) {
                int col = bx + wn * 64 + nt * 8 + 2 * t4;
                size_t r0 = (size_t)(by + wm * 32 + mt * 16 + g);
                size_t r1 = r0 + 8;
                float2 v01 = {acc[mt][nt][0], acc[mt][nt][1]};
                float2 v23 = {acc[mt][nt][2], acc[mt][nt][3]};
                float2 q0 = *(const float2*)(Res + r0 * D_ + col);
                float2 q1 = *(const float2*)(Res + r1 * D_ + col);
                v01.x += q0.x; v01.y += q0.y;
                v23.x += q1.x; v23.y += q1.y;
                *(float2*)(Cf + r0 * D_ + col) = v01;
                *(float2*)(Cf + r1 * D_ + col) = v23;
            }
        }
    }
}

// ---------------- MoE GEMM: ldmatrix + cp.async, gather/scatter, occ-2 ----------
template <int MODE>
__global__ __launch_bounds__(256, 2) void moe_ld(const __half* __restrict__ Ab,
                                                 const __half* __restrict__ Wt,
                                                 __half* __restrict__ Uph,
                                                 float* __restrict__ out) {
    const int Nn = (MODE == 0) ? F_ : D_;
    const int Kk = (MODE == 0) ? D_ : F_;
    const int NT = Kk / 64;
    int e = blockIdx.z;
    int n = g_cnt[e];
    int rb = blockIdx.y * 128;
    if (rb >= n) return;

    extern __shared__ char dsm[];
    uint32_t smb = smem_u32(dsm);

    int tid = threadIdx.x, warp = tid >> 5, lane = tid & 31;
    int g = lane >> 2, t4 = lane & 3;
    int wm = warp >> 1, wn = warp & 1;
    int bx = blockIdx.x * 128;
    const __half* Wz = Wt + (size_t)e * Kk * Nn;

    float acc[2][8][4];
#pragma unroll
    for (int i = 0; i < 2; i++)
#pragma unroll
        for (int j = 0; j < 8; j++)
#pragma unroll
            for (int q = 0; q < 4; q++) acc[i][j][q] = 0.f;

    int lr = tid >> 1;
    int lsh = (tid & 1) * 32;
    int lsb = (tid & 1) * 64;
    const __half* gA;
    if (MODE == 0) {
        int rg = rb + lr;
        int row = (rg < n) ? g_elist[e * T_ + rg] : 0;
        gA = Ab + (size_t)row * D_ + lsh;
    } else {
        gA = Ab + ((size_t)e * T_ + rb + lr) * F_ + lsh;
    }
    const __half* gB = Wz + (size_t)(bx + lr) * Kk + lsh;
    uint32_t sA = smb + lr * 144 + lsb;
    uint32_t sB = smb + 18432 + lr * 144 + lsb;

#pragma unroll
    for (int j = 0; j < 4; j++) {
        CP_ASYNC16(sA + j * 16, gA + j * 8);
        CP_ASYNC16(sB + j * 16, gB + j * 8);
    }
    CP_COMMIT();
#pragma unroll
    for (int j = 0; j < 4; j++) {
        CP_ASYNC16(sA + STG_ + j * 16, gA + 64 + j * 8);
        CP_ASYNC16(sB + STG_ + j * 16, gB + 64 + j * 8);
    }
    CP_COMMIT();

    uint32_t a_off = (uint32_t)((wm * 32 + (lane & 15)) * 144 + (lane >> 4) * 16);
    uint32_t b_row = (uint32_t)(wn * 64 + ((lane >> 4) & 1) * 8 + (lane & 7));
    uint32_t b_khb = ((lane >> 3) & 1) * 16;

    for (int i = 0; i < NT; i++) {
        int s = i % 3;
        if (i < NT - 1) { CP_WAIT(1); } else { CP_WAIT(0); }
        __syncthreads();
        if (i + 2 < NT) {
            int s2 = (i + 2) % 3;
            int k0 = (i + 2) * 64;
#pragma unroll
            for (int j = 0; j < 4; j++) {
                CP_ASYNC16(sA + s2 * STG_ + j * 16, gA + k0 + j * 8);
                CP_ASYNC16(sB + s2 * STG_ + j * 16, gB + k0 + j * 8);
            }
            CP_COMMIT();
        }

        uint32_t ab = smb + s * STG_;
        uint32_t bb = ab + 18432;
#pragma unroll
        for (int kc = 0; kc < 4; kc++) {
            unsigned afr0[4], afr1[4];
            ldsm4(afr0, ab + a_off + kc * 32);
            ldsm4(afr1, ab + a_off + 16 * 144 + kc * 32);
#pragma unroll
            for (int p = 0; p < 4; p++) {
                unsigned bfr[4];
                ldsm4(bfr, bb + (b_row + p * 16) * 144 + b_khb + kc * 32);
                mma16(acc[0][2 * p],     afr0, bfr[0], bfr[1]);
                mma16(acc[0][2 * p + 1], afr0, bfr[2], bfr[3]);
                mma16(acc[1][2 * p],     afr1, bfr[0], bfr[1]);
                mma16(acc[1][2 * p + 1], afr1, bfr[2], bfr[3]);
            }
        }
    }

    if (MODE == 0) {
#pragma unroll
        for (int mt = 0; mt < 2; mt++) {
            int rg0 = rb + wm * 32 + mt * 16 + g;
            int rg1 = rg0 + 8;
            float gt0 = (rg0 < n) ? g_egate[e * T_ + rg0] : 0.f;
            float gt1 = (rg1 < n) ? g_egate[e * T_ + rg1] : 0.f;
#pragma unroll
            for (int nt = 0; nt < 8; nt++) {
                int col = bx + wn * 64 + nt * 8 + 2 * t4;
                if (rg0 < n)
                    *(unsigned*)(Uph + ((size_t)e * T_ + rg0) * F_ + col) =
                        packh(fmaxf(acc[mt][nt][0], 0.f) * gt0,
                              fmaxf(acc[mt][nt][1], 0.f) * gt0);
                if (rg1 < n)
                    *(unsigned*)(Uph + ((size_t)e * T_ + rg1) * F_ + col) =
                        packh(fmaxf(acc[mt][nt][2], 0.f) * gt1,
                              fmaxf(acc[mt][nt][3], 0.f) * gt1);
            }
        }
    } else {
#pragma unroll
        for (int mt = 0; mt < 2; mt++) {
            int rg0 = rb + wm * 32 + mt * 16 + g;
            int rg1 = rg0 + 8;
            int t0 = (rg0 < n) ? g_elist[e * T_ + rg0] : -1;
            int t1 = (rg1 < n) ? g_elist[e * T_ + rg1] : -1;
#pragma unroll
            for (int nt = 0; nt < 8; nt++) {
                int col = bx + wn * 64 + nt * 8 + 2 * t4;
                if (t0 >= 0) {
                    atomicAdd(out + (size_t)t0 * D_ + col,     acc[mt][nt][0]);
                    atomicAdd(out + (size_t)t0 * D_ + col + 1, acc[mt][nt][1]);
                }
                if (t1 >= 0) {
                    atomicAdd(out + (size_t)t1 * D_ + col,     acc[mt][nt][2]);
                    atomicAdd(out + (size_t)t1 * D_ + col + 1, acc[mt][nt][3]);
                }
            }
        }
    }
}

// ---------------- fp16 flash attention: 128-q tile, double-buffered KV ----------
__global__ __launch_bounds__(256) void attn_h_kernel(const __half* __restrict__ Q,
                                                     const __half* __restrict__ Kb,
                                                     const __half* __restrict__ Vb,
                                                     __half* __restrict__ O) {
    __shared__ unsigned KVs[2 * 128 * 36];

    int bh = blockIdx.y;
    int b = bh >> 4, h = bh & 15;
    int q0 = blockIdx.x * 128;
    int tid = threadIdx.x, warp = tid >> 5, lane = tid & 31;
    int g = lane >> 2, t4 = lane & 3;

    uint32_t ksb = smem_u32(KVs);

    // ---- stage Q tile (128 rows) into buffer 0, read fragments ----
#pragma unroll
    for (int i = 0; i < 4; i++) {
        int idx = tid + i * 256;
        int row = idx >> 3, uq = idx & 7;
        *(uint4*)&KVs[row * 36 + uq * 4] =
            *(const uint4*)(Q + (size_t)(b * S_ + q0 + row) * D_ + h * 64 + uq * 8);
    }
    __syncthreads();
    unsigned qf[4][4];
    {
        uint32_t qa = ksb + (warp * 16 + (lane & 15)) * 144 + (lane >> 4) * 16;
#pragma unroll
        for (int kc = 0; kc < 4; kc++) ldsm4(qf[kc], qa + kc * 32);
    }
    __syncthreads();   // qf reads complete before buffer 0 is overwritten

    // ---- prefetch K/V tile 0 into registers ----
    uint4 kp[2], vp[2];
#pragma unroll
    for (int i = 0; i < 2; i++) {
        int idx = tid + i * 256;
        int row = idx >> 3, uq = idx & 7;
        size_t base = (size_t)(b * S_ + row) * D_ + h * 64 + uq * 8;
        kp[i] = *(const uint4*)(Kb + base);
        vp[i] = *(const uint4*)(Vb + base);
    }

    float oacc[8][4];
#pragma unroll
    for (int i = 0; i < 8; i++)
#pragma unroll
        for (int j = 0; j < 4; j++) oacc[i][j] = 0.f;
    float m0 = -1e30f, m1 = -1e30f, l0 = 0.f, l1 = 0.f;

    uint32_t k_row = ((lane >> 4) & 1) * 8 + (lane & 7);
    uint32_t k_khb = ((lane >> 3) & 1) * 16;
    uint32_t v_tok = ((lane >> 3) & 1) * 8 + (lane & 7);
    uint32_t v_dcb = ((lane >> 4) & 1) * 16;

    for (int kt = 0; kt < S_; kt += 64) {
        int buf = (kt >> 6) & 1;
#pragma unroll
        for (int i = 0; i < 2; i++) {
            int idx = tid + i * 256;
            int row = idx >> 3, uq = idx & 7;
            *(uint4*)&KVs[buf * 4608 + row * 36 + uq * 4]        = kp[i];
            *(uint4*)&KVs[buf * 4608 + (64 + row) * 36 + uq * 4] = vp[i];
        }
        __syncthreads();

        {
            int ktn = (kt + 64 < S_) ? kt + 64 : kt;
#pragma unroll
            for (int i = 0; i < 2; i++) {
                int idx = tid + i * 256;
                int row = idx >> 3, uq = idx & 7;
                size_t base = (size_t)(b * S_ + ktn + row) * D_ + h * 64 + uq * 8;
                kp[i] = *(const uint4*)(Kb + base);
                vp[i] = *(const uint4*)(Vb + base);
            }
        }

        uint32_t kbase = ksb + buf * 18432;
        uint32_t vbase = kbase + 64 * 144;

        float sacc[8][4];
#pragma unroll
        for (int i = 0; i < 8; i++)
#pragma unroll
            for (int j = 0; j < 4; j++) sacc[i][j] = 0.f;
#pragma unroll
        for (int kc = 0; kc < 4; kc++) {
#pragma unroll
            for (int p = 0; p < 4; p++) {
                unsigned kb[4];
                ldsm4(kb, kbase + (k_row + p * 16) * 144 + k_khb + kc * 32);
                mma16(sacc[2 * p],     qf[kc], kb[0], kb[1]);
                mma16(sacc[2 * p + 1], qf[kc], kb[2], kb[3]);
            }
        }
#pragma unroll
        for (int nt = 0; nt < 8; nt++)
#pragma unroll
            for (int j = 0; j < 4; j++) sacc[nt][j] *= 0.125f;

        float mx0 = -1e30f, mx1 = -1e30f;
#pragma unroll
        for (int nt = 0; nt < 8; nt++) {
            mx0 = fmaxf(mx0, fmaxf(sacc[nt][0], sacc[nt][1]));
            mx1 = fmaxf(mx1, fmaxf(sacc[nt][2], sacc[nt][3]));
        }
        mx0 = fmaxf(mx0, __shfl_xor_sync(0xffffffffu, mx0, 1));
        mx0 = fmaxf(mx0, __shfl_xor_sync(0xffffffffu, mx0, 2));
        mx1 = fmaxf(mx1, __shfl_xor_sync(0xffffffffu, mx1, 1));
        mx1 = fmaxf(mx1, __shfl_xor_sync(0xffffffffu, mx1, 2));
        float mn0 = fmaxf(m0, mx0), mn1 = fmaxf(m1, mx1);
        float al0 = __expf(m0 - mn0), al1 = __expf(m1 - mn1);
        float rs0 = 0.f, rs1 = 0.f;
#pragma unroll
        for (int nt = 0; nt < 8; nt++) {
            sacc[nt][0] = __expf(sacc[nt][0] - mn0);
            sacc[nt][1] = __expf(sacc[nt][1] - mn0);
            sacc[nt][2] = __expf(sacc[nt][2] - mn1);
            sacc[nt][3] = __expf(sacc[nt][3] - mn1);
            rs0 += sacc[nt][0] + sacc[nt][1];
            rs1 += sacc[nt][2] + sacc[nt][3];
        }
        rs0 += __shfl_xor_sync(0xffffffffu, rs0, 1);
        rs0 += __shfl_xor_sync(0xffffffffu, rs0, 2);
        rs1 += __shfl_xor_sync(0xffffffffu, rs1, 1);
        rs1 += __shfl_xor_sync(0xffffffffu, rs1, 2);
        l0 = l0 * al0 + rs0;
        l1 = l1 * al1 + rs1;
        m0 = mn0; m1 = mn1;
#pragma unroll
        for (int dt = 0; dt < 8; dt++) {
            oacc[dt][0] *= al0; oacc[dt][1] *= al0;
            oacc[dt][2] *= al1; oacc[dt][3] *= al1;
        }

#pragma unroll
        for (int kc = 0; kc < 4; kc++) {
            unsigned pf[4];
            pf[0] = packh(sacc[2 * kc][0],     sacc[2 * kc][1]);
            pf[1] = packh(sacc[2 * kc][2],     sacc[2 * kc][3]);
            pf[2] = packh(sacc[2 * kc + 1][0], sacc[2 * kc + 1][1]);
            pf[3] = packh(sacc[2 * kc + 1][2], sacc[2 * kc + 1][3]);
#pragma unroll
            for (int p = 0; p < 4; p++) {
                unsigned vb[4];
                ldsm4t(vb, vbase + (v_tok + kc * 16) * 144 + v_dcb + p * 32);
                mma16(oacc[2 * p],     pf, vb[0], vb[1]);
                mma16(oacc[2 * p + 1], pf, vb[2], vb[3]);
            }
        }
    }

    float il0 = 1.0f / l0, il1 = 1.0f / l1;
    int row = q0 + warp * 16 + g;
#pragma unroll
    for (int dt = 0; dt < 8; dt++) {
        int col = h * 64 + dt * 8 + 2 * t4;
        *(unsigned*)(O + (size_t)(b * S_ + row) * D_ + col) =
            packh(oacc[dt][0] * il0, oacc[dt][1] * il0);
        *(unsigned*)(O + (size_t)(b * S_ + row + 8) * D_ + col) =
            packh(oacc[dt][2] * il1, oacc[dt][3] * il1);
    }
}

// ---------------- Selector ----------------
__global__ __launch_bounds__(128) void selector_kernel(const float* __restrict__ h,
                                                       const float* __restrict__ Wsel) {
    int t = blockIdx.x * 4 + (threadIdx.x >> 5);
    int lane = threadIdx.x & 31;
    float acc[16];
#pragma unroll
    for (int e = 0; e < 16; e++) acc[e] = 0.f;
    const float* hr = h + (size_t)t * D_;
    for (int d = lane; d < D_; d += 32) {
        float hv = hr[d];
        const float4* w = (const float4*)(Wsel + (size_t)d * E_);
        float4 w0 = w[0], w1 = w[1], w2 = w[2], w3 = w[3];
        acc[0]  = fmaf(hv, w0.x, acc[0]);  acc[1]  = fmaf(hv, w0.y, acc[1]);
        acc[2]  = fmaf(hv, w0.z, acc[2]);  acc[3]  = fmaf(hv, w0.w, acc[3]);
        acc[4]  = fmaf(hv, w1.x, acc[4]);  acc[5]  = fmaf(hv, w1.y, acc[5]);
        acc[6]  = fmaf(hv, w1.z, acc[6]);  acc[7]  = fmaf(hv, w1.w, acc[7]);
        acc[8]  = fmaf(hv, w2.x, acc[8]);  acc[9]  = fmaf(hv, w2.y, acc[9]);
        acc[10] = fmaf(hv, w2.z, acc[10]); acc[11] = fmaf(hv, w2.w, acc[11]);
        acc[12] = fmaf(hv, w3.x, acc[12]); acc[13] = fmaf(hv, w3.y, acc[13]);
        acc[14] = fmaf(hv, w3.z, acc[14]); acc[15] = fmaf(hv, w3.w, acc[15]);
    }
#pragma unroll
    for (int e = 0; e < 16; e++)
#pragma unroll
        for (int o = 16; o; o >>= 1) acc[e] += __shfl_xor_sync(0xffffffffu, acc[e], o);
    if (lane == 0) {
        float v1 = -1.f, v2 = -1.f;
        int i1 = 0, i2 = 0;
#pragma unroll
        for (int e = 0; e < 16; e++) {
            float sg = 1.0f / (1.0f + __expf(-acc[e]));
            if (sg > v1) { v2 = v1; i2 = i1; v1 = sg; i1 = e; }
            else if (sg > v2) { v2 = sg; i2 = e; }
        }
        int p1 = atomicAdd(&g_cnt[i1], 1);
        g_elist[i1 * T_ + p1] = t;
        g_egate[i1 * T_ + p1] = v1;
        int p2 = atomicAdd(&g_cnt[i2], 1);
        g_elist[i2 * T_ + p2] = t;
        g_egate[i2 * T_ + p2] = v2;
    }
}

// ---------------- launch ----------------
extern "C" void kernel_launch(void* const* d_in, const int* in_sizes, int n_in,
                              void* d_out, int out_size) {
    (void)in_sizes; (void)n_in; (void)out_size;
    const float* x    = (const float*)d_in[0];
    const float* Wq   = (const float*)d_in[1];
    const float* Wk   = (const float*)d_in[2];
    const float* Wv   = (const float*)d_in[3];
    const float* Wo   = (const float*)d_in[4];
    const float* ln1s = (const float*)d_in[5];
    const float* ln1b = (const float*)d_in[6];
    const float* ln2s = (const float*)d_in[7];
    const float* ln2b = (const float*)d_in[8];
    const float* Wsel = (const float*)d_in[9];
    const float* W1   = (const float*)d_in[10];
    const float* W2   = (const float*)d_in[11];
    float* out = (float*)d_out;

    __half *wqkvT, *woT, *w1T, *w2T, *h1h, *qkvh, *ctxh, *h2h, *uph;
    float *h2p;
    cudaGetSymbolAddress((void**)&wqkvT, g_wqkvT);
    cudaGetSymbolAddress((void**)&woT,   g_woT);
    cudaGetSymbolAddress((void**)&w1T,   g_w1T);
    cudaGetSymbolAddress((void**)&w2T,   g_w2T);
    cudaGetSymbolAddress((void**)&h1h,   g_h1h);
    cudaGetSymbolAddress((void**)&qkvh,  g_qkvh);
    cudaGetSymbolAddress((void**)&ctxh,  g_ctxh);
    cudaGetSymbolAddress((void**)&h2h,   g_h2h);
    cudaGetSymbolAddress((void**)&uph,   g_uph);
    cudaGetSymbolAddress((void**)&h2p,   g_h2);

    static cudaStream_t s_side = nullptr;
    static cudaEvent_t ev_fork = nullptr, ev_join = nullptr;
    static int attrs_set = 0;
    if (s_side == nullptr) {
        cudaStreamCreateWithFlags(&s_side, cudaStreamNonBlocking);
        cudaEventCreateWithFlags(&ev_fork, cudaEventDisableTiming);
        cudaEventCreateWithFlags(&ev_join, cudaEventDisableTiming);
    }
    if (!attrs_set) {
        cudaFuncSetAttribute(gemm_ld<0>, cudaFuncAttributeMaxDynamicSharedMemorySize, TCSM);
        cudaFuncSetAttribute(gemm_ld<1>, cudaFuncAttributeMaxDynamicSharedMemorySize, TCSM);
        cudaFuncSetAttribute(moe_ld<0>, cudaFuncAttributeMaxDynamicSharedMemorySize, TCSM);
        cudaFuncSetAttribute(moe_ld<1>, cudaFuncAttributeMaxDynamicSharedMemorySize, TCSM);
        attrs_set = 1;
    }

    // fork: Wo transpose + per-expert MoE weight transposes overlap QKV+attention
    cudaEventRecord(ev_fork, 0);
    cudaStreamWaitEvent(s_side, ev_fork, 0);
    conv_f2h_T<<<dim3(32, 32), 256, 0, s_side>>>(Wo, woT);
    conv_TE<<<dim3(8, 32, E_), 256, 0, s_side>>>(W1, w1T, 1024, 256);
    conv_TE<<<dim3(32, 8, E_), 256, 0, s_side>>>(W2, w2T, 256, 1024);
    cudaEventRecord(ev_join, s_side);

    // main path
    conv_f2h_T3<<<dim3(32, 32, 3), 256>>>(Wq, Wk, Wv, wqkvT);
    zero_cnt_kernel<<<1, 32>>>();
    ln_h_kernel<<<T_, 256>>>(x, ln1s, ln1b, h1h);

    gemm_ld<0><<<dim3(8, 32, 3), 256, TCSM>>>(
        h1h, wqkvT, nullptr, nullptr, qkvh);

    attn_h_kernel<<<dim3(S_ / 128, B_ * H_), 256>>>(
        qkvh, qkvh + (size_t)T_ * D_, qkvh + 2 * (size_t)T_ * D_, ctxh);

    cudaStreamWaitEvent(0, ev_join, 0);

    // out = x + ctx @ Wo (single fp32 destination; ln_dual reads it back)
    gemm_ld<1><<<dim3(8, 32, 1), 256, TCSM>>>(
        ctxh, woT, x, out, nullptr);

    ln_dual_kernel<<<T_, 256>>>(out, ln2s, ln2b, h2p, h2h);
    selector_kernel<<<T_ / 4, 128>>>(h2p, Wsel);

    moe_ld<0><<<dim3(F_ / 128, T_ / 128, E_), 256, TCSM>>>(h2h, w1T, uph, nullptr);
    moe_ld<1><<<dim3(D_ / 128, T_ / 128, E_), 256, TCSM>>>(uph, w2T, nullptr, out);
}